// round 2
// baseline (speedup 1.0000x reference)
#include <cuda_runtime.h>
#include <math.h>

// ---------------- Problem constants ----------------
#define DD 256          // hidden dim
#define FIN 128         // input feature dim
#define CC 7            // classes
#define MAXN 100000
#define MAXS 5000

// ---------------- Scratch layout (single device buffer, no allocs) ----------
// floats:
//  h      [MAXN*DD]   GEMM output (X W)
//  x1     [MAXN*DD]   conv branch 1 (pre-relu)
//  x2     [MAXN*DD]   conv branch 2 (pre-relu)
//  hid    [MAXN*DD]   mlp hidden
//  hf     [MAXN*DD]   mlp output / node features
//  hid2   [MAXS*DD]   final mlp hidden
//  dis1   [MAXN]      deg^{-1/2} list 1
//  dis2   [MAXN]
//  p1     [MAXS*DD]   pooled
//  p2     [MAXS*DD]
//  cnt1   [MAXS]
//  cnt2   [MAXS]
#define OFF_H     0L
#define OFF_X1    25600000L
#define OFF_X2    51200000L
#define OFF_HID   76800000L
#define OFF_HF    102400000L
#define OFF_HID2  128000000L
#define OFF_DIS1  129280000L
#define OFF_DIS2  129380000L
#define OFF_P1    129480000L
#define OFF_P2    130760000L
#define OFF_CNT1  132040000L
#define OFF_CNT2  132045000L
#define SCRATCH_TOTAL 132050000L

__device__ float g_buf[SCRATCH_TOTAL];

// ---------------- helpers ----------------
__device__ __forceinline__ void atomicAddF4(float* p, float4 v) {
    asm volatile("red.global.add.v4.f32 [%0], {%1,%2,%3,%4};"
                 :: "l"(p), "f"(v.x), "f"(v.y), "f"(v.z), "f"(v.w) : "memory");
}

// ---------------- small kernels ----------------
__global__ void zero_k(float* __restrict__ p, int n) {
    int i = blockIdx.x * blockDim.x + threadIdx.x;
    if (i < n) p[i] = 0.0f;
}

__global__ void deg_k(const int* __restrict__ ei, int E, float* __restrict__ deg) {
    int i = blockIdx.x * blockDim.x + threadIdx.x;
    if (i < E) atomicAdd(&deg[ei[E + i]], 1.0f);
}

__global__ void dis_k(float* __restrict__ d, int n) {
    int i = blockIdx.x * blockDim.x + threadIdx.x;
    if (i < n) d[i] = rsqrtf(d[i] + 1.0f);   // +1 = self loop
}

// out[i,:] = bias + dis[i]^2 * h[i,:]   (self-loop term + bias init)
__global__ void self_init_k(const float* __restrict__ h, const float* __restrict__ dis,
                            const float* __restrict__ bias, float* __restrict__ out, int Nn) {
    int gid = blockIdx.x * blockDim.x + threadIdx.x;
    int total = Nn * 64;
    if (gid >= total) return;
    int i = gid >> 6;
    int c = (gid & 63) << 2;
    float d2 = dis[i] * dis[i];
    float4 hv = *(const float4*)(h + (size_t)i * DD + c);
    float4 bv = *(const float4*)(bias + c);
    float4 o;
    o.x = bv.x + d2 * hv.x; o.y = bv.y + d2 * hv.y;
    o.z = bv.z + d2 * hv.z; o.w = bv.w + d2 * hv.w;
    *(float4*)(out + (size_t)i * DD + c) = o;
}

// out[col,:] += dis[row]*dis[col] * h[row,:]  for every edge
__global__ void scatter_k(const int* __restrict__ ei, int E,
                          const float* __restrict__ dis,
                          const float* __restrict__ h,
                          float* __restrict__ out) {
    int gid = blockIdx.x * blockDim.x + threadIdx.x;
    int total = E * 64;
    if (gid >= total) return;
    int e = gid >> 6;
    int c = (gid & 63) << 2;
    int r  = ei[e];
    int cl = ei[E + e];
    float coef = dis[r] * dis[cl];
    float4 hv = *(const float4*)(h + (size_t)r * DD + c);
    float4 m;
    m.x = coef * hv.x; m.y = coef * hv.y; m.z = coef * hv.z; m.w = coef * hv.w;
    atomicAddF4(out + (size_t)cl * DD + c, m);
}

__global__ void count_k(const int* __restrict__ i1, const int* __restrict__ i2,
                        float* __restrict__ c1, float* __restrict__ c2, int Nn) {
    int i = blockIdx.x * blockDim.x + threadIdx.x;
    if (i < Nn) {
        atomicAdd(&c1[i1[i]], 1.0f);
        atomicAdd(&c2[i2[i]], 1.0f);
    }
}

__global__ void pool_k(const float* __restrict__ h,
                       const int* __restrict__ i1, const int* __restrict__ i2,
                       float* __restrict__ p1, float* __restrict__ p2, int Nn) {
    int gid = blockIdx.x * blockDim.x + threadIdx.x;
    int total = Nn * 64;
    if (gid >= total) return;
    int i = gid >> 6;
    int c = (gid & 63) << 2;
    float4 hv = *(const float4*)(h + (size_t)i * DD + c);
    atomicAddF4(p1 + (size_t)i1[i] * DD + c, hv);
    atomicAddF4(p2 + (size_t)i2[i] * DD + c, hv);
}

__global__ void norm_k(float* __restrict__ p1, float* __restrict__ p2,
                       const float* __restrict__ c1, const float* __restrict__ c2, int S) {
    int gid = blockIdx.x * blockDim.x + threadIdx.x;
    int total = S * 64;
    if (gid >= total) return;
    int s = gid >> 6;
    int c = (gid & 63) << 2;
    float s1 = 1.0f / fmaxf(c1[s], 1.0f);
    float s2 = 1.0f / fmaxf(c2[s], 1.0f);
    float4 a = *(float4*)(p1 + (size_t)s * DD + c);
    a.x *= s1; a.y *= s1; a.z *= s1; a.w *= s1;
    *(float4*)(p1 + (size_t)s * DD + c) = a;
    float4 b = *(float4*)(p2 + (size_t)s * DD + c);
    b.x *= s2; b.y *= s2; b.z *= s2; b.w *= s2;
    *(float4*)(p2 + (size_t)s * DD + c) = b;
}

// logits + log_softmax head: one block per segment
__global__ void final_k(const float* __restrict__ hid, const float* __restrict__ w2,
                        const float* __restrict__ b2, float* __restrict__ out) {
    __shared__ float sh[DD];
    __shared__ float lg[CC];
    int s = blockIdx.x;
    int tid = threadIdx.x;
    sh[tid] = hid[(size_t)s * DD + tid];
    __syncthreads();
    int w = tid >> 5, lane = tid & 31;
    if (w < CC) {
        float sum = 0.0f;
        for (int k = lane; k < DD; k += 32) sum += sh[k] * w2[k * CC + w];
        #pragma unroll
        for (int o = 16; o > 0; o >>= 1) sum += __shfl_xor_sync(0xFFFFFFFFu, sum, o);
        if (lane == 0) lg[w] = sum + b2[w];
    }
    __syncthreads();
    if (tid == 0) {
        float mx = -1e30f;
        #pragma unroll
        for (int c = 0; c < CC; c++) mx = fmaxf(mx, lg[c]);
        float se = 0.0f;
        #pragma unroll
        for (int c = 0; c < CC; c++) se += expf(lg[c] - mx);
        float lse = mx + logf(se);
        #pragma unroll
        for (int c = 0; c < CC; c++) out[(size_t)s * CC + c] = lg[c] - lse;
    }
}

// ---------------- SGEMM: C[M,N] = op(A[M,K]) @ W[K,N] (+C) (+bias) (relu) -----
#define BM 128
#define BN 128
#define BK 8
#define TM 8
#define TN 8

template<bool RELU_A, bool ACCUM, bool BIAS, bool RELU_OUT>
__global__ void __launch_bounds__(256)
sgemm_k(const float* __restrict__ A, const float* __restrict__ W,
        const float* __restrict__ bias, float* __restrict__ C,
        int M, int N, int K) {
    __shared__ float As[BK][BM];
    __shared__ float Bs[BK][BN];

    int tid = threadIdx.x;
    int bm = blockIdx.y * BM;
    int bn = blockIdx.x * BN;
    int ty = tid >> 4;          // 0..15
    int tx = tid & 15;          // 0..15

    int arow = tid >> 1;        // 0..127
    int acol = (tid & 1) * 4;   // 0 or 4
    int brow = tid >> 5;        // 0..7
    int bcol = (tid & 31) * 4;  // 0..124

    float acc[TM][TN];
    #pragma unroll
    for (int i = 0; i < TM; i++)
        #pragma unroll
        for (int j = 0; j < TN; j++) acc[i][j] = 0.0f;

    bool arow_ok = (bm + arow) < M;
    const float* Aptr = A + (size_t)(bm + arow) * K + acol;

    for (int k0 = 0; k0 < K; k0 += BK) {
        float4 av = make_float4(0.f, 0.f, 0.f, 0.f);
        if (arow_ok) av = *(const float4*)(Aptr + k0);
        if (RELU_A) {
            av.x = fmaxf(av.x, 0.f); av.y = fmaxf(av.y, 0.f);
            av.z = fmaxf(av.z, 0.f); av.w = fmaxf(av.w, 0.f);
        }
        As[acol + 0][arow] = av.x;
        As[acol + 1][arow] = av.y;
        As[acol + 2][arow] = av.z;
        As[acol + 3][arow] = av.w;

        float4 bv = *(const float4*)(W + (size_t)(k0 + brow) * N + bn + bcol);
        *(float4*)&Bs[brow][bcol] = bv;
        __syncthreads();

        #pragma unroll
        for (int k = 0; k < BK; k++) {
            float ar[TM], br[TN];
            #pragma unroll
            for (int i = 0; i < TM; i++) ar[i] = As[k][ty * TM + i];
            #pragma unroll
            for (int j = 0; j < TN; j++) br[j] = Bs[k][tx * TN + j];
            #pragma unroll
            for (int i = 0; i < TM; i++)
                #pragma unroll
                for (int j = 0; j < TN; j++)
                    acc[i][j] = fmaf(ar[i], br[j], acc[i][j]);
        }
        __syncthreads();
    }

    // epilogue
    #pragma unroll
    for (int i = 0; i < TM; i++) {
        int r = bm + ty * TM + i;
        if (r >= M) continue;
        #pragma unroll
        for (int j4 = 0; j4 < TN; j4 += 4) {
            int c = bn + tx * TN + j4;
            float4 v = make_float4(acc[i][j4], acc[i][j4+1], acc[i][j4+2], acc[i][j4+3]);
            if (ACCUM) {
                float4 pv = *(const float4*)(C + (size_t)r * N + c);
                v.x += pv.x; v.y += pv.y; v.z += pv.z; v.w += pv.w;
            }
            if (BIAS) {
                float4 bb = *(const float4*)(bias + c);
                v.x += bb.x; v.y += bb.y; v.z += bb.z; v.w += bb.w;
            }
            if (RELU_OUT) {
                v.x = fmaxf(v.x, 0.f); v.y = fmaxf(v.y, 0.f);
                v.z = fmaxf(v.z, 0.f); v.w = fmaxf(v.w, 0.f);
            }
            *(float4*)(C + (size_t)r * N + c) = v;
        }
    }
}

// ---------------- launch ----------------
static inline dim3 gemm_grid(int M, int N) {
    return dim3((unsigned)(N / BN), (unsigned)((M + BM - 1) / BM), 1);
}

extern "C" void kernel_launch(void* const* d_in, const int* in_sizes, int n_in,
                              void* d_out, int out_size) {
    const float* x    = (const float*)d_in[0];
    const int*   e1   = (const int*)d_in[1];
    const int*   e2   = (const int*)d_in[2];
    const int*   i1   = (const int*)d_in[3];
    const int*   i2   = (const int*)d_in[4];
    const float* w11  = (const float*)d_in[5];
    const float* b11  = (const float*)d_in[6];
    const float* w12  = (const float*)d_in[7];
    const float* b12  = (const float*)d_in[8];
    const float* w21  = (const float*)d_in[9];
    const float* b21  = (const float*)d_in[10];
    const float* w22  = (const float*)d_in[11];
    const float* b22  = (const float*)d_in[12];
    const float* m1w1 = (const float*)d_in[13];
    const float* m1b1 = (const float*)d_in[14];
    const float* m1w2 = (const float*)d_in[15];
    const float* m1b2 = (const float*)d_in[16];
    const float* m2w1 = (const float*)d_in[17];
    const float* m2b1 = (const float*)d_in[18];
    const float* m2w2 = (const float*)d_in[19];
    const float* m2b2 = (const float*)d_in[20];
    const float* mw1  = (const float*)d_in[21];
    const float* mb1  = (const float*)d_in[22];
    const float* mw2  = (const float*)d_in[23];
    const float* mb2  = (const float*)d_in[24];
    float* out = (float*)d_out;

    int Nn = in_sizes[0] / FIN;
    int E1 = in_sizes[1] / 2;
    int E2 = in_sizes[2] / 2;
    int S  = out_size / CC;

    float* base = nullptr;
    cudaGetSymbolAddress((void**)&base, g_buf);
    float* h    = base + OFF_H;
    float* x1   = base + OFF_X1;
    float* x2   = base + OFF_X2;
    float* hid  = base + OFF_HID;
    float* hf   = base + OFF_HF;
    float* hid2 = base + OFF_HID2;
    float* dis1 = base + OFF_DIS1;
    float* dis2 = base + OFF_DIS2;
    float* p1   = base + OFF_P1;
    float* p2   = base + OFF_P2;
    float* c1   = base + OFF_CNT1;
    float* c2   = base + OFF_CNT2;

    const int T = 256;
    // zero dis/pool/count region in one shot (contiguous tail of g_buf)
    int nz = (int)(SCRATCH_TOTAL - OFF_DIS1);
    zero_k<<<(nz + T - 1) / T, T>>>(dis1, nz);

    // degrees -> dis
    deg_k<<<(E1 + T - 1) / T, T>>>(e1, E1, dis1);
    deg_k<<<(E2 + T - 1) / T, T>>>(e2, E2, dis2);
    dis_k<<<(Nn + T - 1) / T, T>>>(dis1, Nn);
    dis_k<<<(Nn + T - 1) / T, T>>>(dis2, Nn);

    int nchunks = Nn * 64;
    int gN = (nchunks + T - 1) / T;

    // ---- layer 1, conv a (edge list 1) ----
    sgemm_k<false,false,false,false><<<gemm_grid(Nn, DD), 256>>>(x, w11, nullptr, h, Nn, DD, FIN);
    self_init_k<<<gN, T>>>(h, dis1, b11, x1, Nn);
    scatter_k<<<(E1 * 64 + T - 1) / T, T>>>(e1, E1, dis1, h, x1);
    // ---- layer 1, conv b (edge list 2) ----
    sgemm_k<false,false,false,false><<<gemm_grid(Nn, DD), 256>>>(x, w12, nullptr, h, Nn, DD, FIN);
    self_init_k<<<gN, T>>>(h, dis2, b12, x2, Nn);
    scatter_k<<<(E2 * 64 + T - 1) / T, T>>>(e2, E2, dis2, h, x2);
    // ---- mlp_1 (concat fused as two K=256 GEMMs; relu on conv outputs fused into A-read) ----
    sgemm_k<true,false,false,false><<<gemm_grid(Nn, DD), 256>>>(x1, m1w1, nullptr, hid, Nn, DD, DD);
    sgemm_k<true,true,true,true><<<gemm_grid(Nn, DD), 256>>>(x2, m1w1 + (size_t)DD * DD, m1b1, hid, Nn, DD, DD);
    sgemm_k<false,false,true,false><<<gemm_grid(Nn, DD), 256>>>(hid, m1w2, m1b2, hf, Nn, DD, DD);

    // ---- layer 2, conv a ----
    sgemm_k<false,false,false,false><<<gemm_grid(Nn, DD), 256>>>(hf, w21, nullptr, h, Nn, DD, DD);
    self_init_k<<<gN, T>>>(h, dis1, b21, x1, Nn);
    scatter_k<<<(E1 * 64 + T - 1) / T, T>>>(e1, E1, dis1, h, x1);
    // ---- layer 2, conv b ----
    sgemm_k<false,false,false,false><<<gemm_grid(Nn, DD), 256>>>(hf, w22, nullptr, h, Nn, DD, DD);
    self_init_k<<<gN, T>>>(h, dis2, b22, x2, Nn);
    scatter_k<<<(E2 * 64 + T - 1) / T, T>>>(e2, E2, dis2, h, x2);
    // ---- mlp_2 ----
    sgemm_k<true,false,false,false><<<gemm_grid(Nn, DD), 256>>>(x1, m2w1, nullptr, hid, Nn, DD, DD);
    sgemm_k<true,true,true,true><<<gemm_grid(Nn, DD), 256>>>(x2, m2w1 + (size_t)DD * DD, m2b1, hid, Nn, DD, DD);
    sgemm_k<false,false,true,false><<<gemm_grid(Nn, DD), 256>>>(hid, m2w2, m2b2, hf, Nn, DD, DD);

    // ---- pooling (scatter mean to S segments) ----
    count_k<<<(Nn + T - 1) / T, T>>>(i1, i2, c1, c2, Nn);
    pool_k<<<gN, T>>>(hf, i1, i2, p1, p2, Nn);
    norm_k<<<(S * 64 + T - 1) / T, T>>>(p1, p2, c1, c2, S);

    // ---- head: mlp(concat[p1,p2]) -> log_softmax ----
    sgemm_k<false,false,false,false><<<gemm_grid(S, DD), 256>>>(p1, mw1, nullptr, hid2, S, DD, DD);
    sgemm_k<false,true,true,true><<<gemm_grid(S, DD), 256>>>(p2, mw1 + (size_t)DD * DD, mb1, hid2, S, DD, DD);
    final_k<<<S, DD>>>(hid2, mw2, mb2, out);
}

// round 5
// speedup vs baseline: 1.2625x; 1.2625x over previous
#include <cuda_runtime.h>
#include <cuda_bf16.h>
#include <math.h>
#include <stdint.h>
#include <cstdint>

// ---------------- Problem constants ----------------
#define DD 256          // hidden dim
#define FIN 128         // input feature dim
#define CC 7            // classes
#define MAXN 100000
#define MAXS 5000

// ---------------- Scratch layout (single device buffer, no allocs) ----------
#define OFF_H     0L
#define OFF_X1    25600000L
#define OFF_X2    51200000L
#define OFF_HID   76800000L
#define OFF_HF    102400000L
#define OFF_HID2  128000000L
#define OFF_DIS1  129280000L
#define OFF_DIS2  129380000L
#define OFF_P1    129480000L
#define OFF_P2    130760000L
#define OFF_CNT1  132040000L
#define OFF_CNT2  132045000L
#define SCRATCH_TOTAL 132050000L

__device__ float g_buf[SCRATCH_TOTAL];

// ---------------- helpers ----------------
__device__ __forceinline__ void atomicAddF4(float* p, float4 v) {
    asm volatile("red.global.add.v4.f32 [%0], {%1,%2,%3,%4};"
                 :: "l"(p), "f"(v.x), "f"(v.y), "f"(v.z), "f"(v.w) : "memory");
}

__device__ __forceinline__ void splitbf(float v, __nv_bfloat16& h, __nv_bfloat16& l) {
    h = __float2bfloat16(v);
    l = __float2bfloat16(v - __bfloat162float(h));
}

__device__ __forceinline__ void ldm_x4(uint32_t r[4], const void* p) {
    uint32_t addr = (uint32_t)__cvta_generic_to_shared(p);
    asm volatile("ldmatrix.sync.aligned.m8n8.x4.shared.b16 {%0,%1,%2,%3}, [%4];"
                 : "=r"(r[0]), "=r"(r[1]), "=r"(r[2]), "=r"(r[3]) : "r"(addr));
}

__device__ __forceinline__ void mma16816(float c[4], const uint32_t a[4],
                                         uint32_t b0, uint32_t b1) {
    asm volatile(
        "mma.sync.aligned.m16n8k16.row.col.f32.bf16.bf16.f32 "
        "{%0,%1,%2,%3}, {%4,%5,%6,%7}, {%8,%9}, {%0,%1,%2,%3};"
        : "+f"(c[0]), "+f"(c[1]), "+f"(c[2]), "+f"(c[3])
        : "r"(a[0]), "r"(a[1]), "r"(a[2]), "r"(a[3]), "r"(b0), "r"(b1));
}

// ---------------- small kernels ----------------
__global__ void zero_k(float* __restrict__ p, int n) {
    int i = blockIdx.x * blockDim.x + threadIdx.x;
    if (i < n) p[i] = 0.0f;
}

__global__ void deg_k(const int* __restrict__ ei, int E, float* __restrict__ deg) {
    int i = blockIdx.x * blockDim.x + threadIdx.x;
    if (i < E) atomicAdd(&deg[ei[E + i]], 1.0f);
}

__global__ void dis_k(float* __restrict__ d, int n) {
    int i = blockIdx.x * blockDim.x + threadIdx.x;
    if (i < n) d[i] = rsqrtf(d[i] + 1.0f);   // +1 = self loop
}

// out[i,:] = bias + dis[i]^2 * h[i,:]
__global__ void self_init_k(const float* __restrict__ h, const float* __restrict__ dis,
                            const float* __restrict__ bias, float* __restrict__ out, int Nn) {
    int gid = blockIdx.x * blockDim.x + threadIdx.x;
    int total = Nn * 64;
    if (gid >= total) return;
    int i = gid >> 6;
    int c = (gid & 63) << 2;
    float d2 = dis[i] * dis[i];
    float4 hv = *(const float4*)(h + (size_t)i * DD + c);
    float4 bv = *(const float4*)(bias + c);
    float4 o;
    o.x = bv.x + d2 * hv.x; o.y = bv.y + d2 * hv.y;
    o.z = bv.z + d2 * hv.z; o.w = bv.w + d2 * hv.w;
    *(float4*)(out + (size_t)i * DD + c) = o;
}

// out[col,:] += dis[row]*dis[col] * h[row,:]
__global__ void scatter_k(const int* __restrict__ ei, int E,
                          const float* __restrict__ dis,
                          const float* __restrict__ h,
                          float* __restrict__ out) {
    int gid = blockIdx.x * blockDim.x + threadIdx.x;
    int total = E * 64;
    if (gid >= total) return;
    int e = gid >> 6;
    int c = (gid & 63) << 2;
    int r  = ei[e];
    int cl = ei[E + e];
    float coef = dis[r] * dis[cl];
    float4 hv = *(const float4*)(h + (size_t)r * DD + c);
    float4 m;
    m.x = coef * hv.x; m.y = coef * hv.y; m.z = coef * hv.z; m.w = coef * hv.w;
    atomicAddF4(out + (size_t)cl * DD + c, m);
}

__global__ void count_k(const int* __restrict__ i1, const int* __restrict__ i2,
                        float* __restrict__ c1, float* __restrict__ c2, int Nn) {
    int i = blockIdx.x * blockDim.x + threadIdx.x;
    if (i < Nn) {
        atomicAdd(&c1[i1[i]], 1.0f);
        atomicAdd(&c2[i2[i]], 1.0f);
    }
}

__global__ void pool_k(const float* __restrict__ h,
                       const int* __restrict__ i1, const int* __restrict__ i2,
                       float* __restrict__ p1, float* __restrict__ p2, int Nn) {
    int gid = blockIdx.x * blockDim.x + threadIdx.x;
    int total = Nn * 64;
    if (gid >= total) return;
    int i = gid >> 6;
    int c = (gid & 63) << 2;
    float4 hv = *(const float4*)(h + (size_t)i * DD + c);
    atomicAddF4(p1 + (size_t)i1[i] * DD + c, hv);
    atomicAddF4(p2 + (size_t)i2[i] * DD + c, hv);
}

__global__ void norm_k(float* __restrict__ p1, float* __restrict__ p2,
                       const float* __restrict__ c1, const float* __restrict__ c2, int S) {
    int gid = blockIdx.x * blockDim.x + threadIdx.x;
    int total = S * 64;
    if (gid >= total) return;
    int s = gid >> 6;
    int c = (gid & 63) << 2;
    float s1 = 1.0f / fmaxf(c1[s], 1.0f);
    float s2 = 1.0f / fmaxf(c2[s], 1.0f);
    float4 a = *(float4*)(p1 + (size_t)s * DD + c);
    a.x *= s1; a.y *= s1; a.z *= s1; a.w *= s1;
    *(float4*)(p1 + (size_t)s * DD + c) = a;
    float4 b = *(float4*)(p2 + (size_t)s * DD + c);
    b.x *= s2; b.y *= s2; b.z *= s2; b.w *= s2;
    *(float4*)(p2 + (size_t)s * DD + c) = b;
}

// logits + log_softmax head
__global__ void final_k(const float* __restrict__ hid, const float* __restrict__ w2,
                        const float* __restrict__ b2, float* __restrict__ out) {
    __shared__ float sh[DD];
    __shared__ float lg[CC];
    int s = blockIdx.x;
    int tid = threadIdx.x;
    sh[tid] = hid[(size_t)s * DD + tid];
    __syncthreads();
    int w = tid >> 5, lane = tid & 31;
    if (w < CC) {
        float sum = 0.0f;
        for (int k = lane; k < DD; k += 32) sum += sh[k] * w2[k * CC + w];
        #pragma unroll
        for (int o = 16; o > 0; o >>= 1) sum += __shfl_xor_sync(0xFFFFFFFFu, sum, o);
        if (lane == 0) lg[w] = sum + b2[w];
    }
    __syncthreads();
    if (tid == 0) {
        float mx = -1e30f;
        #pragma unroll
        for (int c = 0; c < CC; c++) mx = fmaxf(mx, lg[c]);
        float se = 0.0f;
        #pragma unroll
        for (int c = 0; c < CC; c++) se += expf(lg[c] - mx);
        float lse = mx + logf(se);
        #pragma unroll
        for (int c = 0; c < CC; c++) out[(size_t)s * CC + c] = lg[c] - lse;
    }
}

// ---------------- Tensor-core GEMM (bf16 x3 split, fp32 accum) ----------------
// C[M,N] = op(A[M,K]) @ W[K,N] (+C) (+bias) (relu).  N % 128 == 0, K % 32 == 0.
#define LDK 40   // padded k-stride in bf16 (80B/row: 16B-aligned rows, conflict-free ldmatrix)

template<bool RELU_A, bool ACCUM, bool BIAS, bool RELU_OUT>
__global__ void __launch_bounds__(256)
sgemm_tc(const float* __restrict__ A, const float* __restrict__ W,
         const float* __restrict__ bias, float* __restrict__ C,
         int M, int N, int K) {
    __shared__ __nv_bfloat16 As_h[128 * LDK];
    __shared__ __nv_bfloat16 As_l[128 * LDK];
    __shared__ __nv_bfloat16 Bs_h[128 * LDK];
    __shared__ __nv_bfloat16 Bs_l[128 * LDK];

    int tid = threadIdx.x;
    int wid = tid >> 5;
    int lane = tid & 31;
    int bm = blockIdx.y * 128;
    int bn = blockIdx.x * 128;
    int wm = (wid & 3) * 32;    // warp m offset within tile
    int wn = (wid >> 2) * 64;   // warp n offset within tile

    float acc[2][8][4];
    #pragma unroll
    for (int i = 0; i < 2; i++)
        #pragma unroll
        for (int j = 0; j < 8; j++)
            #pragma unroll
            for (int q = 0; q < 4; q++) acc[i][j][q] = 0.0f;

    int idx = lane >> 3;     // ldmatrix sub-matrix index
    int lr  = lane & 7;

    for (int k0 = 0; k0 < K; k0 += 32) {
        // ---- stage A (fp32 -> hi/lo bf16, optional relu) ----
        #pragma unroll
        for (int p = 0; p < 4; p++) {
            int r  = p * 32 + (tid >> 3);
            int kk = (tid & 7) * 4;
            float4 v = make_float4(0.f, 0.f, 0.f, 0.f);
            if (bm + r < M) v = *(const float4*)(A + (size_t)(bm + r) * K + k0 + kk);
            if (RELU_A) {
                v.x = fmaxf(v.x, 0.f); v.y = fmaxf(v.y, 0.f);
                v.z = fmaxf(v.z, 0.f); v.w = fmaxf(v.w, 0.f);
            }
            __nv_bfloat16 h0, l0, h1, l1, h2, l2, h3, l3;
            splitbf(v.x, h0, l0); splitbf(v.y, h1, l1);
            splitbf(v.z, h2, l2); splitbf(v.w, h3, l3);
            __nv_bfloat162* ph = (__nv_bfloat162*)&As_h[r * LDK + kk];
            __nv_bfloat162* pl = (__nv_bfloat162*)&As_l[r * LDK + kk];
            __nv_bfloat162 t;
            t.x = h0; t.y = h1; ph[0] = t;
            t.x = h2; t.y = h3; ph[1] = t;
            t.x = l0; t.y = l1; pl[0] = t;
            t.x = l2; t.y = l3; pl[1] = t;
        }
        // ---- stage B transposed: Bs[n][k] <- W[k0+k][bn+n] ----
        #pragma unroll
        for (int p = 0; p < 4; p++) {
            int kk = p * 8 + wid;
            const float* wp = W + (size_t)(k0 + kk) * N + bn + lane;
            #pragma unroll
            for (int j = 0; j < 4; j++) {
                float v = wp[j * 32];
                __nv_bfloat16 h, l;
                splitbf(v, h, l);
                int n = lane + j * 32;
                Bs_h[n * LDK + kk] = h;
                Bs_l[n * LDK + kk] = l;
            }
        }
        __syncthreads();

        // ---- compute: two k16 steps ----
        #pragma unroll
        for (int ks = 0; ks < 2; ks++) {
            int kb = ks * 16;
            uint32_t ah[2][4], al[2][4];
            #pragma unroll
            for (int mf = 0; mf < 2; mf++) {
                int row = wm + mf * 16 + (idx & 1) * 8 + lr;
                int col = kb + (idx >> 1) * 8;
                ldm_x4(ah[mf], &As_h[row * LDK + col]);
                ldm_x4(al[mf], &As_l[row * LDK + col]);
            }
            uint32_t bh[4][4], bl[4][4];
            #pragma unroll
            for (int bg = 0; bg < 4; bg++) {
                int row = wn + bg * 16 + (idx >> 1) * 8 + lr;
                int col = kb + (idx & 1) * 8;
                ldm_x4(bh[bg], &Bs_h[row * LDK + col]);
                ldm_x4(bl[bg], &Bs_l[row * LDK + col]);
            }
            #pragma unroll
            for (int mf = 0; mf < 2; mf++)
                #pragma unroll
                for (int ng = 0; ng < 8; ng++) {
                    int bg = ng >> 1, pr = (ng & 1) * 2;
                    mma16816(acc[mf][ng], ah[mf], bh[bg][pr], bh[bg][pr + 1]);
                    mma16816(acc[mf][ng], ah[mf], bl[bg][pr], bl[bg][pr + 1]);
                    mma16816(acc[mf][ng], al[mf], bh[bg][pr], bh[bg][pr + 1]);
                }
        }
        __syncthreads();
    }

    // ---- epilogue ----
    int r0 = bm + wm + (lane >> 2);
    int cbase = bn + wn + (lane & 3) * 2;
    #pragma unroll
    for (int mf = 0; mf < 2; mf++) {
        #pragma unroll
        for (int half = 0; half < 2; half++) {
            int r = r0 + mf * 16 + half * 8;
            if (r >= M) continue;
            #pragma unroll
            for (int ng = 0; ng < 8; ng++) {
                int c = cbase + ng * 8;
                float v0 = acc[mf][ng][half * 2 + 0];
                float v1 = acc[mf][ng][half * 2 + 1];
                float* cp = C + (size_t)r * N + c;
                if (ACCUM) {
                    float2 pv = *(const float2*)cp;
                    v0 += pv.x; v1 += pv.y;
                }
                if (BIAS) { v0 += bias[c]; v1 += bias[c + 1]; }
                if (RELU_OUT) { v0 = fmaxf(v0, 0.f); v1 = fmaxf(v1, 0.f); }
                float2 st; st.x = v0; st.y = v1;
                *(float2*)cp = st;
            }
        }
    }
}

// ---------------- launch ----------------
static inline dim3 gemm_grid(int M, int N) {
    return dim3((unsigned)(N / 128), (unsigned)((M + 127) / 128), 1);
}

extern "C" void kernel_launch(void* const* d_in, const int* in_sizes, int n_in,
                              void* d_out, int out_size) {
    const float* x    = (const float*)d_in[0];
    const int*   e1   = (const int*)d_in[1];
    const int*   e2   = (const int*)d_in[2];
    const int*   i1   = (const int*)d_in[3];
    const int*   i2   = (const int*)d_in[4];
    const float* w11  = (const float*)d_in[5];
    const float* b11  = (const float*)d_in[6];
    const float* w12  = (const float*)d_in[7];
    const float* b12  = (const float*)d_in[8];
    const float* w21  = (const float*)d_in[9];
    const float* b21  = (const float*)d_in[10];
    const float* w22  = (const float*)d_in[11];
    const float* b22  = (const float*)d_in[12];
    const float* m1w1 = (const float*)d_in[13];
    const float* m1b1 = (const float*)d_in[14];
    const float* m1w2 = (const float*)d_in[15];
    const float* m1b2 = (const float*)d_in[16];
    const float* m2w1 = (const float*)d_in[17];
    const float* m2b1 = (const float*)d_in[18];
    const float* m2w2 = (const float*)d_in[19];
    const float* m2b2 = (const float*)d_in[20];
    const float* mw1  = (const float*)d_in[21];
    const float* mb1  = (const float*)d_in[22];
    const float* mw2  = (const float*)d_in[23];
    const float* mb2  = (const float*)d_in[24];
    float* out = (float*)d_out;

    int Nn = in_sizes[0] / FIN;
    int E1 = in_sizes[1] / 2;
    int E2 = in_sizes[2] / 2;
    int S  = out_size / CC;

    float* base = nullptr;
    cudaGetSymbolAddress((void**)&base, g_buf);
    float* h    = base + OFF_H;
    float* x1   = base + OFF_X1;
    float* x2   = base + OFF_X2;
    float* hid  = base + OFF_HID;
    float* hf   = base + OFF_HF;
    float* hid2 = base + OFF_HID2;
    float* dis1 = base + OFF_DIS1;
    float* dis2 = base + OFF_DIS2;
    float* p1   = base + OFF_P1;
    float* p2   = base + OFF_P2;
    float* c1   = base + OFF_CNT1;
    float* c2   = base + OFF_CNT2;

    const int T = 256;
    int nz = (int)(SCRATCH_TOTAL - OFF_DIS1);
    zero_k<<<(nz + T - 1) / T, T>>>(dis1, nz);

    deg_k<<<(E1 + T - 1) / T, T>>>(e1, E1, dis1);
    deg_k<<<(E2 + T - 1) / T, T>>>(e2, E2, dis2);
    dis_k<<<(Nn + T - 1) / T, T>>>(dis1, Nn);
    dis_k<<<(Nn + T - 1) / T, T>>>(dis2, Nn);

    int nchunks = Nn * 64;
    int gN = (nchunks + T - 1) / T;

    // ---- layer 1, conv a ----
    sgemm_tc<false,false,false,false><<<gemm_grid(Nn, DD), 256>>>(x, w11, nullptr, h, Nn, DD, FIN);
    self_init_k<<<gN, T>>>(h, dis1, b11, x1, Nn);
    scatter_k<<<(E1 * 64 + T - 1) / T, T>>>(e1, E1, dis1, h, x1);
    // ---- layer 1, conv b ----
    sgemm_tc<false,false,false,false><<<gemm_grid(Nn, DD), 256>>>(x, w12, nullptr, h, Nn, DD, FIN);
    self_init_k<<<gN, T>>>(h, dis2, b12, x2, Nn);
    scatter_k<<<(E2 * 64 + T - 1) / T, T>>>(e2, E2, dis2, h, x2);
    // ---- mlp_1 (concat = two accumulate-GEMMs, relu fused into A-read) ----
    sgemm_tc<true,false,false,false><<<gemm_grid(Nn, DD), 256>>>(x1, m1w1, nullptr, hid, Nn, DD, DD);
    sgemm_tc<true,true,true,true><<<gemm_grid(Nn, DD), 256>>>(x2, m1w1 + (size_t)DD * DD, m1b1, hid, Nn, DD, DD);
    sgemm_tc<false,false,true,false><<<gemm_grid(Nn, DD), 256>>>(hid, m1w2, m1b2, hf, Nn, DD, DD);

    // ---- layer 2, conv a ----
    sgemm_tc<false,false,false,false><<<gemm_grid(Nn, DD), 256>>>(hf, w21, nullptr, h, Nn, DD, DD);
    self_init_k<<<gN, T>>>(h, dis1, b21, x1, Nn);
    scatter_k<<<(E1 * 64 + T - 1) / T, T>>>(e1, E1, dis1, h, x1);
    // ---- layer 2, conv b ----
    sgemm_tc<false,false,false,false><<<gemm_grid(Nn, DD), 256>>>(hf, w22, nullptr, h, Nn, DD, DD);
    self_init_k<<<gN, T>>>(h, dis2, b22, x2, Nn);
    scatter_k<<<(E2 * 64 + T - 1) / T, T>>>(e2, E2, dis2, h, x2);
    // ---- mlp_2 ----
    sgemm_tc<true,false,false,false><<<gemm_grid(Nn, DD), 256>>>(x1, m2w1, nullptr, hid, Nn, DD, DD);
    sgemm_tc<true,true,true,true><<<gemm_grid(Nn, DD), 256>>>(x2, m2w1 + (size_t)DD * DD, m2b1, hid, Nn, DD, DD);
    sgemm_tc<false,false,true,false><<<gemm_grid(Nn, DD), 256>>>(hid, m2w2, m2b2, hf, Nn, DD, DD);

    // ---- pooling ----
    count_k<<<(Nn + T - 1) / T, T>>>(i1, i2, c1, c2, Nn);
    pool_k<<<gN, T>>>(hf, i1, i2, p1, p2, Nn);
    norm_k<<<(S * 64 + T - 1) / T, T>>>(p1, p2, c1, c2, S);

    // ---- head ----
    sgemm_tc<false,false,false,false><<<gemm_grid(S, DD), 256>>>(p1, mw1, nullptr, hid2, S, DD, DD);
    sgemm_tc<false,true,true,true><<<gemm_grid(S, DD), 256>>>(p2, mw1 + (size_t)DD * DD, mb1, hid2, S, DD, DD);
    final_k<<<S, DD>>>(hid2, mw2, mb2, out);
}

// round 6
// speedup vs baseline: 1.7148x; 1.3583x over previous
#include <cuda_runtime.h>
#include <cuda_bf16.h>
#include <math.h>
#include <stdint.h>
#include <cstdint>

// ---------------- Problem constants ----------------
#define DD 256
#define FIN 128
#define CC 7

// ---------------- Scratch layout (floats) ----------------
#define OFF_H     0L
#define OFF_X1    25600000L
#define OFF_X2    51200000L
#define OFF_HID   76800000L
#define OFF_HF    102400000L
#define OFF_AH    128000000L   // bf16 [M,512] hi  (25.6M floats)
#define OFF_AL    153600000L   // bf16 [M,512] lo
#define OFF_WH    179200000L   // bf16 weight hi (131072 bf16)
#define OFF_WL    179265536L
#define OFF_HID2  179331072L
#define OFF_DIS1  180611072L
#define OFF_DIS2  180711072L
#define OFF_P1    180811072L
#define OFF_P2    182091072L
#define OFF_CNT1  183371072L
#define OFF_CNT2  183376072L
#define SCRATCH_TOTAL 183381072L

__device__ float g_buf[SCRATCH_TOTAL];

// ---------------- helpers ----------------
__device__ __forceinline__ void atomicAddF4(float* p, float4 v) {
    asm volatile("red.global.add.v4.f32 [%0], {%1,%2,%3,%4};"
                 :: "l"(p), "f"(v.x), "f"(v.y), "f"(v.z), "f"(v.w) : "memory");
}

__device__ __forceinline__ void splitbf(float v, __nv_bfloat16& h, __nv_bfloat16& l) {
    h = __float2bfloat16(v);
    l = __float2bfloat16(v - __bfloat162float(h));
}

__device__ __forceinline__ void ldm_x4(uint32_t r[4], const void* p) {
    uint32_t addr = (uint32_t)__cvta_generic_to_shared(p);
    asm volatile("ldmatrix.sync.aligned.m8n8.x4.shared.b16 {%0,%1,%2,%3}, [%4];"
                 : "=r"(r[0]), "=r"(r[1]), "=r"(r[2]), "=r"(r[3]) : "r"(addr));
}

__device__ __forceinline__ void mma16816(float c[4], const uint32_t a[4],
                                         uint32_t b0, uint32_t b1) {
    asm volatile(
        "mma.sync.aligned.m16n8k16.row.col.f32.bf16.bf16.f32 "
        "{%0,%1,%2,%3}, {%4,%5,%6,%7}, {%8,%9}, {%0,%1,%2,%3};"
        : "+f"(c[0]), "+f"(c[1]), "+f"(c[2]), "+f"(c[3])
        : "r"(a[0]), "r"(a[1]), "r"(a[2]), "r"(a[3]), "r"(b0), "r"(b1));
}

__device__ __forceinline__ void cp16(uint32_t s, const void* g, int sz) {
    asm volatile("cp.async.cg.shared.global [%0], [%1], 16, %2;"
                 :: "r"(s), "l"(g), "r"(sz));
}

// ---------------- split kernels ----------------
// src fp32 [M,Ks] -> dh/dl bf16 at [r*dstride + coff + c], optional relu
template<bool RELU>
__global__ void splitA_k(const float* __restrict__ src, int Ks,
                         __nv_bfloat16* __restrict__ dh, __nv_bfloat16* __restrict__ dl,
                         int dstride, int coff, long total4) {
    long gid = blockIdx.x * (long)blockDim.x + threadIdx.x;
    if (gid >= total4) return;
    long e = gid * 4;
    long r = e / Ks;
    int  c = (int)(e - r * Ks);
    float4 v = *(const float4*)(src + e);
    if (RELU) {
        v.x = fmaxf(v.x, 0.f); v.y = fmaxf(v.y, 0.f);
        v.z = fmaxf(v.z, 0.f); v.w = fmaxf(v.w, 0.f);
    }
    __nv_bfloat16 h0,l0,h1,l1,h2,l2,h3,l3;
    splitbf(v.x,h0,l0); splitbf(v.y,h1,l1); splitbf(v.z,h2,l2); splitbf(v.w,h3,l3);
    __nv_bfloat162* ph = (__nv_bfloat162*)(dh + r * (long)dstride + coff + c);
    __nv_bfloat162* pl = (__nv_bfloat162*)(dl + r * (long)dstride + coff + c);
    __nv_bfloat162 t;
    t.x=h0; t.y=h1; ph[0]=t;  t.x=h2; t.y=h3; ph[1]=t;
    t.x=l0; t.y=l1; pl[0]=t;  t.x=l2; t.y=l3; pl[1]=t;
}

// W [K,N] fp32 -> Wt hi/lo bf16 [N][K]
__global__ void splitW_k(const float* __restrict__ w, int K, int N,
                         __nv_bfloat16* __restrict__ dh, __nv_bfloat16* __restrict__ dl) {
    int gid = blockIdx.x * blockDim.x + threadIdx.x;
    if (gid >= K * N) return;
    int k = gid / N, n = gid - k * N;
    __nv_bfloat16 h, l;
    splitbf(w[gid], h, l);
    dh[n * K + k] = h;
    dl[n * K + k] = l;
}

// ---------------- small kernels ----------------
__global__ void zero_k(float* __restrict__ p, int n) {
    int i = blockIdx.x * blockDim.x + threadIdx.x;
    if (i < n) p[i] = 0.0f;
}

__global__ void deg_k(const int* __restrict__ ei, int E, float* __restrict__ deg) {
    int i = blockIdx.x * blockDim.x + threadIdx.x;
    if (i < E) atomicAdd(&deg[ei[E + i]], 1.0f);
}

__global__ void dis_k(float* __restrict__ d, int n) {
    int i = blockIdx.x * blockDim.x + threadIdx.x;
    if (i < n) d[i] = rsqrtf(d[i] + 1.0f);
}

__global__ void scatter_k(const int* __restrict__ ei, int E,
                          const float* __restrict__ dis,
                          const float* __restrict__ h,
                          float* __restrict__ out) {
    int gid = blockIdx.x * blockDim.x + threadIdx.x;
    int total = E * 64;
    if (gid >= total) return;
    int e = gid >> 6;
    int c = (gid & 63) << 2;
    int r  = ei[e];
    int cl = ei[E + e];
    float coef = dis[r] * dis[cl];
    float4 hv = *(const float4*)(h + (size_t)r * DD + c);
    float4 m;
    m.x = coef*hv.x; m.y = coef*hv.y; m.z = coef*hv.z; m.w = coef*hv.w;
    atomicAddF4(out + (size_t)cl * DD + c, m);
}

__global__ void count_k(const int* __restrict__ i1, const int* __restrict__ i2,
                        float* __restrict__ c1, float* __restrict__ c2, int Nn) {
    int i = blockIdx.x * blockDim.x + threadIdx.x;
    if (i < Nn) {
        atomicAdd(&c1[i1[i]], 1.0f);
        atomicAdd(&c2[i2[i]], 1.0f);
    }
}

__global__ void pool_k(const float* __restrict__ h,
                       const int* __restrict__ i1, const int* __restrict__ i2,
                       float* __restrict__ p1, float* __restrict__ p2, int Nn) {
    int gid = blockIdx.x * blockDim.x + threadIdx.x;
    int total = Nn * 64;
    if (gid >= total) return;
    int i = gid >> 6;
    int c = (gid & 63) << 2;
    float4 hv = *(const float4*)(h + (size_t)i * DD + c);
    atomicAddF4(p1 + (size_t)i1[i] * DD + c, hv);
    atomicAddF4(p2 + (size_t)i2[i] * DD + c, hv);
}

__global__ void norm_k(float* __restrict__ p1, float* __restrict__ p2,
                       const float* __restrict__ c1, const float* __restrict__ c2, int S) {
    int gid = blockIdx.x * blockDim.x + threadIdx.x;
    int total = S * 64;
    if (gid >= total) return;
    int s = gid >> 6;
    int c = (gid & 63) << 2;
    float s1 = 1.0f / fmaxf(c1[s], 1.0f);
    float s2 = 1.0f / fmaxf(c2[s], 1.0f);
    float4 a = *(float4*)(p1 + (size_t)s * DD + c);
    a.x*=s1; a.y*=s1; a.z*=s1; a.w*=s1;
    *(float4*)(p1 + (size_t)s * DD + c) = a;
    float4 b = *(float4*)(p2 + (size_t)s * DD + c);
    b.x*=s2; b.y*=s2; b.z*=s2; b.w*=s2;
    *(float4*)(p2 + (size_t)s * DD + c) = b;
}

__global__ void final_k(const float* __restrict__ hid, const float* __restrict__ w2,
                        const float* __restrict__ b2, float* __restrict__ out) {
    __shared__ float sh[DD];
    __shared__ float lg[CC];
    int s = blockIdx.x;
    int tid = threadIdx.x;
    sh[tid] = hid[(size_t)s * DD + tid];
    __syncthreads();
    int w = tid >> 5, lane = tid & 31;
    if (w < CC) {
        float sum = 0.0f;
        for (int k = lane; k < DD; k += 32) sum += sh[k] * w2[k * CC + w];
        #pragma unroll
        for (int o = 16; o > 0; o >>= 1) sum += __shfl_xor_sync(0xFFFFFFFFu, sum, o);
        if (lane == 0) lg[w] = sum + b2[w];
    }
    __syncthreads();
    if (tid == 0) {
        float mx = -1e30f;
        #pragma unroll
        for (int c = 0; c < CC; c++) mx = fmaxf(mx, lg[c]);
        float se = 0.0f;
        #pragma unroll
        for (int c = 0; c < CC; c++) se += expf(lg[c] - mx);
        float lse = mx + logf(se);
        #pragma unroll
        for (int c = 0; c < CC; c++) out[(size_t)s * CC + c] = lg[c] - lse;
    }
}

// ---------------- bf16 double-buffered GEMM ----------------
// C[M,256] = A @ Wt^T with 3-term hi/lo split. Epilogues:
//   EPI=1 (SELF):      C = acc (h);  D = bias + dis[r]^2 * acc
//   EPI=2 (BIASRELU):  C = relu(acc + bias)
//   EPI=3 (BIAS):      C = acc + bias
#define LDK2 40
#define STAGE_BYTES 40960   // 4 matrices * 128*40*2

__device__ __forceinline__ void gemm_prefetch(
    char* smbase, int stage, int row, int half,
    const __nv_bfloat16* AH, const __nv_bfloat16* AL, int lda,
    const __nv_bfloat16* BH, const __nv_bfloat16* BL, int ldb,
    int bm, int bn, int M, int k0)
{
    int gra = bm + row;
    int szA = (gra < M) ? 16 : 0;
    if (gra >= M) gra = 0;
    const char* pAH = (const char*)(AH + (size_t)gra * lda + k0) + half * 32;
    const char* pAL = (const char*)(AL + (size_t)gra * lda + k0) + half * 32;
    int grb = bn + row;
    const char* pBH = (const char*)(BH + (size_t)grb * ldb + k0) + half * 32;
    const char* pBL = (const char*)(BL + (size_t)grb * ldb + k0) + half * 32;
    uint32_t so = (uint32_t)__cvta_generic_to_shared(smbase + stage * STAGE_BYTES)
                  + row * (LDK2 * 2) + half * 32;
    cp16(so,              pAH,      szA);  cp16(so + 16,          pAH + 16, szA);
    cp16(so + 10240,      pAL,      szA);  cp16(so + 10240 + 16,  pAL + 16, szA);
    cp16(so + 20480,      pBH,      16);   cp16(so + 20480 + 16,  pBH + 16, 16);
    cp16(so + 30720,      pBL,      16);   cp16(so + 30720 + 16,  pBL + 16, 16);
}

template<int EPI>
__global__ void __launch_bounds__(256)
gemm_bf16(const __nv_bfloat16* __restrict__ AH, const __nv_bfloat16* __restrict__ AL, int lda,
          const __nv_bfloat16* __restrict__ BH, const __nv_bfloat16* __restrict__ BL, int ldb,
          float* __restrict__ C, float* __restrict__ D,
          const float* __restrict__ dis, const float* __restrict__ bias,
          int M, int K)
{
    extern __shared__ char sm_[];
    int tid = threadIdx.x, wid = tid >> 5, lane = tid & 31;
    int bm = blockIdx.y * 128, bn = blockIdx.x * 128;
    int wm = (wid & 3) * 32, wn = (wid >> 2) * 64;
    int idx = lane >> 3, lr = lane & 7;
    int row = tid >> 1, half = tid & 1;

    float acc[2][8][4];
    #pragma unroll
    for (int i = 0; i < 2; i++)
        #pragma unroll
        for (int j = 0; j < 8; j++)
            #pragma unroll
            for (int q = 0; q < 4; q++) acc[i][j][q] = 0.0f;

    int KT = K >> 5;
    gemm_prefetch(sm_, 0, row, half, AH, AL, lda, BH, BL, ldb, bm, bn, M, 0);
    asm volatile("cp.async.commit_group;");

    for (int kt = 0; kt < KT; kt++) {
        int s = kt & 1;
        if (kt + 1 < KT) {
            gemm_prefetch(sm_, s ^ 1, row, half, AH, AL, lda, BH, BL, ldb,
                          bm, bn, M, (kt + 1) << 5);
            asm volatile("cp.async.commit_group;");
            asm volatile("cp.async.wait_group 1;");
        } else {
            asm volatile("cp.async.wait_group 0;");
        }
        __syncthreads();

        const __nv_bfloat16* sAh = (const __nv_bfloat16*)(sm_ + s * STAGE_BYTES);
        const __nv_bfloat16* sAl = (const __nv_bfloat16*)(sm_ + s * STAGE_BYTES + 10240);
        const __nv_bfloat16* sBh = (const __nv_bfloat16*)(sm_ + s * STAGE_BYTES + 20480);
        const __nv_bfloat16* sBl = (const __nv_bfloat16*)(sm_ + s * STAGE_BYTES + 30720);

        #pragma unroll
        for (int ks = 0; ks < 2; ks++) {
            int kb = ks * 16;
            uint32_t ah[2][4], al[2][4];
            #pragma unroll
            for (int mf = 0; mf < 2; mf++) {
                int rr = wm + mf * 16 + (idx & 1) * 8 + lr;
                int cc = kb + (idx >> 1) * 8;
                ldm_x4(ah[mf], &sAh[rr * LDK2 + cc]);
                ldm_x4(al[mf], &sAl[rr * LDK2 + cc]);
            }
            uint32_t bh[4][4], bl[4][4];
            #pragma unroll
            for (int bg = 0; bg < 4; bg++) {
                int rr = wn + bg * 16 + (idx >> 1) * 8 + lr;
                int cc = kb + (idx & 1) * 8;
                ldm_x4(bh[bg], &sBh[rr * LDK2 + cc]);
                ldm_x4(bl[bg], &sBl[rr * LDK2 + cc]);
            }
            #pragma unroll
            for (int mf = 0; mf < 2; mf++)
                #pragma unroll
                for (int ng = 0; ng < 8; ng++) {
                    int bg = ng >> 1, pr = (ng & 1) * 2;
                    mma16816(acc[mf][ng], ah[mf], bh[bg][pr], bh[bg][pr + 1]);
                    mma16816(acc[mf][ng], ah[mf], bl[bg][pr], bl[bg][pr + 1]);
                    mma16816(acc[mf][ng], al[mf], bh[bg][pr], bh[bg][pr + 1]);
                }
        }
        __syncthreads();
    }

    // ---- epilogue ----
    int r0 = bm + wm + (lane >> 2);
    int cb = bn + wn + (lane & 3) * 2;
    #pragma unroll
    for (int mf = 0; mf < 2; mf++) {
        #pragma unroll
        for (int hf2 = 0; hf2 < 2; hf2++) {
            int r = r0 + mf * 16 + hf2 * 8;
            if (r >= M) continue;
            float d2 = 0.0f;
            if (EPI == 1) { float dv = dis[r]; d2 = dv * dv; }
            #pragma unroll
            for (int ng = 0; ng < 8; ng++) {
                int c = cb + ng * 8;
                float v0 = acc[mf][ng][hf2 * 2 + 0];
                float v1 = acc[mf][ng][hf2 * 2 + 1];
                float* cp = C + (size_t)r * 256 + c;
                if (EPI == 1) {
                    float2 st; st.x = v0; st.y = v1;
                    *(float2*)cp = st;
                    float2 dd;
                    dd.x = bias[c]     + d2 * v0;
                    dd.y = bias[c + 1] + d2 * v1;
                    *(float2*)(D + (size_t)r * 256 + c) = dd;
                } else if (EPI == 2) {
                    float2 st;
                    st.x = fmaxf(v0 + bias[c], 0.f);
                    st.y = fmaxf(v1 + bias[c + 1], 0.f);
                    *(float2*)cp = st;
                } else {
                    float2 st;
                    st.x = v0 + bias[c];
                    st.y = v1 + bias[c + 1];
                    *(float2*)cp = st;
                }
            }
        }
    }
}

// ---------------- launch ----------------
#define SMEM_GEMM (2 * STAGE_BYTES)

extern "C" void kernel_launch(void* const* d_in, const int* in_sizes, int n_in,
                              void* d_out, int out_size) {
    const float* x    = (const float*)d_in[0];
    const int*   e1   = (const int*)d_in[1];
    const int*   e2   = (const int*)d_in[2];
    const int*   i1   = (const int*)d_in[3];
    const int*   i2   = (const int*)d_in[4];
    const float* w11  = (const float*)d_in[5];
    const float* b11  = (const float*)d_in[6];
    const float* w12  = (const float*)d_in[7];
    const float* b12  = (const float*)d_in[8];
    const float* w21  = (const float*)d_in[9];
    const float* b21  = (const float*)d_in[10];
    const float* w22  = (const float*)d_in[11];
    const float* b22  = (const float*)d_in[12];
    const float* m1w1 = (const float*)d_in[13];
    const float* m1b1 = (const float*)d_in[14];
    const float* m1w2 = (const float*)d_in[15];
    const float* m1b2 = (const float*)d_in[16];
    const float* m2w1 = (const float*)d_in[17];
    const float* m2b1 = (const float*)d_in[18];
    const float* m2w2 = (const float*)d_in[19];
    const float* m2b2 = (const float*)d_in[20];
    const float* mw1  = (const float*)d_in[21];
    const float* mb1  = (const float*)d_in[22];
    const float* mw2  = (const float*)d_in[23];
    const float* mb2  = (const float*)d_in[24];
    float* out = (float*)d_out;

    int Nn = in_sizes[0] / FIN;
    int E1 = in_sizes[1] / 2;
    int E2 = in_sizes[2] / 2;
    int S  = out_size / CC;

    float* base = nullptr;
    cudaGetSymbolAddress((void**)&base, g_buf);
    float* h    = base + OFF_H;
    float* x1   = base + OFF_X1;
    float* x2   = base + OFF_X2;
    float* hid  = base + OFF_HID;
    float* hf   = base + OFF_HF;
    float* hid2 = base + OFF_HID2;
    float* dis1 = base + OFF_DIS1;
    float* dis2 = base + OFF_DIS2;
    float* p1   = base + OFF_P1;
    float* p2   = base + OFF_P2;
    float* c1   = base + OFF_CNT1;
    float* c2   = base + OFF_CNT2;
    __nv_bfloat16* aH = (__nv_bfloat16*)(base + OFF_AH);
    __nv_bfloat16* aL = (__nv_bfloat16*)(base + OFF_AL);
    __nv_bfloat16* wH = (__nv_bfloat16*)(base + OFF_WH);
    __nv_bfloat16* wL = (__nv_bfloat16*)(base + OFF_WL);

    cudaFuncSetAttribute(gemm_bf16<1>, cudaFuncAttributeMaxDynamicSharedMemorySize, SMEM_GEMM);
    cudaFuncSetAttribute(gemm_bf16<2>, cudaFuncAttributeMaxDynamicSharedMemorySize, SMEM_GEMM);
    cudaFuncSetAttribute(gemm_bf16<3>, cudaFuncAttributeMaxDynamicSharedMemorySize, SMEM_GEMM);

    const int T = 256;
    dim3 gg(2, (unsigned)((Nn + 127) / 128));
    dim3 gs(2, (unsigned)((S + 127) / 128));

    long t4;
    #define SPLITA(RELU, SRC, KS, STRIDE, COFF, M_) \
        t4 = (long)(M_) * (KS) / 4; \
        splitA_k<RELU><<<(unsigned)((t4 + T - 1) / T), T>>>(SRC, KS, aH, aL, STRIDE, COFF, t4)
    #define SPLITW(W, K_, N_) \
        splitW_k<<<((K_) * (N_) + T - 1) / T, T>>>(W, K_, N_, wH, wL)

    int nz = (int)(SCRATCH_TOTAL - OFF_DIS1);
    int gE1 = (E1 * 64 + T - 1) / T, gE2 = (E2 * 64 + T - 1) / T;
    int gN64 = (Nn * 64 + T - 1) / T;

    // ---- prologue (ordered so launch #6 = conv GEMM for ncu) ----
    SPLITA(false, x, FIN, FIN, 0, Nn);                 // 1
    SPLITW(w11, FIN, DD);                              // 2
    zero_k<<<(nz + T - 1) / T, T>>>(dis1, nz);         // 3
    deg_k<<<(E1 + T - 1) / T, T>>>(e1, E1, dis1);      // 4
    dis_k<<<(Nn + T - 1) / T, T>>>(dis1, Nn);          // 5

    // ---- layer 1, conv a ----
    gemm_bf16<1><<<gg, 256, SMEM_GEMM>>>(aH, aL, FIN, wH, wL, FIN, h, x1, dis1, b11, Nn, FIN); // 6
    scatter_k<<<gE1, T>>>(e1, E1, dis1, h, x1);
    // ---- layer 1, conv b ----
    deg_k<<<(E2 + T - 1) / T, T>>>(e2, E2, dis2);
    dis_k<<<(Nn + T - 1) / T, T>>>(dis2, Nn);
    SPLITW(w12, FIN, DD);
    gemm_bf16<1><<<gg, 256, SMEM_GEMM>>>(aH, aL, FIN, wH, wL, FIN, h, x2, dis2, b12, Nn, FIN);
    scatter_k<<<gE2, T>>>(e2, E2, dis2, h, x2);
    // ---- mlp_1 (single K=512 GEMM over concat, relu fused into split) ----
    SPLITA(true, x1, DD, 512, 0, Nn);
    SPLITA(true, x2, DD, 512, DD, Nn);
    SPLITW(m1w1, 2 * DD, DD);
    gemm_bf16<2><<<gg, 256, SMEM_GEMM>>>(aH, aL, 512, wH, wL, 512, hid, nullptr, nullptr, m1b1, Nn, 512);
    SPLITA(false, hid, DD, DD, 0, Nn);
    SPLITW(m1w2, DD, DD);
    gemm_bf16<3><<<gg, 256, SMEM_GEMM>>>(aH, aL, DD, wH, wL, DD, hf, nullptr, nullptr, m1b2, Nn, DD);

    // ---- layer 2 (A = hf for both convs: split once) ----
    SPLITA(false, hf, DD, DD, 0, Nn);
    SPLITW(w21, DD, DD);
    gemm_bf16<1><<<gg, 256, SMEM_GEMM>>>(aH, aL, DD, wH, wL, DD, h, x1, dis1, b21, Nn, DD);
    scatter_k<<<gE1, T>>>(e1, E1, dis1, h, x1);
    SPLITW(w22, DD, DD);
    gemm_bf16<1><<<gg, 256, SMEM_GEMM>>>(aH, aL, DD, wH, wL, DD, h, x2, dis2, b22, Nn, DD);
    scatter_k<<<gE2, T>>>(e2, E2, dis2, h, x2);
    // ---- mlp_2 ----
    SPLITA(true, x1, DD, 512, 0, Nn);
    SPLITA(true, x2, DD, 512, DD, Nn);
    SPLITW(m2w1, 2 * DD, DD);
    gemm_bf16<2><<<gg, 256, SMEM_GEMM>>>(aH, aL, 512, wH, wL, 512, hid, nullptr, nullptr, m2b1, Nn, 512);
    SPLITA(false, hid, DD, DD, 0, Nn);
    SPLITW(m2w2, DD, DD);
    gemm_bf16<3><<<gg, 256, SMEM_GEMM>>>(aH, aL, DD, wH, wL, DD, hf, nullptr, nullptr, m2b2, Nn, DD);

    // ---- pooling ----
    count_k<<<(Nn + T - 1) / T, T>>>(i1, i2, c1, c2, Nn);
    pool_k<<<gN64, T>>>(hf, i1, i2, p1, p2, Nn);
    norm_k<<<(S * 64 + T - 1) / T, T>>>(p1, p2, c1, c2, S);

    // ---- head ----
    SPLITA(false, p1, DD, 512, 0, S);
    SPLITA(false, p2, DD, 512, DD, S);
    SPLITW(mw1, 2 * DD, DD);
    gemm_bf16<2><<<gs, 256, SMEM_GEMM>>>(aH, aL, 512, wH, wL, 512, hid2, nullptr, nullptr, mb1, S, 512);
    final_k<<<S, DD>>>(hid2, mw2, mb2, out);
}

// round 7
// speedup vs baseline: 1.7725x; 1.0336x over previous
#include <cuda_runtime.h>
#include <cuda_bf16.h>
#include <math.h>
#include <stdint.h>
#include <cstdint>

// ---------------- Problem constants ----------------
#define DD 256
#define FIN 128
#define CC 7

// ---------------- Scratch layout (float offsets) ----------------
#define OFF_H     0L            // fp32 [M,512] conv GEMM out (both halves)
#define OFF_X1    51200000L     // fp32 [M,256]
#define OFF_X2    76800000L
#define OFF_HF    102400000L    // fp32 [M,256] final node features
#define OFF_XH    128000000L    // bf16 [M,512] A-buffer X hi
#define OFF_XL    153600000L
#define OFF_YH    179200000L    // bf16 [M,256] A-buffer Y hi
#define OFF_YL    192000000L
#define OFF_WH    204800000L    // bf16 weights (<=131072 elems)
#define OFF_WL    204865536L
#define OFF_HID2  204931072L
#define OFF_DIS1  206211072L
#define OFF_P1    206411072L
#define OFF_P2    207691072L
#define OFF_CNT1  208971072L
#define OFF_CNT2  208976072L
#define SCRATCH_TOTAL 208981072L

__device__ float g_buf[SCRATCH_TOTAL];

// ---------------- helpers ----------------
__device__ __forceinline__ void atomicAddF4(float* p, float4 v) {
    asm volatile("red.global.add.v4.f32 [%0], {%1,%2,%3,%4};"
                 :: "l"(p), "f"(v.x), "f"(v.y), "f"(v.z), "f"(v.w) : "memory");
}

__device__ __forceinline__ void splitbf(float v, __nv_bfloat16& h, __nv_bfloat16& l) {
    h = __float2bfloat16(v);
    l = __float2bfloat16(v - __bfloat162float(h));
}

__device__ __forceinline__ void ldm_x4(uint32_t r[4], const void* p) {
    uint32_t addr = (uint32_t)__cvta_generic_to_shared(p);
    asm volatile("ldmatrix.sync.aligned.m8n8.x4.shared.b16 {%0,%1,%2,%3}, [%4];"
                 : "=r"(r[0]), "=r"(r[1]), "=r"(r[2]), "=r"(r[3]) : "r"(addr));
}

__device__ __forceinline__ void mma16816(float c[4], const uint32_t a[4],
                                         uint32_t b0, uint32_t b1) {
    asm volatile(
        "mma.sync.aligned.m16n8k16.row.col.f32.bf16.bf16.f32 "
        "{%0,%1,%2,%3}, {%4,%5,%6,%7}, {%8,%9}, {%0,%1,%2,%3};"
        : "+f"(c[0]), "+f"(c[1]), "+f"(c[2]), "+f"(c[3])
        : "r"(a[0]), "r"(a[1]), "r"(a[2]), "r"(a[3]), "r"(b0), "r"(b1));
}

__device__ __forceinline__ void cp16(uint32_t s, const void* g, int sz) {
    asm volatile("cp.async.cg.shared.global [%0], [%1], 16, %2;"
                 :: "r"(s), "l"(g), "r"(sz));
}

// ---------------- split kernels ----------------
template<bool RELU>
__global__ void splitA_k(const float* __restrict__ src, int Ks,
                         __nv_bfloat16* __restrict__ dh, __nv_bfloat16* __restrict__ dl,
                         int dstride, int coff, long total4) {
    long gid = blockIdx.x * (long)blockDim.x + threadIdx.x;
    if (gid >= total4) return;
    long e = gid * 4;
    long r = e / Ks;
    int  c = (int)(e - r * Ks);
    float4 v = *(const float4*)(src + e);
    if (RELU) {
        v.x = fmaxf(v.x, 0.f); v.y = fmaxf(v.y, 0.f);
        v.z = fmaxf(v.z, 0.f); v.w = fmaxf(v.w, 0.f);
    }
    __nv_bfloat16 h0,l0,h1,l1,h2,l2,h3,l3;
    splitbf(v.x,h0,l0); splitbf(v.y,h1,l1); splitbf(v.z,h2,l2); splitbf(v.w,h3,l3);
    __nv_bfloat162* ph = (__nv_bfloat162*)(dh + r * (long)dstride + coff + c);
    __nv_bfloat162* pl = (__nv_bfloat162*)(dl + r * (long)dstride + coff + c);
    __nv_bfloat162 t;
    t.x=h0; t.y=h1; ph[0]=t;  t.x=h2; t.y=h3; ph[1]=t;
    t.x=l0; t.y=l1; pl[0]=t;  t.x=l2; t.y=l3; pl[1]=t;
}

// single weight W[K,N] -> Wt hi/lo [N][K]
__global__ void splitW_k(const float* __restrict__ w, int K, int N,
                         __nv_bfloat16* __restrict__ dh, __nv_bfloat16* __restrict__ dl) {
    int gid = blockIdx.x * blockDim.x + threadIdx.x;
    if (gid >= K * N) return;
    int k = gid / N, n = gid - k * N;
    __nv_bfloat16 h, l;
    splitbf(w[gid], h, l);
    dh[n * K + k] = h;
    dl[n * K + k] = l;
}

// dual weights wA,wB [K,N] -> Wt [2N][K] (wA rows 0..N-1, wB rows N..2N-1)
__global__ void splitWdual_k(const float* __restrict__ wA, const float* __restrict__ wB,
                             int K, int N,
                             __nv_bfloat16* __restrict__ dh, __nv_bfloat16* __restrict__ dl) {
    int gid = blockIdx.x * blockDim.x + threadIdx.x;
    int tot = K * N;
    if (gid >= 2 * tot) return;
    int which = gid >= tot;
    int g = gid - which * tot;
    int k = g / N, n = g - k * N;
    __nv_bfloat16 h, l;
    splitbf(which ? wB[g] : wA[g], h, l);
    dh[(n + which * N) * K + k] = h;
    dl[(n + which * N) * K + k] = l;
}

// ---------------- small kernels ----------------
__global__ void zero_k(float* __restrict__ p, int n) {
    int i = blockIdx.x * blockDim.x + threadIdx.x;
    if (i < n) p[i] = 0.0f;
}

__global__ void degboth_k(const int* __restrict__ e1, int E1,
                          const int* __restrict__ e2, int E2,
                          float* __restrict__ d1, float* __restrict__ d2) {
    int i = blockIdx.x * blockDim.x + threadIdx.x;
    if (i < E1) atomicAdd(&d1[e1[E1 + i]], 1.0f);
    else if (i < E1 + E2) atomicAdd(&d2[e2[E2 + (i - E1)]], 1.0f);
}

__global__ void dis_k(float* __restrict__ d, int n) {
    int i = blockIdx.x * blockDim.x + threadIdx.x;
    if (i < n) d[i] = rsqrtf(d[i] + 1.0f);
}

// out[col,:] += dis[row]*dis[col]*h[row, hoff:hoff+256]  (h stride 512)
__global__ void scatter_k(const int* __restrict__ ei, int E,
                          const float* __restrict__ dis,
                          const float* __restrict__ h,
                          float* __restrict__ out) {
    int gid = blockIdx.x * blockDim.x + threadIdx.x;
    int total = E * 64;
    if (gid >= total) return;
    int e = gid >> 6;
    int c = (gid & 63) << 2;
    int r  = ei[e];
    int cl = ei[E + e];
    float coef = dis[r] * dis[cl];
    float4 hv = *(const float4*)(h + (size_t)r * 512 + c);
    float4 m;
    m.x = coef*hv.x; m.y = coef*hv.y; m.z = coef*hv.z; m.w = coef*hv.w;
    atomicAddF4(out + (size_t)cl * DD + c, m);
}

__global__ void count_k(const int* __restrict__ i1, const int* __restrict__ i2,
                        float* __restrict__ c1, float* __restrict__ c2, int Nn) {
    int i = blockIdx.x * blockDim.x + threadIdx.x;
    if (i < Nn) {
        atomicAdd(&c1[i1[i]], 1.0f);
        atomicAdd(&c2[i2[i]], 1.0f);
    }
}

__global__ void pool_k(const float* __restrict__ h,
                       const int* __restrict__ i1, const int* __restrict__ i2,
                       float* __restrict__ p1, float* __restrict__ p2, int Nn) {
    int gid = blockIdx.x * blockDim.x + threadIdx.x;
    int total = Nn * 64;
    if (gid >= total) return;
    int i = gid >> 6;
    int c = (gid & 63) << 2;
    float4 hv = *(const float4*)(h + (size_t)i * DD + c);
    atomicAddF4(p1 + (size_t)i1[i] * DD + c, hv);
    atomicAddF4(p2 + (size_t)i2[i] * DD + c, hv);
}

__global__ void norm_k(float* __restrict__ p1, float* __restrict__ p2,
                       const float* __restrict__ c1, const float* __restrict__ c2, int S) {
    int gid = blockIdx.x * blockDim.x + threadIdx.x;
    int total = S * 64;
    if (gid >= total) return;
    int s = gid >> 6;
    int c = (gid & 63) << 2;
    float s1 = 1.0f / fmaxf(c1[s], 1.0f);
    float s2 = 1.0f / fmaxf(c2[s], 1.0f);
    float4 a = *(float4*)(p1 + (size_t)s * DD + c);
    a.x*=s1; a.y*=s1; a.z*=s1; a.w*=s1;
    *(float4*)(p1 + (size_t)s * DD + c) = a;
    float4 b = *(float4*)(p2 + (size_t)s * DD + c);
    b.x*=s2; b.y*=s2; b.z*=s2; b.w*=s2;
    *(float4*)(p2 + (size_t)s * DD + c) = b;
}

__global__ void final_k(const float* __restrict__ hid, const float* __restrict__ w2,
                        const float* __restrict__ b2, float* __restrict__ out) {
    __shared__ float sh[DD];
    __shared__ float lg[CC];
    int s = blockIdx.x;
    int tid = threadIdx.x;
    sh[tid] = hid[(size_t)s * DD + tid];
    __syncthreads();
    int w = tid >> 5, lane = tid & 31;
    if (w < CC) {
        float sum = 0.0f;
        for (int k = lane; k < DD; k += 32) sum += sh[k] * w2[k * CC + w];
        #pragma unroll
        for (int o = 16; o > 0; o >>= 1) sum += __shfl_xor_sync(0xFFFFFFFFu, sum, o);
        if (lane == 0) lg[w] = sum + b2[w];
    }
    __syncthreads();
    if (tid == 0) {
        float mx = -1e30f;
        #pragma unroll
        for (int c = 0; c < CC; c++) mx = fmaxf(mx, lg[c]);
        float se = 0.0f;
        #pragma unroll
        for (int c = 0; c < CC; c++) se += expf(lg[c] - mx);
        float lse = mx + logf(se);
        #pragma unroll
        for (int c = 0; c < CC; c++) out[(size_t)s * CC + c] = lg[c] - lse;
    }
}

// ---------------- bf16 double-buffered GEMM, fused epilogues ----------------
// EPI=1 CONV:  C[r*512+cg]=acc;  (cg<256)? x1[r,cg]=b1[cg]+dis1[r]^2*acc
//                                        : x2[r,cg-256]=b2[..]+dis2[r]^2*acc
// EPI=2 SPLIT_RELU: split(relu(acc+bias)) -> oH/oL
// EPI=3 SPLIT:      split(acc+bias)       -> oH/oL
// EPI=4 F32:        C[r*256+c] = acc+bias
// EPI=5 F32_RELU:   C[r*256+c] = relu(acc+bias)
#define LDK2 40
#define STAGE_BYTES 40960

__device__ __forceinline__ void gemm_prefetch(
    char* smbase, int stage, int row, int half,
    const __nv_bfloat16* AH, const __nv_bfloat16* AL, int lda,
    const __nv_bfloat16* BH, const __nv_bfloat16* BL, int ldb,
    int bm, int bn, int M, int k0)
{
    int gra = bm + row;
    int szA = (gra < M) ? 16 : 0;
    if (gra >= M) gra = 0;
    const char* pAH = (const char*)(AH + (size_t)gra * lda + k0) + half * 32;
    const char* pAL = (const char*)(AL + (size_t)gra * lda + k0) + half * 32;
    int grb = bn + row;
    const char* pBH = (const char*)(BH + (size_t)grb * ldb + k0) + half * 32;
    const char* pBL = (const char*)(BL + (size_t)grb * ldb + k0) + half * 32;
    uint32_t so = (uint32_t)__cvta_generic_to_shared(smbase + stage * STAGE_BYTES)
                  + row * (LDK2 * 2) + half * 32;
    cp16(so,              pAH,      szA);  cp16(so + 16,          pAH + 16, szA);
    cp16(so + 10240,      pAL,      szA);  cp16(so + 10240 + 16,  pAL + 16, szA);
    cp16(so + 20480,      pBH,      16);   cp16(so + 20480 + 16,  pBH + 16, 16);
    cp16(so + 30720,      pBL,      16);   cp16(so + 30720 + 16,  pBL + 16, 16);
}

template<int EPI>
__global__ void __launch_bounds__(256)
gemm_bf16(const __nv_bfloat16* __restrict__ AH, const __nv_bfloat16* __restrict__ AL, int lda,
          const __nv_bfloat16* __restrict__ BH, const __nv_bfloat16* __restrict__ BL, int ldb,
          float* __restrict__ C, float* __restrict__ D1, float* __restrict__ D2,
          const float* __restrict__ dis1, const float* __restrict__ dis2,
          const float* __restrict__ bias1, const float* __restrict__ bias2,
          __nv_bfloat16* __restrict__ oH, __nv_bfloat16* __restrict__ oL,
          int ostride, int ocoff,
          int M, int K)
{
    extern __shared__ char sm_[];
    int tid = threadIdx.x, wid = tid >> 5, lane = tid & 31;
    int bm = blockIdx.y * 128, bn = blockIdx.x * 128;
    int wm = (wid & 3) * 32, wn = (wid >> 2) * 64;
    int idx = lane >> 3, lr = lane & 7;
    int row = tid >> 1, half = tid & 1;

    float acc[2][8][4];
    #pragma unroll
    for (int i = 0; i < 2; i++)
        #pragma unroll
        for (int j = 0; j < 8; j++)
            #pragma unroll
            for (int q = 0; q < 4; q++) acc[i][j][q] = 0.0f;

    int KT = K >> 5;
    gemm_prefetch(sm_, 0, row, half, AH, AL, lda, BH, BL, ldb, bm, bn, M, 0);
    asm volatile("cp.async.commit_group;");

    for (int kt = 0; kt < KT; kt++) {
        int s = kt & 1;
        if (kt + 1 < KT) {
            gemm_prefetch(sm_, s ^ 1, row, half, AH, AL, lda, BH, BL, ldb,
                          bm, bn, M, (kt + 1) << 5);
            asm volatile("cp.async.commit_group;");
            asm volatile("cp.async.wait_group 1;");
        } else {
            asm volatile("cp.async.wait_group 0;");
        }
        __syncthreads();

        const __nv_bfloat16* sAh = (const __nv_bfloat16*)(sm_ + s * STAGE_BYTES);
        const __nv_bfloat16* sAl = (const __nv_bfloat16*)(sm_ + s * STAGE_BYTES + 10240);
        const __nv_bfloat16* sBh = (const __nv_bfloat16*)(sm_ + s * STAGE_BYTES + 20480);
        const __nv_bfloat16* sBl = (const __nv_bfloat16*)(sm_ + s * STAGE_BYTES + 30720);

        #pragma unroll
        for (int ks = 0; ks < 2; ks++) {
            int kb = ks * 16;
            uint32_t ah[2][4], al[2][4];
            #pragma unroll
            for (int mf = 0; mf < 2; mf++) {
                int rr = wm + mf * 16 + (idx & 1) * 8 + lr;
                int cc = kb + (idx >> 1) * 8;
                ldm_x4(ah[mf], &sAh[rr * LDK2 + cc]);
                ldm_x4(al[mf], &sAl[rr * LDK2 + cc]);
            }
            uint32_t bh[4][4], bl[4][4];
            #pragma unroll
            for (int bg = 0; bg < 4; bg++) {
                int rr = wn + bg * 16 + (idx >> 1) * 8 + lr;
                int cc = kb + (idx & 1) * 8;
                ldm_x4(bh[bg], &sBh[rr * LDK2 + cc]);
                ldm_x4(bl[bg], &sBl[rr * LDK2 + cc]);
            }
            #pragma unroll
            for (int mf = 0; mf < 2; mf++)
                #pragma unroll
                for (int ng = 0; ng < 8; ng++) {
                    int bg = ng >> 1, pr = (ng & 1) * 2;
                    mma16816(acc[mf][ng], ah[mf], bh[bg][pr], bh[bg][pr + 1]);
                    mma16816(acc[mf][ng], ah[mf], bl[bg][pr], bl[bg][pr + 1]);
                    mma16816(acc[mf][ng], al[mf], bh[bg][pr], bh[bg][pr + 1]);
                }
        }
        __syncthreads();
    }

    // ---- epilogue ----
    int r0 = bm + wm + (lane >> 2);
    int lc0 = wn + (lane & 3) * 2;   // local col in [0,128)
    bool second = (bn >= 256);       // EPI=1 half select (per block)
    const float* disp = (EPI == 1) ? (second ? dis2 : dis1) : nullptr;
    const float* bp   = (EPI == 1) ? (second ? bias2 : bias1) : bias1;
    float* Dp         = (EPI == 1) ? (second ? D2 : D1) : nullptr;
    int dcb = (EPI == 1) ? (bn - (second ? 256 : 0)) : bn;

    #pragma unroll
    for (int mf = 0; mf < 2; mf++) {
        #pragma unroll
        for (int hf2 = 0; hf2 < 2; hf2++) {
            int r = r0 + mf * 16 + hf2 * 8;
            if (r >= M) continue;
            float d2 = 0.0f;
            if (EPI == 1) { float dv = disp[r]; d2 = dv * dv; }
            #pragma unroll
            for (int ng = 0; ng < 8; ng++) {
                int lc = lc0 + ng * 8;
                float v0 = acc[mf][ng][hf2 * 2 + 0];
                float v1 = acc[mf][ng][hf2 * 2 + 1];
                if (EPI == 1) {
                    int cg = bn + lc;
                    float2 st; st.x = v0; st.y = v1;
                    *(float2*)(C + (size_t)r * 512 + cg) = st;
                    int dc = dcb + lc;
                    float2 dd;
                    dd.x = bp[dc]     + d2 * v0;
                    dd.y = bp[dc + 1] + d2 * v1;
                    *(float2*)(Dp + (size_t)r * 256 + dc) = dd;
                } else if (EPI == 2 || EPI == 3) {
                    int c = bn + lc;
                    v0 += bp[c]; v1 += bp[c + 1];
                    if (EPI == 2) { v0 = fmaxf(v0, 0.f); v1 = fmaxf(v1, 0.f); }
                    __nv_bfloat16 h0, l0, h1, l1;
                    splitbf(v0, h0, l0); splitbf(v1, h1, l1);
                    __nv_bfloat162 th; th.x = h0; th.y = h1;
                    __nv_bfloat162 tl; tl.x = l0; tl.y = l1;
                    size_t o = (size_t)r * ostride + ocoff + c;
                    *(__nv_bfloat162*)(oH + o) = th;
                    *(__nv_bfloat162*)(oL + o) = tl;
                } else {
                    int c = bn + lc;
                    v0 += bp[c]; v1 += bp[c + 1];
                    if (EPI == 5) { v0 = fmaxf(v0, 0.f); v1 = fmaxf(v1, 0.f); }
                    float2 st; st.x = v0; st.y = v1;
                    *(float2*)(C + (size_t)r * 256 + c) = st;
                }
            }
        }
    }
}

// ---------------- launch ----------------
#define SMEM_GEMM (2 * STAGE_BYTES)
typedef __nv_bfloat16 bf16;

extern "C" void kernel_launch(void* const* d_in, const int* in_sizes, int n_in,
                              void* d_out, int out_size) {
    const float* x    = (const float*)d_in[0];
    const int*   e1   = (const int*)d_in[1];
    const int*   e2   = (const int*)d_in[2];
    const int*   i1   = (const int*)d_in[3];
    const int*   i2   = (const int*)d_in[4];
    const float* w11  = (const float*)d_in[5];
    const float* b11  = (const float*)d_in[6];
    const float* w12  = (const float*)d_in[7];
    const float* b12  = (const float*)d_in[8];
    const float* w21  = (const float*)d_in[9];
    const float* b21  = (const float*)d_in[10];
    const float* w22  = (const float*)d_in[11];
    const float* b22  = (const float*)d_in[12];
    const float* m1w1 = (const float*)d_in[13];
    const float* m1b1 = (const float*)d_in[14];
    const float* m1w2 = (const float*)d_in[15];
    const float* m1b2 = (const float*)d_in[16];
    const float* m2w1 = (const float*)d_in[17];
    const float* m2b1 = (const float*)d_in[18];
    const float* m2w2 = (const float*)d_in[19];
    const float* m2b2 = (const float*)d_in[20];
    const float* mw1  = (const float*)d_in[21];
    const float* mb1  = (const float*)d_in[22];
    const float* mw2  = (const float*)d_in[23];
    const float* mb2  = (const float*)d_in[24];
    float* out = (float*)d_out;

    int Nn = in_sizes[0] / FIN;
    int E1 = in_sizes[1] / 2;
    int E2 = in_sizes[2] / 2;
    int S  = out_size / CC;

    float* base = nullptr;
    cudaGetSymbolAddress((void**)&base, g_buf);
    float* h    = base + OFF_H;
    float* x1   = base + OFF_X1;
    float* x2   = base + OFF_X2;
    float* hf   = base + OFF_HF;
    float* hid2 = base + OFF_HID2;
    float* dis1 = base + OFF_DIS1;
    float* dis2 = dis1 + Nn;
    float* p1   = base + OFF_P1;
    float* p2   = base + OFF_P2;
    float* c1   = base + OFF_CNT1;
    float* c2   = base + OFF_CNT2;
    bf16* XH = (bf16*)(base + OFF_XH);
    bf16* XL = (bf16*)(base + OFF_XL);
    bf16* YH = (bf16*)(base + OFF_YH);
    bf16* YL = (bf16*)(base + OFF_YL);
    bf16* WH = (bf16*)(base + OFF_WH);
    bf16* WL = (bf16*)(base + OFF_WL);

    cudaFuncSetAttribute(gemm_bf16<1>, cudaFuncAttributeMaxDynamicSharedMemorySize, SMEM_GEMM);
    cudaFuncSetAttribute(gemm_bf16<2>, cudaFuncAttributeMaxDynamicSharedMemorySize, SMEM_GEMM);
    cudaFuncSetAttribute(gemm_bf16<3>, cudaFuncAttributeMaxDynamicSharedMemorySize, SMEM_GEMM);
    cudaFuncSetAttribute(gemm_bf16<4>, cudaFuncAttributeMaxDynamicSharedMemorySize, SMEM_GEMM);
    cudaFuncSetAttribute(gemm_bf16<5>, cudaFuncAttributeMaxDynamicSharedMemorySize, SMEM_GEMM);

    const int T = 256;
    unsigned gy  = (unsigned)((Nn + 127) / 128);
    unsigned gys = (unsigned)((S + 127) / 128);
    dim3 g512(4, gy), g256(2, gy), gh(2, gys);
    int gE1 = (E1 * 64 + T - 1) / T, gE2 = (E2 * 64 + T - 1) / T;
    int gN64 = (Nn * 64 + T - 1) / T;
    int nz = (int)(SCRATCH_TOTAL - OFF_DIS1);
    long t4;
    #define SPLITA(RELU, SRC, KS, DH, DL, STRIDE, COFF, M_) \
        t4 = (long)(M_) * (KS) / 4; \
        splitA_k<RELU><<<(unsigned)((t4 + T - 1) / T), T>>>(SRC, KS, DH, DL, STRIDE, COFF, t4)

    // ---- prologue (conv1 GEMM = launch idx 5 for ncu -s 5 -c 1) ----
    zero_k<<<(nz + T - 1) / T, T>>>(dis1, nz);                                   // 0
    degboth_k<<<(E1 + E2 + T - 1) / T, T>>>(e1, E1, e2, E2, dis1, dis2);         // 1
    dis_k<<<(2 * Nn + T - 1) / T, T>>>(dis1, 2 * Nn);                            // 2
    SPLITA(false, x, FIN, XH, XL, 512, 0, Nn);                                   // 3
    splitWdual_k<<<(2 * FIN * DD + T - 1) / T, T>>>(w11, w12, FIN, DD, WH, WL);  // 4

    // ---- layer 1: dual conv GEMM (N=512) ----
    gemm_bf16<1><<<g512, 256, SMEM_GEMM>>>(XH, XL, 512, WH, WL, FIN,
        h, x1, x2, dis1, dis2, b11, b12, nullptr, nullptr, 0, 0, Nn, FIN);       // 5
    scatter_k<<<gE1, T>>>(e1, E1, dis1, h,       x1);
    scatter_k<<<gE2, T>>>(e2, E2, dis2, h + 256, x2);
    // ---- mlp_1 ----
    SPLITA(true, x1, DD, XH, XL, 512, 0,   Nn);
    SPLITA(true, x2, DD, XH, XL, 512, DD,  Nn);
    splitW_k<<<(2 * DD * DD + T - 1) / T, T>>>(m1w1, 2 * DD, DD, WH, WL);
    gemm_bf16<2><<<g256, 256, SMEM_GEMM>>>(XH, XL, 512, WH, WL, 512,
        nullptr, nullptr, nullptr, nullptr, nullptr, m1b1, nullptr, YH, YL, 256, 0, Nn, 512);
    splitW_k<<<(DD * DD + T - 1) / T, T>>>(m1w2, DD, DD, WH, WL);
    gemm_bf16<3><<<g256, 256, SMEM_GEMM>>>(YH, YL, 256, WH, WL, 256,
        nullptr, nullptr, nullptr, nullptr, nullptr, m1b2, nullptr, XH, XL, 512, 0, Nn, 256);

    // ---- layer 2: dual conv GEMM (A = h1 split in XH/XL cols 0-255) ----
    splitWdual_k<<<(2 * DD * DD + T - 1) / T, T>>>(w21, w22, DD, DD, WH, WL);
    gemm_bf16<1><<<g512, 256, SMEM_GEMM>>>(XH, XL, 512, WH, WL, DD,
        h, x1, x2, dis1, dis2, b21, b22, nullptr, nullptr, 0, 0, Nn, DD);
    scatter_k<<<gE1, T>>>(e1, E1, dis1, h,       x1);
    scatter_k<<<gE2, T>>>(e2, E2, dis2, h + 256, x2);
    // ---- mlp_2 ----
    SPLITA(true, x1, DD, XH, XL, 512, 0,  Nn);
    SPLITA(true, x2, DD, XH, XL, 512, DD, Nn);
    splitW_k<<<(2 * DD * DD + T - 1) / T, T>>>(m2w1, 2 * DD, DD, WH, WL);
    gemm_bf16<2><<<g256, 256, SMEM_GEMM>>>(XH, XL, 512, WH, WL, 512,
        nullptr, nullptr, nullptr, nullptr, nullptr, m2b1, nullptr, YH, YL, 256, 0, Nn, 512);
    splitW_k<<<(DD * DD + T - 1) / T, T>>>(m2w2, DD, DD, WH, WL);
    gemm_bf16<4><<<g256, 256, SMEM_GEMM>>>(YH, YL, 256, WH, WL, 256,
        hf, nullptr, nullptr, nullptr, nullptr, m2b2, nullptr, nullptr, nullptr, 0, 0, Nn, 256);

    // ---- pooling ----
    count_k<<<(Nn + T - 1) / T, T>>>(i1, i2, c1, c2, Nn);
    pool_k<<<gN64, T>>>(hf, i1, i2, p1, p2, Nn);
    norm_k<<<(S * 64 + T - 1) / T, T>>>(p1, p2, c1, c2, S);

    // ---- head ----
    SPLITA(false, p1, DD, XH, XL, 512, 0,  S);
    SPLITA(false, p2, DD, XH, XL, 512, DD, S);
    splitW_k<<<(2 * DD * DD + T - 1) / T, T>>>(mw1, 2 * DD, DD, WH, WL);
    gemm_bf16<5><<<gh, 256, SMEM_GEMM>>>(XH, XL, 512, WH, WL, 512,
        hid2, nullptr, nullptr, nullptr, nullptr, mb1, nullptr, nullptr, nullptr, 0, 0, S, 512);
    final_k<<<S, DD>>>(hid2, mw2, mb2, out);
}

// round 8
// speedup vs baseline: 2.2173x; 1.2509x over previous
#include <cuda_runtime.h>
#include <cuda_bf16.h>
#include <math.h>
#include <stdint.h>
#include <cstdint>

// ---------------- Problem constants ----------------
#define DD 256
#define FIN 128
#define CC 7

typedef __nv_bfloat16 bf16;

// ---------------- Scratch layout (float offsets) ----------------
#define OFF_H     0L             // fp32 [M,512] conv GEMM out
#define OFF_HF    51200000L      // fp32 [M,256] final node features
#define OFF_XH    76800000L      // bf16 [M,512] hi
#define OFF_XL    102400000L     // bf16 [M,512] lo
#define OFF_YH    128000000L     // bf16 [M,256] hi
#define OFF_YL    140800000L
#define OFF_WH    153600000L     // bf16 weights
#define OFF_WL    153665536L
#define OFF_HID2  153731072L
#define OFF_DIS1  155011072L
#define OFF_DIS2  155111072L
// ---- zero block start ----
#define OFF_P1    155211072L
#define OFF_P2    156491072L
#define OFF_CNT1  157771072L
#define OFF_CNT2  157776072L
#define OFF_ICNT1 157781072L     // int[100000]
#define OFF_ICNT2 157881072L
// ---- zero block end ----
#define OFF_IOFF1 157981072L     // int[100004]
#define OFF_IOFF2 158081076L
#define OFF_ICUR1 158181080L
#define OFF_ICUR2 158281080L
#define OFF_CSR1  158381080L     // int[800000]
#define OFF_CSR2  159181080L
#define SCRATCH_TOTAL 159981080L

__device__ float g_buf[SCRATCH_TOTAL];

// ---------------- helpers ----------------
__device__ __forceinline__ void atomicAddF4(float* p, float4 v) {
    asm volatile("red.global.add.v4.f32 [%0], {%1,%2,%3,%4};"
                 :: "l"(p), "f"(v.x), "f"(v.y), "f"(v.z), "f"(v.w) : "memory");
}

__device__ __forceinline__ void splitbf(float v, bf16& h, bf16& l) {
    h = __float2bfloat16(v);
    l = __float2bfloat16(v - __bfloat162float(h));
}

__device__ __forceinline__ void ldm_x4(uint32_t r[4], const void* p) {
    uint32_t addr = (uint32_t)__cvta_generic_to_shared(p);
    asm volatile("ldmatrix.sync.aligned.m8n8.x4.shared.b16 {%0,%1,%2,%3}, [%4];"
                 : "=r"(r[0]), "=r"(r[1]), "=r"(r[2]), "=r"(r[3]) : "r"(addr));
}

__device__ __forceinline__ void mma16816(float c[4], const uint32_t a[4],
                                         uint32_t b0, uint32_t b1) {
    asm volatile(
        "mma.sync.aligned.m16n8k16.row.col.f32.bf16.bf16.f32 "
        "{%0,%1,%2,%3}, {%4,%5,%6,%7}, {%8,%9}, {%0,%1,%2,%3};"
        : "+f"(c[0]), "+f"(c[1]), "+f"(c[2]), "+f"(c[3])
        : "r"(a[0]), "r"(a[1]), "r"(a[2]), "r"(a[3]), "r"(b0), "r"(b1));
}

__device__ __forceinline__ void cp16(uint32_t s, const void* g, int sz) {
    asm volatile("cp.async.cg.shared.global [%0], [%1], 16, %2;"
                 :: "r"(s), "l"(g), "r"(sz));
}

// ---------------- CSR build kernels ----------------
__global__ void zero_k(float* __restrict__ p, int n) {
    int i = blockIdx.x * blockDim.x + threadIdx.x;
    if (i < n) p[i] = 0.0f;
}

__global__ void cntboth_k(const int* __restrict__ e1, int E1,
                          const int* __restrict__ e2, int E2,
                          int* __restrict__ c1, int* __restrict__ c2) {
    int i = blockIdx.x * blockDim.x + threadIdx.x;
    if (i < E1) atomicAdd(&c1[e1[E1 + i]], 1);
    else if (i < E1 + E2) atomicAdd(&c2[e2[E2 + (i - E1)]], 1);
}

// single-block exclusive scan; also fills cursor copy
__global__ void scan_k(const int* __restrict__ cnt, int* __restrict__ off,
                       int* __restrict__ cur, int n) {
    __shared__ int sh[1024];
    __shared__ int carry;
    int tid = threadIdx.x;
    if (tid == 0) carry = 0;
    __syncthreads();
    for (int base = 0; base < n; base += 1024) {
        int i = base + tid;
        int v = (i < n) ? cnt[i] : 0;
        sh[tid] = v;
        __syncthreads();
        #pragma unroll
        for (int o = 1; o < 1024; o <<= 1) {
            int t = (tid >= o) ? sh[tid - o] : 0;
            __syncthreads();
            sh[tid] += t;
            __syncthreads();
        }
        int excl = sh[tid] - v + carry;
        if (i < n) { off[i] = excl; cur[i] = excl; }
        __syncthreads();
        if (tid == 0) carry += sh[1023];
        __syncthreads();
    }
    if (tid == 0) off[n] = carry;
}

__global__ void disint_k(const int* __restrict__ c1, const int* __restrict__ c2,
                         float* __restrict__ d1, float* __restrict__ d2, int n) {
    int i = blockIdx.x * blockDim.x + threadIdx.x;
    if (i < n) {
        d1[i] = rsqrtf((float)c1[i] + 1.0f);
        d2[i] = rsqrtf((float)c2[i] + 1.0f);
    }
}

__global__ void place_k(const int* __restrict__ ei, int E,
                        int* __restrict__ cur, int* __restrict__ csr) {
    int i = blockIdx.x * blockDim.x + threadIdx.x;
    if (i < E) {
        int dst = ei[E + i];
        int pos = atomicAdd(&cur[dst], 1);
        csr[pos] = ei[i];
    }
}

// ---------------- gather conv: out = split(relu(bias + d^2 h_i + sum coef h_j)) ----
__global__ void gather_k(const int* __restrict__ csr, const int* __restrict__ off,
                         const float* __restrict__ dis,
                         const float* __restrict__ h,      // pre-offset, stride 512
                         const float* __restrict__ bias,
                         bf16* __restrict__ oH, bf16* __restrict__ oL,
                         int ocoff, int Nn) {
    int node = blockIdx.x * 4 + (threadIdx.x >> 6);
    if (node >= Nn) return;
    int c = (threadIdx.x & 63) << 2;
    float di = dis[node];
    float d2 = di * di;
    float4 hv = *(const float4*)(h + (size_t)node * 512 + c);
    float4 bv = *(const float4*)(bias + c);
    float4 acc;
    acc.x = bv.x + d2 * hv.x; acc.y = bv.y + d2 * hv.y;
    acc.z = bv.z + d2 * hv.z; acc.w = bv.w + d2 * hv.w;
    int s = off[node], e = off[node + 1];
    for (int k = s; k < e; k++) {
        int j = csr[k];
        float coef = di * dis[j];
        float4 hj = *(const float4*)(h + (size_t)j * 512 + c);
        acc.x += coef * hj.x; acc.y += coef * hj.y;
        acc.z += coef * hj.z; acc.w += coef * hj.w;
    }
    acc.x = fmaxf(acc.x, 0.f); acc.y = fmaxf(acc.y, 0.f);
    acc.z = fmaxf(acc.z, 0.f); acc.w = fmaxf(acc.w, 0.f);
    bf16 h0,l0,h1,l1,h2,l2,h3,l3;
    splitbf(acc.x,h0,l0); splitbf(acc.y,h1,l1);
    splitbf(acc.z,h2,l2); splitbf(acc.w,h3,l3);
    size_t o = (size_t)node * 512 + ocoff + c;
    __nv_bfloat162 t;
    t.x=h0; t.y=h1; *(__nv_bfloat162*)(oH + o) = t;
    t.x=h2; t.y=h3; *(__nv_bfloat162*)(oH + o + 2) = t;
    t.x=l0; t.y=l1; *(__nv_bfloat162*)(oL + o) = t;
    t.x=l2; t.y=l3; *(__nv_bfloat162*)(oL + o + 2) = t;
}

// ---------------- split kernels ----------------
template<bool RELU>
__global__ void splitA_k(const float* __restrict__ src, int Ks,
                         bf16* __restrict__ dh, bf16* __restrict__ dl,
                         int dstride, int coff, long total4) {
    long gid = blockIdx.x * (long)blockDim.x + threadIdx.x;
    if (gid >= total4) return;
    long e = gid * 4;
    long r = e / Ks;
    int  c = (int)(e - r * Ks);
    float4 v = *(const float4*)(src + e);
    if (RELU) {
        v.x = fmaxf(v.x, 0.f); v.y = fmaxf(v.y, 0.f);
        v.z = fmaxf(v.z, 0.f); v.w = fmaxf(v.w, 0.f);
    }
    bf16 h0,l0,h1,l1,h2,l2,h3,l3;
    splitbf(v.x,h0,l0); splitbf(v.y,h1,l1); splitbf(v.z,h2,l2); splitbf(v.w,h3,l3);
    __nv_bfloat162* ph = (__nv_bfloat162*)(dh + r * (long)dstride + coff + c);
    __nv_bfloat162* pl = (__nv_bfloat162*)(dl + r * (long)dstride + coff + c);
    __nv_bfloat162 t;
    t.x=h0; t.y=h1; ph[0]=t;  t.x=h2; t.y=h3; ph[1]=t;
    t.x=l0; t.y=l1; pl[0]=t;  t.x=l2; t.y=l3; pl[1]=t;
}

__global__ void splitW_k(const float* __restrict__ w, int K, int N,
                         bf16* __restrict__ dh, bf16* __restrict__ dl) {
    int gid = blockIdx.x * blockDim.x + threadIdx.x;
    if (gid >= K * N) return;
    int k = gid / N, n = gid - k * N;
    bf16 h, l;
    splitbf(w[gid], h, l);
    dh[n * K + k] = h;
    dl[n * K + k] = l;
}

__global__ void splitWdual_k(const float* __restrict__ wA, const float* __restrict__ wB,
                             int K, int N,
                             bf16* __restrict__ dh, bf16* __restrict__ dl) {
    int gid = blockIdx.x * blockDim.x + threadIdx.x;
    int tot = K * N;
    if (gid >= 2 * tot) return;
    int which = gid >= tot;
    int g = gid - which * tot;
    int k = g / N, n = g - k * N;
    bf16 h, l;
    splitbf(which ? wB[g] : wA[g], h, l);
    dh[(n + which * N) * K + k] = h;
    dl[(n + which * N) * K + k] = l;
}

// ---------------- pooling / head ----------------
__global__ void count_k(const int* __restrict__ i1, const int* __restrict__ i2,
                        float* __restrict__ c1, float* __restrict__ c2, int Nn) {
    int i = blockIdx.x * blockDim.x + threadIdx.x;
    if (i < Nn) {
        atomicAdd(&c1[i1[i]], 1.0f);
        atomicAdd(&c2[i2[i]], 1.0f);
    }
}

__global__ void pool_k(const float* __restrict__ h,
                       const int* __restrict__ i1, const int* __restrict__ i2,
                       float* __restrict__ p1, float* __restrict__ p2, int Nn) {
    int gid = blockIdx.x * blockDim.x + threadIdx.x;
    int total = Nn * 64;
    if (gid >= total) return;
    int i = gid >> 6;
    int c = (gid & 63) << 2;
    float4 hv = *(const float4*)(h + (size_t)i * DD + c);
    atomicAddF4(p1 + (size_t)i1[i] * DD + c, hv);
    atomicAddF4(p2 + (size_t)i2[i] * DD + c, hv);
}

__global__ void norm_k(float* __restrict__ p1, float* __restrict__ p2,
                       const float* __restrict__ c1, const float* __restrict__ c2, int S) {
    int gid = blockIdx.x * blockDim.x + threadIdx.x;
    int total = S * 64;
    if (gid >= total) return;
    int s = gid >> 6;
    int c = (gid & 63) << 2;
    float s1 = 1.0f / fmaxf(c1[s], 1.0f);
    float s2 = 1.0f / fmaxf(c2[s], 1.0f);
    float4 a = *(float4*)(p1 + (size_t)s * DD + c);
    a.x*=s1; a.y*=s1; a.z*=s1; a.w*=s1;
    *(float4*)(p1 + (size_t)s * DD + c) = a;
    float4 b = *(float4*)(p2 + (size_t)s * DD + c);
    b.x*=s2; b.y*=s2; b.z*=s2; b.w*=s2;
    *(float4*)(p2 + (size_t)s * DD + c) = b;
}

__global__ void final_k(const float* __restrict__ hid, const float* __restrict__ w2,
                        const float* __restrict__ b2, float* __restrict__ out) {
    __shared__ float sh[DD];
    __shared__ float lg[CC];
    int s = blockIdx.x;
    int tid = threadIdx.x;
    sh[tid] = hid[(size_t)s * DD + tid];
    __syncthreads();
    int w = tid >> 5, lane = tid & 31;
    if (w < CC) {
        float sum = 0.0f;
        for (int k = lane; k < DD; k += 32) sum += sh[k] * w2[k * CC + w];
        #pragma unroll
        for (int o = 16; o > 0; o >>= 1) sum += __shfl_xor_sync(0xFFFFFFFFu, sum, o);
        if (lane == 0) lg[w] = sum + b2[w];
    }
    __syncthreads();
    if (tid == 0) {
        float mx = -1e30f;
        #pragma unroll
        for (int c = 0; c < CC; c++) mx = fmaxf(mx, lg[c]);
        float se = 0.0f;
        #pragma unroll
        for (int c = 0; c < CC; c++) se += expf(lg[c] - mx);
        float lse = mx + logf(se);
        #pragma unroll
        for (int c = 0; c < CC; c++) out[(size_t)s * CC + c] = lg[c] - lse;
    }
}

// ---------------- bf16 double-buffered GEMM ----------------
// EPI=0 RAW512:     C[r*512+c] = acc
// EPI=2 SPLIT_RELU: split(relu(acc+bias)) -> oH/oL
// EPI=3 SPLIT:      split(acc+bias)       -> oH/oL
// EPI=4 F32:        C[r*256+c] = acc+bias
// EPI=5 F32_RELU:   C[r*256+c] = relu(acc+bias)
#define LDK2 40
#define STAGE_BYTES 40960

__device__ __forceinline__ void gemm_prefetch(
    char* smbase, int stage, int row, int half,
    const bf16* AH, const bf16* AL, int lda,
    const bf16* BH, const bf16* BL, int ldb,
    int bm, int bn, int M, int k0)
{
    int gra = bm + row;
    int szA = (gra < M) ? 16 : 0;
    if (gra >= M) gra = 0;
    const char* pAH = (const char*)(AH + (size_t)gra * lda + k0) + half * 32;
    const char* pAL = (const char*)(AL + (size_t)gra * lda + k0) + half * 32;
    int grb = bn + row;
    const char* pBH = (const char*)(BH + (size_t)grb * ldb + k0) + half * 32;
    const char* pBL = (const char*)(BL + (size_t)grb * ldb + k0) + half * 32;
    uint32_t so = (uint32_t)__cvta_generic_to_shared(smbase + stage * STAGE_BYTES)
                  + row * (LDK2 * 2) + half * 32;
    cp16(so,              pAH,      szA);  cp16(so + 16,          pAH + 16, szA);
    cp16(so + 10240,      pAL,      szA);  cp16(so + 10240 + 16,  pAL + 16, szA);
    cp16(so + 20480,      pBH,      16);   cp16(so + 20480 + 16,  pBH + 16, 16);
    cp16(so + 30720,      pBL,      16);   cp16(so + 30720 + 16,  pBL + 16, 16);
}

template<int EPI>
__global__ void __launch_bounds__(256)
gemm_bf16(const bf16* __restrict__ AH, const bf16* __restrict__ AL, int lda,
          const bf16* __restrict__ BH, const bf16* __restrict__ BL, int ldb,
          float* __restrict__ C,
          const float* __restrict__ bias,
          bf16* __restrict__ oH, bf16* __restrict__ oL, int ostride, int ocoff,
          int M, int K)
{
    extern __shared__ char sm_[];
    int tid = threadIdx.x, wid = tid >> 5, lane = tid & 31;
    int bm = blockIdx.y * 128, bn = blockIdx.x * 128;
    int wm = (wid & 3) * 32, wn = (wid >> 2) * 64;
    int idx = lane >> 3, lr = lane & 7;
    int row = tid >> 1, half = tid & 1;

    float acc[2][8][4];
    #pragma unroll
    for (int i = 0; i < 2; i++)
        #pragma unroll
        for (int j = 0; j < 8; j++)
            #pragma unroll
            for (int q = 0; q < 4; q++) acc[i][j][q] = 0.0f;

    int KT = K >> 5;
    gemm_prefetch(sm_, 0, row, half, AH, AL, lda, BH, BL, ldb, bm, bn, M, 0);
    asm volatile("cp.async.commit_group;");

    for (int kt = 0; kt < KT; kt++) {
        int s = kt & 1;
        if (kt + 1 < KT) {
            gemm_prefetch(sm_, s ^ 1, row, half, AH, AL, lda, BH, BL, ldb,
                          bm, bn, M, (kt + 1) << 5);
            asm volatile("cp.async.commit_group;");
            asm volatile("cp.async.wait_group 1;");
        } else {
            asm volatile("cp.async.wait_group 0;");
        }
        __syncthreads();

        const bf16* sAh = (const bf16*)(sm_ + s * STAGE_BYTES);
        const bf16* sAl = (const bf16*)(sm_ + s * STAGE_BYTES + 10240);
        const bf16* sBh = (const bf16*)(sm_ + s * STAGE_BYTES + 20480);
        const bf16* sBl = (const bf16*)(sm_ + s * STAGE_BYTES + 30720);

        #pragma unroll
        for (int ks = 0; ks < 2; ks++) {
            int kb = ks * 16;
            uint32_t ah[2][4], al[2][4];
            #pragma unroll
            for (int mf = 0; mf < 2; mf++) {
                int rr = wm + mf * 16 + (idx & 1) * 8 + lr;
                int cc = kb + (idx >> 1) * 8;
                ldm_x4(ah[mf], &sAh[rr * LDK2 + cc]);
                ldm_x4(al[mf], &sAl[rr * LDK2 + cc]);
            }
            uint32_t bh[4][4], bl[4][4];
            #pragma unroll
            for (int bg = 0; bg < 4; bg++) {
                int rr = wn + bg * 16 + (idx >> 1) * 8 + lr;
                int cc = kb + (idx & 1) * 8;
                ldm_x4(bh[bg], &sBh[rr * LDK2 + cc]);
                ldm_x4(bl[bg], &sBl[rr * LDK2 + cc]);
            }
            #pragma unroll
            for (int mf = 0; mf < 2; mf++)
                #pragma unroll
                for (int ng = 0; ng < 8; ng++) {
                    int bg = ng >> 1, pr = (ng & 1) * 2;
                    mma16816(acc[mf][ng], ah[mf], bh[bg][pr], bh[bg][pr + 1]);
                    mma16816(acc[mf][ng], ah[mf], bl[bg][pr], bl[bg][pr + 1]);
                    mma16816(acc[mf][ng], al[mf], bh[bg][pr], bh[bg][pr + 1]);
                }
        }
        __syncthreads();
    }

    // ---- epilogue ----
    int r0 = bm + wm + (lane >> 2);
    int lc0 = wn + (lane & 3) * 2;
    #pragma unroll
    for (int mf = 0; mf < 2; mf++) {
        #pragma unroll
        for (int hf2 = 0; hf2 < 2; hf2++) {
            int r = r0 + mf * 16 + hf2 * 8;
            if (r >= M) continue;
            #pragma unroll
            for (int ng = 0; ng < 8; ng++) {
                int lc = lc0 + ng * 8;
                int c = bn + lc;
                float v0 = acc[mf][ng][hf2 * 2 + 0];
                float v1 = acc[mf][ng][hf2 * 2 + 1];
                if (EPI == 0) {
                    float2 st; st.x = v0; st.y = v1;
                    *(float2*)(C + (size_t)r * 512 + c) = st;
                } else if (EPI == 2 || EPI == 3) {
                    v0 += bias[c]; v1 += bias[c + 1];
                    if (EPI == 2) { v0 = fmaxf(v0, 0.f); v1 = fmaxf(v1, 0.f); }
                    bf16 h0, l0, h1, l1;
                    splitbf(v0, h0, l0); splitbf(v1, h1, l1);
                    __nv_bfloat162 th; th.x = h0; th.y = h1;
                    __nv_bfloat162 tl; tl.x = l0; tl.y = l1;
                    size_t o = (size_t)r * ostride + ocoff + c;
                    *(__nv_bfloat162*)(oH + o) = th;
                    *(__nv_bfloat162*)(oL + o) = tl;
                } else {
                    v0 += bias[c]; v1 += bias[c + 1];
                    if (EPI == 5) { v0 = fmaxf(v0, 0.f); v1 = fmaxf(v1, 0.f); }
                    float2 st; st.x = v0; st.y = v1;
                    *(float2*)(C + (size_t)r * 256 + c) = st;
                }
            }
        }
    }
}

// ---------------- launch ----------------
#define SMEM_GEMM (2 * STAGE_BYTES)

extern "C" void kernel_launch(void* const* d_in, const int* in_sizes, int n_in,
                              void* d_out, int out_size) {
    const float* x    = (const float*)d_in[0];
    const int*   e1   = (const int*)d_in[1];
    const int*   e2   = (const int*)d_in[2];
    const int*   i1   = (const int*)d_in[3];
    const int*   i2   = (const int*)d_in[4];
    const float* w11  = (const float*)d_in[5];
    const float* b11  = (const float*)d_in[6];
    const float* w12  = (const float*)d_in[7];
    const float* b12  = (const float*)d_in[8];
    const float* w21  = (const float*)d_in[9];
    const float* b21  = (const float*)d_in[10];
    const float* w22  = (const float*)d_in[11];
    const float* b22  = (const float*)d_in[12];
    const float* m1w1 = (const float*)d_in[13];
    const float* m1b1 = (const float*)d_in[14];
    const float* m1w2 = (const float*)d_in[15];
    const float* m1b2 = (const float*)d_in[16];
    const float* m2w1 = (const float*)d_in[17];
    const float* m2b1 = (const float*)d_in[18];
    const float* m2w2 = (const float*)d_in[19];
    const float* m2b2 = (const float*)d_in[20];
    const float* mw1  = (const float*)d_in[21];
    const float* mb1  = (const float*)d_in[22];
    const float* mw2  = (const float*)d_in[23];
    const float* mb2  = (const float*)d_in[24];
    float* out = (float*)d_out;

    int Nn = in_sizes[0] / FIN;
    int E1 = in_sizes[1] / 2;
    int E2 = in_sizes[2] / 2;
    int S  = out_size / CC;

    float* base = nullptr;
    cudaGetSymbolAddress((void**)&base, g_buf);
    float* h    = base + OFF_H;
    float* hf   = base + OFF_HF;
    float* hid2 = base + OFF_HID2;
    float* dis1 = base + OFF_DIS1;
    float* dis2 = base + OFF_DIS2;
    float* p1   = base + OFF_P1;
    float* p2   = base + OFF_P2;
    float* c1   = base + OFF_CNT1;
    float* c2   = base + OFF_CNT2;
    int* icnt1  = (int*)(base + OFF_ICNT1);
    int* icnt2  = (int*)(base + OFF_ICNT2);
    int* ioff1  = (int*)(base + OFF_IOFF1);
    int* ioff2  = (int*)(base + OFF_IOFF2);
    int* icur1  = (int*)(base + OFF_ICUR1);
    int* icur2  = (int*)(base + OFF_ICUR2);
    int* csr1   = (int*)(base + OFF_CSR1);
    int* csr2   = (int*)(base + OFF_CSR2);
    bf16* XH = (bf16*)(base + OFF_XH);
    bf16* XL = (bf16*)(base + OFF_XL);
    bf16* YH = (bf16*)(base + OFF_YH);
    bf16* YL = (bf16*)(base + OFF_YL);
    bf16* WH = (bf16*)(base + OFF_WH);
    bf16* WL = (bf16*)(base + OFF_WL);

    cudaFuncSetAttribute(gemm_bf16<0>, cudaFuncAttributeMaxDynamicSharedMemorySize, SMEM_GEMM);
    cudaFuncSetAttribute(gemm_bf16<2>, cudaFuncAttributeMaxDynamicSharedMemorySize, SMEM_GEMM);
    cudaFuncSetAttribute(gemm_bf16<3>, cudaFuncAttributeMaxDynamicSharedMemorySize, SMEM_GEMM);
    cudaFuncSetAttribute(gemm_bf16<4>, cudaFuncAttributeMaxDynamicSharedMemorySize, SMEM_GEMM);
    cudaFuncSetAttribute(gemm_bf16<5>, cudaFuncAttributeMaxDynamicSharedMemorySize, SMEM_GEMM);

    const int T = 256;
    unsigned gy  = (unsigned)((Nn + 127) / 128);
    unsigned gys = (unsigned)((S + 127) / 128);
    dim3 g512(4, gy), g256(2, gy), gh(2, gys);
    int gN64 = (Nn * 64 + T - 1) / T;
    unsigned gGat = (unsigned)((Nn + 3) / 4);
    long t4;
    #define SPLITA(RELU, SRC, KS, DH, DL, STRIDE, COFF, M_) \
        t4 = (long)(M_) * (KS) / 4; \
        splitA_k<RELU><<<(unsigned)((t4 + T - 1) / T), T>>>(SRC, KS, DH, DL, STRIDE, COFF, t4)

    int nz = (int)(OFF_IOFF1 - OFF_P1);

    // ---- prologue: zero + CSR build ----
    zero_k<<<(nz + T - 1) / T, T>>>(p1, nz);
    cntboth_k<<<(E1 + E2 + T - 1) / T, T>>>(e1, E1, e2, E2, icnt1, icnt2);
    scan_k<<<1, 1024>>>(icnt1, ioff1, icur1, Nn);
    scan_k<<<1, 1024>>>(icnt2, ioff2, icur2, Nn);
    disint_k<<<(Nn + T - 1) / T, T>>>(icnt1, icnt2, dis1, dis2, Nn);
    place_k<<<(E1 + T - 1) / T, T>>>(e1, E1, icur1, csr1);
    place_k<<<(E2 + T - 1) / T, T>>>(e2, E2, icur2, csr2);

    // ---- input split ----
    SPLITA(false, x, FIN, XH, XL, 512, 0, Nn);
    splitWdual_k<<<(2 * FIN * DD + T - 1) / T, T>>>(w11, w12, FIN, DD, WH, WL);

    // ---- layer 1: dual conv GEMM (raw) + gathers (fused bias/self/relu/split) ----
    gemm_bf16<0><<<g512, 256, SMEM_GEMM>>>(XH, XL, 512, WH, WL, FIN,
        h, nullptr, nullptr, nullptr, 0, 0, Nn, FIN);
    gather_k<<<gGat, T>>>(csr1, ioff1, dis1, h,       b11, XH, XL, 0,   Nn);
    gather_k<<<gGat, T>>>(csr2, ioff2, dis2, h + 256, b12, XH, XL, 256, Nn);
    // ---- mlp_1 ----
    splitW_k<<<(2 * DD * DD + T - 1) / T, T>>>(m1w1, 2 * DD, DD, WH, WL);
    gemm_bf16<2><<<g256, 256, SMEM_GEMM>>>(XH, XL, 512, WH, WL, 512,
        nullptr, m1b1, YH, YL, 256, 0, Nn, 512);
    splitW_k<<<(DD * DD + T - 1) / T, T>>>(m1w2, DD, DD, WH, WL);
    gemm_bf16<3><<<g256, 256, SMEM_GEMM>>>(YH, YL, 256, WH, WL, 256,
        nullptr, m1b2, XH, XL, 512, 0, Nn, 256);

    // ---- layer 2: dual conv GEMM (A = h1 split, X cols 0-255) ----
    splitWdual_k<<<(2 * DD * DD + T - 1) / T, T>>>(w21, w22, DD, DD, WH, WL);
    gemm_bf16<0><<<g512, 256, SMEM_GEMM>>>(XH, XL, 512, WH, WL, DD,
        h, nullptr, nullptr, nullptr, 0, 0, Nn, DD);
    gather_k<<<gGat, T>>>(csr1, ioff1, dis1, h,       b21, XH, XL, 0,   Nn);
    gather_k<<<gGat, T>>>(csr2, ioff2, dis2, h + 256, b22, XH, XL, 256, Nn);
    // ---- mlp_2 ----
    splitW_k<<<(2 * DD * DD + T - 1) / T, T>>>(m2w1, 2 * DD, DD, WH, WL);
    gemm_bf16<2><<<g256, 256, SMEM_GEMM>>>(XH, XL, 512, WH, WL, 512,
        nullptr, m2b1, YH, YL, 256, 0, Nn, 512);
    splitW_k<<<(DD * DD + T - 1) / T, T>>>(m2w2, DD, DD, WH, WL);
    gemm_bf16<4><<<g256, 256, SMEM_GEMM>>>(YH, YL, 256, WH, WL, 256,
        hf, m2b2, nullptr, nullptr, 0, 0, Nn, 256);

    // ---- pooling ----
    count_k<<<(Nn + T - 1) / T, T>>>(i1, i2, c1, c2, Nn);
    pool_k<<<gN64, T>>>(hf, i1, i2, p1, p2, Nn);
    norm_k<<<(S * 64 + T - 1) / T, T>>>(p1, p2, c1, c2, S);

    // ---- head ----
    SPLITA(false, p1, DD, XH, XL, 512, 0,  S);
    SPLITA(false, p2, DD, XH, XL, 512, DD, S);
    splitW_k<<<(2 * DD * DD + T - 1) / T, T>>>(mw1, 2 * DD, DD, WH, WL);
    gemm_bf16<5><<<gh, 256, SMEM_GEMM>>>(XH, XL, 512, WH, WL, 512,
        hid2, mb1, nullptr, nullptr, 0, 0, S, 512);
    final_k<<<S, DD>>>(hid2, mw2, mb2, out);
}

// round 9
// speedup vs baseline: 2.5478x; 1.1491x over previous
#include <cuda_runtime.h>
#include <cuda_bf16.h>
#include <math.h>
#include <stdint.h>
#include <cstdint>

// ---------------- Problem constants ----------------
#define DD 256
#define FIN 128
#define CC 7

typedef __nv_bfloat16 bf16;

// ---------------- Scratch layout (float offsets) ----------------
#define OFF_H     0L             // fp32 [M,512] conv GEMM out
#define OFF_HF    51200000L      // fp32 [M,256] final node features
#define OFF_XH    76800000L      // bf16 [M,512] hi
#define OFF_XL    102400000L     // bf16 [M,512] lo
#define OFF_YH    128000000L     // bf16 [M,256] hi
#define OFF_YL    140800000L
#define OFF_WH    153600000L     // bf16 weights
#define OFF_WL    153665536L
#define OFF_HID2  153731072L
#define OFF_DIS1  155011072L
#define OFF_DIS2  155111072L
// ---- zero block start ----
#define OFF_P1    155211072L
#define OFF_P2    156491072L
#define OFF_CNT1  157771072L
#define OFF_CNT2  157776072L
#define OFF_ICNT1 157781072L     // int[100000]
#define OFF_ICNT2 157881072L
#define OFF_BSUM1 157981072L     // int[128]
#define OFF_BSUM2 157981200L
// ---- zero block end ----
#define OFF_IOFF1 157981328L     // int[100004]
#define OFF_IOFF2 158081332L
#define OFF_ICUR1 158181336L
#define OFF_ICUR2 158281336L
#define OFF_CSR1  158381336L     // int[800000]
#define OFF_CSR2  159181336L
#define SCRATCH_TOTAL 159981336L

__device__ float g_buf[SCRATCH_TOTAL];

// ---------------- helpers ----------------
__device__ __forceinline__ void atomicAddF4(float* p, float4 v) {
    asm volatile("red.global.add.v4.f32 [%0], {%1,%2,%3,%4};"
                 :: "l"(p), "f"(v.x), "f"(v.y), "f"(v.z), "f"(v.w) : "memory");
}

__device__ __forceinline__ void splitbf(float v, bf16& h, bf16& l) {
    h = __float2bfloat16(v);
    l = __float2bfloat16(v - __bfloat162float(h));
}

__device__ __forceinline__ void ldm_x4(uint32_t r[4], const void* p) {
    uint32_t addr = (uint32_t)__cvta_generic_to_shared(p);
    asm volatile("ldmatrix.sync.aligned.m8n8.x4.shared.b16 {%0,%1,%2,%3}, [%4];"
                 : "=r"(r[0]), "=r"(r[1]), "=r"(r[2]), "=r"(r[3]) : "r"(addr));
}

__device__ __forceinline__ void mma16816(float c[4], const uint32_t a[4],
                                         uint32_t b0, uint32_t b1) {
    asm volatile(
        "mma.sync.aligned.m16n8k16.row.col.f32.bf16.bf16.f32 "
        "{%0,%1,%2,%3}, {%4,%5,%6,%7}, {%8,%9}, {%0,%1,%2,%3};"
        : "+f"(c[0]), "+f"(c[1]), "+f"(c[2]), "+f"(c[3])
        : "r"(a[0]), "r"(a[1]), "r"(a[2]), "r"(a[3]), "r"(b0), "r"(b1));
}

__device__ __forceinline__ void cp16(uint32_t s, const void* g, int sz) {
    asm volatile("cp.async.cg.shared.global [%0], [%1], 16, %2;"
                 :: "r"(s), "l"(g), "r"(sz));
}

// ---------------- CSR build kernels ----------------
#define SCAN_B 1024

__global__ void zero_k(float* __restrict__ p, int n) {
    int i = blockIdx.x * blockDim.x + threadIdx.x;
    if (i < n) p[i] = 0.0f;
}

__global__ void cntboth_k(const int* __restrict__ e1, int E1,
                          const int* __restrict__ e2, int E2,
                          int* __restrict__ c1, int* __restrict__ c2) {
    int i = blockIdx.x * blockDim.x + threadIdx.x;
    if (i < E1) atomicAdd(&c1[e1[E1 + i]], 1);
    else if (i < E1 + E2) atomicAdd(&c2[e2[E2 + (i - E1)]], 1);
}

// phase 1: per-chunk sums (int atomics -> deterministic)
__global__ void blocksum_k(const int* __restrict__ cnt, int* __restrict__ bsum, int n) {
    int i = blockIdx.x * SCAN_B + threadIdx.x;
    int v = (i < n) ? cnt[i] : 0;
    #pragma unroll
    for (int o = 16; o > 0; o >>= 1) v += __shfl_xor_sync(0xFFFFFFFFu, v, o);
    if ((threadIdx.x & 31) == 0) atomicAdd(&bsum[blockIdx.x], v);
}

// phase 2: serial exclusive scan of <=128 block sums, write total to off[n]
__global__ void scanbsum_k(int* __restrict__ bsum, int nb, int* __restrict__ off_n) {
    if (threadIdx.x == 0) {
        int acc = 0;
        for (int i = 0; i < nb; i++) { int v = bsum[i]; bsum[i] = acc; acc += v; }
        *off_n = acc;
    }
}

// phase 3: block-local exclusive scan + block offset
__global__ void scanblock_k(const int* __restrict__ cnt, const int* __restrict__ bsum,
                            int* __restrict__ off, int* __restrict__ cur, int n) {
    __shared__ int sw[32];
    int tid = threadIdx.x, lane = tid & 31, wid = tid >> 5;
    int i = blockIdx.x * SCAN_B + tid;
    int v = (i < n) ? cnt[i] : 0;
    int inc = v;
    #pragma unroll
    for (int o = 1; o < 32; o <<= 1) {
        int t = __shfl_up_sync(0xFFFFFFFFu, inc, o);
        if (lane >= o) inc += t;
    }
    if (lane == 31) sw[wid] = inc;
    __syncthreads();
    if (wid == 0) {
        int t = sw[lane];
        int ti = t;
        #pragma unroll
        for (int o = 1; o < 32; o <<= 1) {
            int u = __shfl_up_sync(0xFFFFFFFFu, ti, o);
            if (lane >= o) ti += u;
        }
        sw[lane] = ti - t;
    }
    __syncthreads();
    int excl = inc - v + sw[wid] + bsum[blockIdx.x];
    if (i < n) { off[i] = excl; cur[i] = excl; }
}

__global__ void disint_k(const int* __restrict__ c1, const int* __restrict__ c2,
                         float* __restrict__ d1, float* __restrict__ d2, int n) {
    int i = blockIdx.x * blockDim.x + threadIdx.x;
    if (i < n) {
        d1[i] = rsqrtf((float)c1[i] + 1.0f);
        d2[i] = rsqrtf((float)c2[i] + 1.0f);
    }
}

__global__ void place_k(const int* __restrict__ ei, int E,
                        int* __restrict__ cur, int* __restrict__ csr) {
    int i = blockIdx.x * blockDim.x + threadIdx.x;
    if (i < E) {
        int dst = ei[E + i];
        int pos = atomicAdd(&cur[dst], 1);
        csr[pos] = ei[i];
    }
}

// ---------------- gather conv: out = split(relu(bias + d^2 h_i + sum coef h_j)) ----
__global__ void gather_k(const int* __restrict__ csr, const int* __restrict__ off,
                         const float* __restrict__ dis,
                         const float* __restrict__ h,      // pre-offset, stride 512
                         const float* __restrict__ bias,
                         bf16* __restrict__ oH, bf16* __restrict__ oL,
                         int ocoff, int Nn) {
    int node = blockIdx.x * 4 + (threadIdx.x >> 6);
    if (node >= Nn) return;
    int c = (threadIdx.x & 63) << 2;
    float di = dis[node];
    float d2 = di * di;
    float4 hv = *(const float4*)(h + (size_t)node * 512 + c);
    float4 bv = *(const float4*)(bias + c);
    float4 acc;
    acc.x = bv.x + d2 * hv.x; acc.y = bv.y + d2 * hv.y;
    acc.z = bv.z + d2 * hv.z; acc.w = bv.w + d2 * hv.w;
    int s = off[node], e = off[node + 1];
    for (int k = s; k < e; k++) {
        int j = csr[k];
        float coef = di * dis[j];
        float4 hj = *(const float4*)(h + (size_t)j * 512 + c);
        acc.x += coef * hj.x; acc.y += coef * hj.y;
        acc.z += coef * hj.z; acc.w += coef * hj.w;
    }
    acc.x = fmaxf(acc.x, 0.f); acc.y = fmaxf(acc.y, 0.f);
    acc.z = fmaxf(acc.z, 0.f); acc.w = fmaxf(acc.w, 0.f);
    bf16 h0,l0,h1,l1,h2,l2,h3,l3;
    splitbf(acc.x,h0,l0); splitbf(acc.y,h1,l1);
    splitbf(acc.z,h2,l2); splitbf(acc.w,h3,l3);
    size_t o = (size_t)node * 512 + ocoff + c;
    __nv_bfloat162 t;
    t.x=h0; t.y=h1; *(__nv_bfloat162*)(oH + o) = t;
    t.x=h2; t.y=h3; *(__nv_bfloat162*)(oH + o + 2) = t;
    t.x=l0; t.y=l1; *(__nv_bfloat162*)(oL + o) = t;
    t.x=l2; t.y=l3; *(__nv_bfloat162*)(oL + o + 2) = t;
}

// ---------------- split kernels ----------------
template<bool RELU>
__global__ void splitA_k(const float* __restrict__ src, int Ks,
                         bf16* __restrict__ dh, bf16* __restrict__ dl,
                         int dstride, int coff, long total4) {
    long gid = blockIdx.x * (long)blockDim.x + threadIdx.x;
    if (gid >= total4) return;
    long e = gid * 4;
    long r = e / Ks;
    int  c = (int)(e - r * Ks);
    float4 v = *(const float4*)(src + e);
    if (RELU) {
        v.x = fmaxf(v.x, 0.f); v.y = fmaxf(v.y, 0.f);
        v.z = fmaxf(v.z, 0.f); v.w = fmaxf(v.w, 0.f);
    }
    bf16 h0,l0,h1,l1,h2,l2,h3,l3;
    splitbf(v.x,h0,l0); splitbf(v.y,h1,l1); splitbf(v.z,h2,l2); splitbf(v.w,h3,l3);
    __nv_bfloat162* ph = (__nv_bfloat162*)(dh + r * (long)dstride + coff + c);
    __nv_bfloat162* pl = (__nv_bfloat162*)(dl + r * (long)dstride + coff + c);
    __nv_bfloat162 t;
    t.x=h0; t.y=h1; ph[0]=t;  t.x=h2; t.y=h3; ph[1]=t;
    t.x=l0; t.y=l1; pl[0]=t;  t.x=l2; t.y=l3; pl[1]=t;
}

__global__ void splitW_k(const float* __restrict__ w, int K, int N,
                         bf16* __restrict__ dh, bf16* __restrict__ dl) {
    int gid = blockIdx.x * blockDim.x + threadIdx.x;
    if (gid >= K * N) return;
    int k = gid / N, n = gid - k * N;
    bf16 h, l;
    splitbf(w[gid], h, l);
    dh[n * K + k] = h;
    dl[n * K + k] = l;
}

__global__ void splitWdual_k(const float* __restrict__ wA, const float* __restrict__ wB,
                             int K, int N,
                             bf16* __restrict__ dh, bf16* __restrict__ dl) {
    int gid = blockIdx.x * blockDim.x + threadIdx.x;
    int tot = K * N;
    if (gid >= 2 * tot) return;
    int which = gid >= tot;
    int g = gid - which * tot;
    int k = g / N, n = g - k * N;
    bf16 h, l;
    splitbf(which ? wB[g] : wA[g], h, l);
    dh[(n + which * N) * K + k] = h;
    dl[(n + which * N) * K + k] = l;
}

// ---------------- pooling / head ----------------
__global__ void count_k(const int* __restrict__ i1, const int* __restrict__ i2,
                        float* __restrict__ c1, float* __restrict__ c2, int Nn) {
    int i = blockIdx.x * blockDim.x + threadIdx.x;
    if (i < Nn) {
        atomicAdd(&c1[i1[i]], 1.0f);
        atomicAdd(&c2[i2[i]], 1.0f);
    }
}

__global__ void pool_k(const float* __restrict__ h,
                       const int* __restrict__ i1, const int* __restrict__ i2,
                       float* __restrict__ p1, float* __restrict__ p2, int Nn) {
    int gid = blockIdx.x * blockDim.x + threadIdx.x;
    int total = Nn * 64;
    if (gid >= total) return;
    int i = gid >> 6;
    int c = (gid & 63) << 2;
    float4 hv = *(const float4*)(h + (size_t)i * DD + c);
    atomicAddF4(p1 + (size_t)i1[i] * DD + c, hv);
    atomicAddF4(p2 + (size_t)i2[i] * DD + c, hv);
}

__global__ void norm_k(float* __restrict__ p1, float* __restrict__ p2,
                       const float* __restrict__ c1, const float* __restrict__ c2, int S) {
    int gid = blockIdx.x * blockDim.x + threadIdx.x;
    int total = S * 64;
    if (gid >= total) return;
    int s = gid >> 6;
    int c = (gid & 63) << 2;
    float s1 = 1.0f / fmaxf(c1[s], 1.0f);
    float s2 = 1.0f / fmaxf(c2[s], 1.0f);
    float4 a = *(float4*)(p1 + (size_t)s * DD + c);
    a.x*=s1; a.y*=s1; a.z*=s1; a.w*=s1;
    *(float4*)(p1 + (size_t)s * DD + c) = a;
    float4 b = *(float4*)(p2 + (size_t)s * DD + c);
    b.x*=s2; b.y*=s2; b.z*=s2; b.w*=s2;
    *(float4*)(p2 + (size_t)s * DD + c) = b;
}

__global__ void final_k(const float* __restrict__ hid, const float* __restrict__ w2,
                        const float* __restrict__ b2, float* __restrict__ out) {
    __shared__ float sh[DD];
    __shared__ float lg[CC];
    int s = blockIdx.x;
    int tid = threadIdx.x;
    sh[tid] = hid[(size_t)s * DD + tid];
    __syncthreads();
    int w = tid >> 5, lane = tid & 31;
    if (w < CC) {
        float sum = 0.0f;
        for (int k = lane; k < DD; k += 32) sum += sh[k] * w2[k * CC + w];
        #pragma unroll
        for (int o = 16; o > 0; o >>= 1) sum += __shfl_xor_sync(0xFFFFFFFFu, sum, o);
        if (lane == 0) lg[w] = sum + b2[w];
    }
    __syncthreads();
    if (tid == 0) {
        float mx = -1e30f;
        #pragma unroll
        for (int c = 0; c < CC; c++) mx = fmaxf(mx, lg[c]);
        float se = 0.0f;
        #pragma unroll
        for (int c = 0; c < CC; c++) se += expf(lg[c] - mx);
        float lse = mx + logf(se);
        #pragma unroll
        for (int c = 0; c < CC; c++) out[(size_t)s * CC + c] = lg[c] - lse;
    }
}

// ---------------- bf16 double-buffered GEMM ----------------
// EPI=0 RAW512:     C[r*512+c] = acc
// EPI=2 SPLIT_RELU: split(relu(acc+bias)) -> oH/oL
// EPI=3 SPLIT:      split(acc+bias)       -> oH/oL
// EPI=4 F32:        C[r*256+c] = acc+bias
// EPI=5 F32_RELU:   C[r*256+c] = relu(acc+bias)
#define LDK2 40
#define STAGE_BYTES 40960

__device__ __forceinline__ void gemm_prefetch(
    char* smbase, int stage, int row, int half,
    const bf16* AH, const bf16* AL, int lda,
    const bf16* BH, const bf16* BL, int ldb,
    int bm, int bn, int M, int k0)
{
    int gra = bm + row;
    int szA = (gra < M) ? 16 : 0;
    if (gra >= M) gra = 0;
    const char* pAH = (const char*)(AH + (size_t)gra * lda + k0) + half * 32;
    const char* pAL = (const char*)(AL + (size_t)gra * lda + k0) + half * 32;
    int grb = bn + row;
    const char* pBH = (const char*)(BH + (size_t)grb * ldb + k0) + half * 32;
    const char* pBL = (const char*)(BL + (size_t)grb * ldb + k0) + half * 32;
    uint32_t so = (uint32_t)__cvta_generic_to_shared(smbase + stage * STAGE_BYTES)
                  + row * (LDK2 * 2) + half * 32;
    cp16(so,              pAH,      szA);  cp16(so + 16,          pAH + 16, szA);
    cp16(so + 10240,      pAL,      szA);  cp16(so + 10240 + 16,  pAL + 16, szA);
    cp16(so + 20480,      pBH,      16);   cp16(so + 20480 + 16,  pBH + 16, 16);
    cp16(so + 30720,      pBL,      16);   cp16(so + 30720 + 16,  pBL + 16, 16);
}

template<int EPI>
__global__ void __launch_bounds__(256)
gemm_bf16(const bf16* __restrict__ AH, const bf16* __restrict__ AL, int lda,
          const bf16* __restrict__ BH, const bf16* __restrict__ BL, int ldb,
          float* __restrict__ C,
          const float* __restrict__ bias,
          bf16* __restrict__ oH, bf16* __restrict__ oL, int ostride, int ocoff,
          int M, int K)
{
    extern __shared__ char sm_[];
    int tid = threadIdx.x, wid = tid >> 5, lane = tid & 31;
    int bm = blockIdx.y * 128, bn = blockIdx.x * 128;
    int wm = (wid & 3) * 32, wn = (wid >> 2) * 64;
    int idx = lane >> 3, lr = lane & 7;
    int row = tid >> 1, half = tid & 1;

    float acc[2][8][4];
    #pragma unroll
    for (int i = 0; i < 2; i++)
        #pragma unroll
        for (int j = 0; j < 8; j++)
            #pragma unroll
            for (int q = 0; q < 4; q++) acc[i][j][q] = 0.0f;

    int KT = K >> 5;
    gemm_prefetch(sm_, 0, row, half, AH, AL, lda, BH, BL, ldb, bm, bn, M, 0);
    asm volatile("cp.async.commit_group;");

    for (int kt = 0; kt < KT; kt++) {
        int s = kt & 1;
        if (kt + 1 < KT) {
            gemm_prefetch(sm_, s ^ 1, row, half, AH, AL, lda, BH, BL, ldb,
                          bm, bn, M, (kt + 1) << 5);
            asm volatile("cp.async.commit_group;");
            asm volatile("cp.async.wait_group 1;");
        } else {
            asm volatile("cp.async.wait_group 0;");
        }
        __syncthreads();

        const bf16* sAh = (const bf16*)(sm_ + s * STAGE_BYTES);
        const bf16* sAl = (const bf16*)(sm_ + s * STAGE_BYTES + 10240);
        const bf16* sBh = (const bf16*)(sm_ + s * STAGE_BYTES + 20480);
        const bf16* sBl = (const bf16*)(sm_ + s * STAGE_BYTES + 30720);

        #pragma unroll
        for (int ks = 0; ks < 2; ks++) {
            int kb = ks * 16;
            uint32_t ah[2][4], al[2][4];
            #pragma unroll
            for (int mf = 0; mf < 2; mf++) {
                int rr = wm + mf * 16 + (idx & 1) * 8 + lr;
                int cc = kb + (idx >> 1) * 8;
                ldm_x4(ah[mf], &sAh[rr * LDK2 + cc]);
                ldm_x4(al[mf], &sAl[rr * LDK2 + cc]);
            }
            uint32_t bh[4][4], bl[4][4];
            #pragma unroll
            for (int bg = 0; bg < 4; bg++) {
                int rr = wn + bg * 16 + (idx >> 1) * 8 + lr;
                int cc = kb + (idx & 1) * 8;
                ldm_x4(bh[bg], &sBh[rr * LDK2 + cc]);
                ldm_x4(bl[bg], &sBl[rr * LDK2 + cc]);
            }
            #pragma unroll
            for (int mf = 0; mf < 2; mf++)
                #pragma unroll
                for (int ng = 0; ng < 8; ng++) {
                    int bg = ng >> 1, pr = (ng & 1) * 2;
                    mma16816(acc[mf][ng], ah[mf], bh[bg][pr], bh[bg][pr + 1]);
                    mma16816(acc[mf][ng], ah[mf], bl[bg][pr], bl[bg][pr + 1]);
                    mma16816(acc[mf][ng], al[mf], bh[bg][pr], bh[bg][pr + 1]);
                }
        }
        __syncthreads();
    }

    // ---- epilogue ----
    int r0 = bm + wm + (lane >> 2);
    int lc0 = wn + (lane & 3) * 2;
    #pragma unroll
    for (int mf = 0; mf < 2; mf++) {
        #pragma unroll
        for (int hf2 = 0; hf2 < 2; hf2++) {
            int r = r0 + mf * 16 + hf2 * 8;
            if (r >= M) continue;
            #pragma unroll
            for (int ng = 0; ng < 8; ng++) {
                int lc = lc0 + ng * 8;
                int c = bn + lc;
                float v0 = acc[mf][ng][hf2 * 2 + 0];
                float v1 = acc[mf][ng][hf2 * 2 + 1];
                if (EPI == 0) {
                    float2 st; st.x = v0; st.y = v1;
                    *(float2*)(C + (size_t)r * 512 + c) = st;
                } else if (EPI == 2 || EPI == 3) {
                    v0 += bias[c]; v1 += bias[c + 1];
                    if (EPI == 2) { v0 = fmaxf(v0, 0.f); v1 = fmaxf(v1, 0.f); }
                    bf16 h0, l0, h1, l1;
                    splitbf(v0, h0, l0); splitbf(v1, h1, l1);
                    __nv_bfloat162 th; th.x = h0; th.y = h1;
                    __nv_bfloat162 tl; tl.x = l0; tl.y = l1;
                    size_t o = (size_t)r * ostride + ocoff + c;
                    *(__nv_bfloat162*)(oH + o) = th;
                    *(__nv_bfloat162*)(oL + o) = tl;
                } else {
                    v0 += bias[c]; v1 += bias[c + 1];
                    if (EPI == 5) { v0 = fmaxf(v0, 0.f); v1 = fmaxf(v1, 0.f); }
                    float2 st; st.x = v0; st.y = v1;
                    *(float2*)(C + (size_t)r * 256 + c) = st;
                }
            }
        }
    }
}

// ---------------- launch ----------------
#define SMEM_GEMM (2 * STAGE_BYTES)

extern "C" void kernel_launch(void* const* d_in, const int* in_sizes, int n_in,
                              void* d_out, int out_size) {
    const float* x    = (const float*)d_in[0];
    const int*   e1   = (const int*)d_in[1];
    const int*   e2   = (const int*)d_in[2];
    const int*   i1   = (const int*)d_in[3];
    const int*   i2   = (const int*)d_in[4];
    const float* w11  = (const float*)d_in[5];
    const float* b11  = (const float*)d_in[6];
    const float* w12  = (const float*)d_in[7];
    const float* b12  = (const float*)d_in[8];
    const float* w21  = (const float*)d_in[9];
    const float* b21  = (const float*)d_in[10];
    const float* w22  = (const float*)d_in[11];
    const float* b22  = (const float*)d_in[12];
    const float* m1w1 = (const float*)d_in[13];
    const float* m1b1 = (const float*)d_in[14];
    const float* m1w2 = (const float*)d_in[15];
    const float* m1b2 = (const float*)d_in[16];
    const float* m2w1 = (const float*)d_in[17];
    const float* m2b1 = (const float*)d_in[18];
    const float* m2w2 = (const float*)d_in[19];
    const float* m2b2 = (const float*)d_in[20];
    const float* mw1  = (const float*)d_in[21];
    const float* mb1  = (const float*)d_in[22];
    const float* mw2  = (const float*)d_in[23];
    const float* mb2  = (const float*)d_in[24];
    float* out = (float*)d_out;

    int Nn = in_sizes[0] / FIN;
    int E1 = in_sizes[1] / 2;
    int E2 = in_sizes[2] / 2;
    int S  = out_size / CC;

    float* base = nullptr;
    cudaGetSymbolAddress((void**)&base, g_buf);
    float* h    = base + OFF_H;
    float* hf   = base + OFF_HF;
    float* hid2 = base + OFF_HID2;
    float* dis1 = base + OFF_DIS1;
    float* dis2 = base + OFF_DIS2;
    float* p1   = base + OFF_P1;
    float* p2   = base + OFF_P2;
    float* c1   = base + OFF_CNT1;
    float* c2   = base + OFF_CNT2;
    int* icnt1  = (int*)(base + OFF_ICNT1);
    int* icnt2  = (int*)(base + OFF_ICNT2);
    int* bsum1  = (int*)(base + OFF_BSUM1);
    int* bsum2  = (int*)(base + OFF_BSUM2);
    int* ioff1  = (int*)(base + OFF_IOFF1);
    int* ioff2  = (int*)(base + OFF_IOFF2);
    int* icur1  = (int*)(base + OFF_ICUR1);
    int* icur2  = (int*)(base + OFF_ICUR2);
    int* csr1   = (int*)(base + OFF_CSR1);
    int* csr2   = (int*)(base + OFF_CSR2);
    bf16* XH = (bf16*)(base + OFF_XH);
    bf16* XL = (bf16*)(base + OFF_XL);
    bf16* YH = (bf16*)(base + OFF_YH);
    bf16* YL = (bf16*)(base + OFF_YL);
    bf16* WH = (bf16*)(base + OFF_WH);
    bf16* WL = (bf16*)(base + OFF_WL);

    cudaFuncSetAttribute(gemm_bf16<0>, cudaFuncAttributeMaxDynamicSharedMemorySize, SMEM_GEMM);
    cudaFuncSetAttribute(gemm_bf16<2>, cudaFuncAttributeMaxDynamicSharedMemorySize, SMEM_GEMM);
    cudaFuncSetAttribute(gemm_bf16<3>, cudaFuncAttributeMaxDynamicSharedMemorySize, SMEM_GEMM);
    cudaFuncSetAttribute(gemm_bf16<4>, cudaFuncAttributeMaxDynamicSharedMemorySize, SMEM_GEMM);
    cudaFuncSetAttribute(gemm_bf16<5>, cudaFuncAttributeMaxDynamicSharedMemorySize, SMEM_GEMM);

    const int T = 256;
    unsigned gy  = (unsigned)((Nn + 127) / 128);
    unsigned gys = (unsigned)((S + 127) / 128);
    dim3 g512(4, gy), g256(2, gy), gh(2, gys);
    int gN64 = (Nn * 64 + T - 1) / T;
    unsigned gGat = (unsigned)((Nn + 3) / 4);
    int nb = (Nn + SCAN_B - 1) / SCAN_B;
    long t4;
    #define SPLITA(RELU, SRC, KS, DH, DL, STRIDE, COFF, M_) \
        t4 = (long)(M_) * (KS) / 4; \
        splitA_k<RELU><<<(unsigned)((t4 + T - 1) / T), T>>>(SRC, KS, DH, DL, STRIDE, COFF, t4)

    int nz = (int)(OFF_IOFF1 - OFF_P1);

    // ---- prologue: zero + CSR build (parallel scan) ----
    zero_k<<<(nz + T - 1) / T, T>>>(p1, nz);
    cntboth_k<<<(E1 + E2 + T - 1) / T, T>>>(e1, E1, e2, E2, icnt1, icnt2);
    blocksum_k<<<nb, SCAN_B>>>(icnt1, bsum1, Nn);
    blocksum_k<<<nb, SCAN_B>>>(icnt2, bsum2, Nn);
    scanbsum_k<<<1, 32>>>(bsum1, nb, ioff1 + Nn);
    scanbsum_k<<<1, 32>>>(bsum2, nb, ioff2 + Nn);
    scanblock_k<<<nb, SCAN_B>>>(icnt1, bsum1, ioff1, icur1, Nn);
    scanblock_k<<<nb, SCAN_B>>>(icnt2, bsum2, ioff2, icur2, Nn);
    disint_k<<<(Nn + T - 1) / T, T>>>(icnt1, icnt2, dis1, dis2, Nn);
    place_k<<<(E1 + T - 1) / T, T>>>(e1, E1, icur1, csr1);
    place_k<<<(E2 + T - 1) / T, T>>>(e2, E2, icur2, csr2);

    // ---- input split ----
    SPLITA(false, x, FIN, XH, XL, 512, 0, Nn);
    splitWdual_k<<<(2 * FIN * DD + T - 1) / T, T>>>(w11, w12, FIN, DD, WH, WL);

    // ---- layer 1: dual conv GEMM (raw) + gathers (fused bias/self/relu/split) ----
    gemm_bf16<0><<<g512, 256, SMEM_GEMM>>>(XH, XL, 512, WH, WL, FIN,
        h, nullptr, nullptr, nullptr, 0, 0, Nn, FIN);
    gather_k<<<gGat, T>>>(csr1, ioff1, dis1, h,       b11, XH, XL, 0,   Nn);
    gather_k<<<gGat, T>>>(csr2, ioff2, dis2, h + 256, b12, XH, XL, 256, Nn);
    // ---- mlp_1 ----
    splitW_k<<<(2 * DD * DD + T - 1) / T, T>>>(m1w1, 2 * DD, DD, WH, WL);
    gemm_bf16<2><<<g256, 256, SMEM_GEMM>>>(XH, XL, 512, WH, WL, 512,
        nullptr, m1b1, YH, YL, 256, 0, Nn, 512);
    splitW_k<<<(DD * DD + T - 1) / T, T>>>(m1w2, DD, DD, WH, WL);
    gemm_bf16<3><<<g256, 256, SMEM_GEMM>>>(YH, YL, 256, WH, WL, 256,
        nullptr, m1b2, XH, XL, 512, 0, Nn, 256);

    // ---- layer 2: dual conv GEMM (A = h1 split, X cols 0-255) ----
    splitWdual_k<<<(2 * DD * DD + T - 1) / T, T>>>(w21, w22, DD, DD, WH, WL);
    gemm_bf16<0><<<g512, 256, SMEM_GEMM>>>(XH, XL, 512, WH, WL, DD,
        h, nullptr, nullptr, nullptr, 0, 0, Nn, DD);
    gather_k<<<gGat, T>>>(csr1, ioff1, dis1, h,       b21, XH, XL, 0,   Nn);
    gather_k<<<gGat, T>>>(csr2, ioff2, dis2, h + 256, b22, XH, XL, 256, Nn);
    // ---- mlp_2 ----
    splitW_k<<<(2 * DD * DD + T - 1) / T, T>>>(m2w1, 2 * DD, DD, WH, WL);
    gemm_bf16<2><<<g256, 256, SMEM_GEMM>>>(XH, XL, 512, WH, WL, 512,
        nullptr, m2b1, YH, YL, 256, 0, Nn, 512);
    splitW_k<<<(DD * DD + T - 1) / T, T>>>(m2w2, DD, DD, WH, WL);
    gemm_bf16<4><<<g256, 256, SMEM_GEMM>>>(YH, YL, 256, WH, WL, 256,
        hf, m2b2, nullptr, nullptr, 0, 0, Nn, 256);

    // ---- pooling ----
    count_k<<<(Nn + T - 1) / T, T>>>(i1, i2, c1, c2, Nn);
    pool_k<<<gN64, T>>>(hf, i1, i2, p1, p2, Nn);
    norm_k<<<(S * 64 + T - 1) / T, T>>>(p1, p2, c1, c2, S);

    // ---- head ----
    SPLITA(false, p1, DD, XH, XL, 512, 0,  S);
    SPLITA(false, p2, DD, XH, XL, 512, DD, S);
    splitW_k<<<(2 * DD * DD + T - 1) / T, T>>>(mw1, 2 * DD, DD, WH, WL);
    gemm_bf16<5><<<gh, 256, SMEM_GEMM>>>(XH, XL, 512, WH, WL, 512,
        hid2, mb1, nullptr, nullptr, 0, 0, S, 512);
    final_k<<<S, DD>>>(hid2, mw2, mb2, out);
}

// round 10
// speedup vs baseline: 2.5904x; 1.0167x over previous
#include <cuda_runtime.h>
#include <cuda_bf16.h>
#include <math.h>
#include <stdint.h>
#include <cstdint>

// ---------------- Problem constants ----------------
#define DD 256
#define FIN 128
#define CC 7

typedef __nv_bfloat16 bf16;

// ---------------- Scratch layout (float offsets) ----------------
#define OFF_H     0L             // fp32 [M,512]
#define OFF_HF    51200000L      // fp32 [M,256]
#define OFF_XH    76800000L      // bf16 [M,512] hi
#define OFF_XL    102400000L
#define OFF_YH    128000000L     // bf16 [M,256] hi
#define OFF_YL    140800000L
#define OFF_WH    153600000L     // bf16 weight arena hi (720896 bf16)
#define OFF_WL    154000000L
#define OFF_HID2  154400000L
#define OFF_DIS1  155680000L
#define OFF_DIS2  155780000L
// ---- zero block start ----
#define OFF_CC    155880000L     // int[2N]   edge-dst counts (concat)
#define OFF_SC    156080000L     // int[2S]   segment counts (concat)
#define OFF_BSN   156090000L     // int[256]
#define OFF_BSS   156090256L     // int[16]
// ---- zero block end ----
#define OFF_COFF  156090272L     // int[2N+1]
#define OFF_CCUR  156290276L     // int[2N]
#define OFF_SOFF  156490276L     // int[2S+1]
#define OFF_SCUR  156500280L     // int[2S]
#define OFF_CSR   156510280L     // int[E1+E2]
#define OFF_SLIST 158110280L     // int[2N]
#define SCRATCH_TOTAL 158310280L

// weight arena offsets (bf16 elements)
#define WC1  0
#define WC2  65536
#define WM1A 196608
#define WM1B 327680
#define WM2A 393216
#define WM2B 524288
#define WHD  589824
#define WTOT 720896

__device__ float g_buf[SCRATCH_TOTAL];

// ---------------- helpers ----------------
__device__ __forceinline__ void splitbf(float v, bf16& h, bf16& l) {
    h = __float2bfloat16(v);
    l = __float2bfloat16(v - __bfloat162float(h));
}

__device__ __forceinline__ void ldm_x4(uint32_t r[4], const void* p) {
    uint32_t addr = (uint32_t)__cvta_generic_to_shared(p);
    asm volatile("ldmatrix.sync.aligned.m8n8.x4.shared.b16 {%0,%1,%2,%3}, [%4];"
                 : "=r"(r[0]), "=r"(r[1]), "=r"(r[2]), "=r"(r[3]) : "r"(addr));
}

__device__ __forceinline__ void mma16816(float c[4], const uint32_t a[4],
                                         uint32_t b0, uint32_t b1) {
    asm volatile(
        "mma.sync.aligned.m16n8k16.row.col.f32.bf16.bf16.f32 "
        "{%0,%1,%2,%3}, {%4,%5,%6,%7}, {%8,%9}, {%0,%1,%2,%3};"
        : "+f"(c[0]), "+f"(c[1]), "+f"(c[2]), "+f"(c[3])
        : "r"(a[0]), "r"(a[1]), "r"(a[2]), "r"(a[3]), "r"(b0), "r"(b1));
}

__device__ __forceinline__ void cp16(uint32_t s, const void* g, int sz) {
    asm volatile("cp.async.cg.shared.global [%0], [%1], 16, %2;"
                 :: "r"(s), "l"(g), "r"(sz));
}

// ---------------- prologue kernels ----------------
#define SCAN_B 1024

__global__ void zero_k(float* __restrict__ p, int n) {
    int i = blockIdx.x * blockDim.x + threadIdx.x;
    if (i < n) p[i] = 0.0f;
}

// counts: edge-dst (both lists, concat at Nn) + segment (both lists, concat at S)
__global__ void countall_k(const int* __restrict__ e1, int E1,
                           const int* __restrict__ e2, int E2,
                           const int* __restrict__ i1, const int* __restrict__ i2,
                           int Nn, int S,
                           int* __restrict__ cc, int* __restrict__ sc) {
    int i = blockIdx.x * blockDim.x + threadIdx.x;
    if (i < E1) atomicAdd(&cc[e1[E1 + i]], 1);
    else if (i < E1 + E2) atomicAdd(&cc[Nn + e2[E2 + (i - E1)]], 1);
    else {
        int j = i - E1 - E2;
        if (j < Nn) {
            atomicAdd(&sc[i1[j]], 1);
            atomicAdd(&sc[S + i2[j]], 1);
        }
    }
}

__global__ void blocksum_k(const int* __restrict__ cnt, int* __restrict__ bsum, int n) {
    int i = blockIdx.x * SCAN_B + threadIdx.x;
    int v = (i < n) ? cnt[i] : 0;
    #pragma unroll
    for (int o = 16; o > 0; o >>= 1) v += __shfl_xor_sync(0xFFFFFFFFu, v, o);
    if ((threadIdx.x & 31) == 0) atomicAdd(&bsum[blockIdx.x], v);
}

__global__ void scanbsum_k(int* __restrict__ bsum, int nb, int* __restrict__ off_n) {
    if (threadIdx.x == 0) {
        int acc = 0;
        for (int i = 0; i < nb; i++) { int v = bsum[i]; bsum[i] = acc; acc += v; }
        *off_n = acc;
    }
}

__global__ void scanblock_k(const int* __restrict__ cnt, const int* __restrict__ bsum,
                            int* __restrict__ off, int* __restrict__ cur, int n) {
    __shared__ int sw[32];
    int tid = threadIdx.x, lane = tid & 31, wid = tid >> 5;
    int i = blockIdx.x * SCAN_B + tid;
    int v = (i < n) ? cnt[i] : 0;
    int inc = v;
    #pragma unroll
    for (int o = 1; o < 32; o <<= 1) {
        int t = __shfl_up_sync(0xFFFFFFFFu, inc, o);
        if (lane >= o) inc += t;
    }
    if (lane == 31) sw[wid] = inc;
    __syncthreads();
    if (wid == 0) {
        int t = sw[lane];
        int ti = t;
        #pragma unroll
        for (int o = 1; o < 32; o <<= 1) {
            int u = __shfl_up_sync(0xFFFFFFFFu, ti, o);
            if (lane >= o) ti += u;
        }
        sw[lane] = ti - t;
    }
    __syncthreads();
    int excl = inc - v + sw[wid] + bsum[blockIdx.x];
    if (i < n) { off[i] = excl; cur[i] = excl; }
}

__global__ void disint_k(const int* __restrict__ cc,
                         float* __restrict__ d1, float* __restrict__ d2, int Nn) {
    int i = blockIdx.x * blockDim.x + threadIdx.x;
    if (i < Nn) {
        d1[i] = rsqrtf((float)cc[i] + 1.0f);
        d2[i] = rsqrtf((float)cc[Nn + i] + 1.0f);
    }
}

__global__ void placeboth_k(const int* __restrict__ e1, int E1,
                            const int* __restrict__ e2, int E2, int Nn,
                            int* __restrict__ cur, int* __restrict__ csr) {
    int i = blockIdx.x * blockDim.x + threadIdx.x;
    if (i < E1) {
        int pos = atomicAdd(&cur[e1[E1 + i]], 1);
        csr[pos] = e1[i];
    } else if (i < E1 + E2) {
        int j = i - E1;
        int pos = atomicAdd(&cur[Nn + e2[E2 + j]], 1);
        csr[pos] = e2[j];
    }
}

__global__ void placeseg_k(const int* __restrict__ i1, const int* __restrict__ i2,
                           int Nn, int S,
                           int* __restrict__ scur, int* __restrict__ slist) {
    int i = blockIdx.x * blockDim.x + threadIdx.x;
    if (i < Nn) {
        int p1 = atomicAdd(&scur[i1[i]], 1);
        slist[p1] = i;
        int p2 = atomicAdd(&scur[S + i2[i]], 1);
        slist[p2] = i;
    }
}

// ---------------- gather conv: X = split(relu(bias + d^2 h_i + sum coef h_j)) ----
__global__ void gather_k(const int* __restrict__ csr, const int* __restrict__ off,
                         const float* __restrict__ dis,
                         const float* __restrict__ h,      // pre-offset, stride 512
                         const float* __restrict__ bias,
                         bf16* __restrict__ oH, bf16* __restrict__ oL,
                         int ocoff, int Nn) {
    int node = blockIdx.x * 4 + (threadIdx.x >> 6);
    if (node >= Nn) return;
    int c = (threadIdx.x & 63) << 2;
    float di = dis[node];
    float d2 = di * di;
    float4 hv = *(const float4*)(h + (size_t)node * 512 + c);
    float4 bv = *(const float4*)(bias + c);
    float4 acc;
    acc.x = bv.x + d2 * hv.x; acc.y = bv.y + d2 * hv.y;
    acc.z = bv.z + d2 * hv.z; acc.w = bv.w + d2 * hv.w;
    int s = off[node], e = off[node + 1];
    for (int k = s; k < e; k++) {
        int j = csr[k];
        float coef = di * dis[j];
        float4 hj = *(const float4*)(h + (size_t)j * 512 + c);
        acc.x += coef * hj.x; acc.y += coef * hj.y;
        acc.z += coef * hj.z; acc.w += coef * hj.w;
    }
    acc.x = fmaxf(acc.x, 0.f); acc.y = fmaxf(acc.y, 0.f);
    acc.z = fmaxf(acc.z, 0.f); acc.w = fmaxf(acc.w, 0.f);
    bf16 h0,l0,h1,l1,h2,l2,h3,l3;
    splitbf(acc.x,h0,l0); splitbf(acc.y,h1,l1);
    splitbf(acc.z,h2,l2); splitbf(acc.w,h3,l3);
    size_t o = (size_t)node * 512 + ocoff + c;
    __nv_bfloat162 t;
    t.x=h0; t.y=h1; *(__nv_bfloat162*)(oH + o) = t;
    t.x=h2; t.y=h3; *(__nv_bfloat162*)(oH + o + 2) = t;
    t.x=l0; t.y=l1; *(__nv_bfloat162*)(oL + o) = t;
    t.x=l2; t.y=l3; *(__nv_bfloat162*)(oL + o + 2) = t;
}

// ---------------- pool gather: X[seg, ocoff..] = split(mean hf over segment) ----
// handles BOTH index lists: global segment g in [0, 2S); g>=S -> list 2 (cols 256+)
__global__ void poolgather_k(const int* __restrict__ slist, const int* __restrict__ soff,
                             const float* __restrict__ hf,
                             bf16* __restrict__ oH, bf16* __restrict__ oL, int S) {
    int g = blockIdx.x * 4 + (threadIdx.x >> 6);
    if (g >= 2 * S) return;
    int part = (g >= S);
    int seg = g - part * S;
    int c = (threadIdx.x & 63) << 2;
    int s = soff[g], e = soff[g + 1];
    float4 acc = make_float4(0.f, 0.f, 0.f, 0.f);
    for (int k = s; k < e; k++) {
        int node = slist[k];
        float4 hv = *(const float4*)(hf + (size_t)node * 256 + c);
        acc.x += hv.x; acc.y += hv.y; acc.z += hv.z; acc.w += hv.w;
    }
    float inv = 1.0f / fmaxf((float)(e - s), 1.0f);
    acc.x *= inv; acc.y *= inv; acc.z *= inv; acc.w *= inv;
    bf16 h0,l0,h1,l1,h2,l2,h3,l3;
    splitbf(acc.x,h0,l0); splitbf(acc.y,h1,l1);
    splitbf(acc.z,h2,l2); splitbf(acc.w,h3,l3);
    size_t o = (size_t)seg * 512 + part * 256 + c;
    __nv_bfloat162 t;
    t.x=h0; t.y=h1; *(__nv_bfloat162*)(oH + o) = t;
    t.x=h2; t.y=h3; *(__nv_bfloat162*)(oH + o + 2) = t;
    t.x=l0; t.y=l1; *(__nv_bfloat162*)(oL + o) = t;
    t.x=l2; t.y=l3; *(__nv_bfloat162*)(oL + o + 2) = t;
}

// ---------------- splits ----------------
template<bool RELU>
__global__ void splitA_k(const float* __restrict__ src, int Ks,
                         bf16* __restrict__ dh, bf16* __restrict__ dl,
                         int dstride, int coff, long total4) {
    long gid = blockIdx.x * (long)blockDim.x + threadIdx.x;
    if (gid >= total4) return;
    long e = gid * 4;
    long r = e / Ks;
    int  c = (int)(e - r * Ks);
    float4 v = *(const float4*)(src + e);
    if (RELU) {
        v.x = fmaxf(v.x, 0.f); v.y = fmaxf(v.y, 0.f);
        v.z = fmaxf(v.z, 0.f); v.w = fmaxf(v.w, 0.f);
    }
    bf16 h0,l0,h1,l1,h2,l2,h3,l3;
    splitbf(v.x,h0,l0); splitbf(v.y,h1,l1); splitbf(v.z,h2,l2); splitbf(v.w,h3,l3);
    __nv_bfloat162* ph = (__nv_bfloat162*)(dh + r * (long)dstride + coff + c);
    __nv_bfloat162* pl = (__nv_bfloat162*)(dl + r * (long)dstride + coff + c);
    __nv_bfloat162 t;
    t.x=h0; t.y=h1; ph[0]=t;  t.x=h2; t.y=h3; ph[1]=t;
    t.x=l0; t.y=l1; pl[0]=t;  t.x=l2; t.y=l3; pl[1]=t;
}

// all 9 weight matrices -> transposed hi/lo arena, one launch
__global__ void splitAllW_k(const float* __restrict__ w11, const float* __restrict__ w12,
                            const float* __restrict__ w21, const float* __restrict__ w22,
                            const float* __restrict__ m1w1, const float* __restrict__ m1w2,
                            const float* __restrict__ m2w1, const float* __restrict__ m2w2,
                            const float* __restrict__ mw1,
                            bf16* __restrict__ dh, bf16* __restrict__ dl) {
    int gid = blockIdx.x * blockDim.x + threadIdx.x;
    if (gid >= WTOT) return;
    float v; int dst;
    if (gid < 65536) {                       // w11/w12 dual: K=128, N=256
        int l = gid, which = l >= 32768, g = l - which * 32768;
        int k = g >> 8, n = g & 255;
        v = which ? w12[g] : w11[g];
        dst = WC1 + (n + which * 256) * 128 + k;
    } else if (gid < 196608) {               // w21/w22 dual: K=256, N=256
        int l = gid - 65536, which = l >= 65536, g = l - which * 65536;
        int k = g >> 8, n = g & 255;
        v = which ? w22[g] : w21[g];
        dst = WC2 + (n + which * 256) * 256 + k;
    } else if (gid < 327680) {               // m1w1: K=512, N=256
        int g = gid - 196608;
        int k = g >> 8, n = g & 255;
        v = m1w1[g];
        dst = WM1A + n * 512 + k;
    } else if (gid < 393216) {               // m1w2: K=256, N=256
        int g = gid - 327680;
        int k = g >> 8, n = g & 255;
        v = m1w2[g];
        dst = WM1B + n * 256 + k;
    } else if (gid < 524288) {               // m2w1: K=512, N=256
        int g = gid - 393216;
        int k = g >> 8, n = g & 255;
        v = m2w1[g];
        dst = WM2A + n * 512 + k;
    } else if (gid < 589824) {               // m2w2: K=256, N=256
        int g = gid - 524288;
        int k = g >> 8, n = g & 255;
        v = m2w2[g];
        dst = WM2B + n * 256 + k;
    } else {                                 // mw1: K=512, N=256
        int g = gid - 589824;
        int k = g >> 8, n = g & 255;
        v = mw1[g];
        dst = WHD + n * 512 + k;
    }
    bf16 h, l;
    splitbf(v, h, l);
    dh[dst] = h;
    dl[dst] = l;
}

// ---------------- head ----------------
__global__ void final_k(const float* __restrict__ hid, const float* __restrict__ w2,
                        const float* __restrict__ b2, float* __restrict__ out) {
    __shared__ float sh[DD];
    __shared__ float lg[CC];
    int s = blockIdx.x;
    int tid = threadIdx.x;
    sh[tid] = hid[(size_t)s * DD + tid];
    __syncthreads();
    int w = tid >> 5, lane = tid & 31;
    if (w < CC) {
        float sum = 0.0f;
        for (int k = lane; k < DD; k += 32) sum += sh[k] * w2[k * CC + w];
        #pragma unroll
        for (int o = 16; o > 0; o >>= 1) sum += __shfl_xor_sync(0xFFFFFFFFu, sum, o);
        if (lane == 0) lg[w] = sum + b2[w];
    }
    __syncthreads();
    if (tid == 0) {
        float mx = -1e30f;
        #pragma unroll
        for (int c = 0; c < CC; c++) mx = fmaxf(mx, lg[c]);
        float se = 0.0f;
        #pragma unroll
        for (int c = 0; c < CC; c++) se += expf(lg[c] - mx);
        float lse = mx + logf(se);
        #pragma unroll
        for (int c = 0; c < CC; c++) out[(size_t)s * CC + c] = lg[c] - lse;
    }
}

// ---------------- bf16 double-buffered GEMM ----------------
// EPI=0 RAW512: C[r*512+c]=acc   EPI=2 split(relu(acc+b))->oH/oL
// EPI=3 split(acc+b)->oH/oL      EPI=4 C[r*256+c]=acc+b   EPI=5 relu
#define LDK2 40
#define STAGE_BYTES 40960

__device__ __forceinline__ void gemm_prefetch(
    char* smbase, int stage, int row, int half,
    const bf16* AH, const bf16* AL, int lda,
    const bf16* BH, const bf16* BL, int ldb,
    int bm, int bn, int M, int k0)
{
    int gra = bm + row;
    int szA = (gra < M) ? 16 : 0;
    if (gra >= M) gra = 0;
    const char* pAH = (const char*)(AH + (size_t)gra * lda + k0) + half * 32;
    const char* pAL = (const char*)(AL + (size_t)gra * lda + k0) + half * 32;
    int grb = bn + row;
    const char* pBH = (const char*)(BH + (size_t)grb * ldb + k0) + half * 32;
    const char* pBL = (const char*)(BL + (size_t)grb * ldb + k0) + half * 32;
    uint32_t so = (uint32_t)__cvta_generic_to_shared(smbase + stage * STAGE_BYTES)
                  + row * (LDK2 * 2) + half * 32;
    cp16(so,              pAH,      szA);  cp16(so + 16,          pAH + 16, szA);
    cp16(so + 10240,      pAL,      szA);  cp16(so + 10240 + 16,  pAL + 16, szA);
    cp16(so + 20480,      pBH,      16);   cp16(so + 20480 + 16,  pBH + 16, 16);
    cp16(so + 30720,      pBL,      16);   cp16(so + 30720 + 16,  pBL + 16, 16);
}

template<int EPI>
__global__ void __launch_bounds__(256)
gemm_bf16(const bf16* __restrict__ AH, const bf16* __restrict__ AL, int lda,
          const bf16* __restrict__ BH, const bf16* __restrict__ BL, int ldb,
          float* __restrict__ C,
          const float* __restrict__ bias,
          bf16* __restrict__ oH, bf16* __restrict__ oL, int ostride, int ocoff,
          int M, int K)
{
    extern __shared__ char sm_[];
    int tid = threadIdx.x, wid = tid >> 5, lane = tid & 31;
    int bm = blockIdx.y * 128, bn = blockIdx.x * 128;
    int wm = (wid & 3) * 32, wn = (wid >> 2) * 64;
    int idx = lane >> 3, lr = lane & 7;
    int row = tid >> 1, half = tid & 1;

    float acc[2][8][4];
    #pragma unroll
    for (int i = 0; i < 2; i++)
        #pragma unroll
        for (int j = 0; j < 8; j++)
            #pragma unroll
            for (int q = 0; q < 4; q++) acc[i][j][q] = 0.0f;

    int KT = K >> 5;
    gemm_prefetch(sm_, 0, row, half, AH, AL, lda, BH, BL, ldb, bm, bn, M, 0);
    asm volatile("cp.async.commit_group;");

    for (int kt = 0; kt < KT; kt++) {
        int s = kt & 1;
        if (kt + 1 < KT) {
            gemm_prefetch(sm_, s ^ 1, row, half, AH, AL, lda, BH, BL, ldb,
                          bm, bn, M, (kt + 1) << 5);
            asm volatile("cp.async.commit_group;");
            asm volatile("cp.async.wait_group 1;");
        } else {
            asm volatile("cp.async.wait_group 0;");
        }
        __syncthreads();

        const bf16* sAh = (const bf16*)(sm_ + s * STAGE_BYTES);
        const bf16* sAl = (const bf16*)(sm_ + s * STAGE_BYTES + 10240);
        const bf16* sBh = (const bf16*)(sm_ + s * STAGE_BYTES + 20480);
        const bf16* sBl = (const bf16*)(sm_ + s * STAGE_BYTES + 30720);

        #pragma unroll
        for (int ks = 0; ks < 2; ks++) {
            int kb = ks * 16;
            uint32_t ah[2][4], al[2][4];
            #pragma unroll
            for (int mf = 0; mf < 2; mf++) {
                int rr = wm + mf * 16 + (idx & 1) * 8 + lr;
                int cc = kb + (idx >> 1) * 8;
                ldm_x4(ah[mf], &sAh[rr * LDK2 + cc]);
                ldm_x4(al[mf], &sAl[rr * LDK2 + cc]);
            }
            uint32_t bh[4][4], bl[4][4];
            #pragma unroll
            for (int bg = 0; bg < 4; bg++) {
                int rr = wn + bg * 16 + (idx >> 1) * 8 + lr;
                int cc = kb + (idx & 1) * 8;
                ldm_x4(bh[bg], &sBh[rr * LDK2 + cc]);
                ldm_x4(bl[bg], &sBl[rr * LDK2 + cc]);
            }
            #pragma unroll
            for (int mf = 0; mf < 2; mf++)
                #pragma unroll
                for (int ng = 0; ng < 8; ng++) {
                    int bg = ng >> 1, pr = (ng & 1) * 2;
                    mma16816(acc[mf][ng], ah[mf], bh[bg][pr], bh[bg][pr + 1]);
                    mma16816(acc[mf][ng], ah[mf], bl[bg][pr], bl[bg][pr + 1]);
                    mma16816(acc[mf][ng], al[mf], bh[bg][pr], bh[bg][pr + 1]);
                }
        }
        __syncthreads();
    }

    // ---- epilogue ----
    int r0 = bm + wm + (lane >> 2);
    int lc0 = wn + (lane & 3) * 2;
    #pragma unroll
    for (int mf = 0; mf < 2; mf++) {
        #pragma unroll
        for (int hf2 = 0; hf2 < 2; hf2++) {
            int r = r0 + mf * 16 + hf2 * 8;
            if (r >= M) continue;
            #pragma unroll
            for (int ng = 0; ng < 8; ng++) {
                int lc = lc0 + ng * 8;
                int c = bn + lc;
                float v0 = acc[mf][ng][hf2 * 2 + 0];
                float v1 = acc[mf][ng][hf2 * 2 + 1];
                if (EPI == 0) {
                    float2 st; st.x = v0; st.y = v1;
                    *(float2*)(C + (size_t)r * 512 + c) = st;
                } else if (EPI == 2 || EPI == 3) {
                    v0 += bias[c]; v1 += bias[c + 1];
                    if (EPI == 2) { v0 = fmaxf(v0, 0.f); v1 = fmaxf(v1, 0.f); }
                    bf16 h0, l0, h1, l1;
                    splitbf(v0, h0, l0); splitbf(v1, h1, l1);
                    __nv_bfloat162 th; th.x = h0; th.y = h1;
                    __nv_bfloat162 tl; tl.x = l0; tl.y = l1;
                    size_t o = (size_t)r * ostride + ocoff + c;
                    *(__nv_bfloat162*)(oH + o) = th;
                    *(__nv_bfloat162*)(oL + o) = tl;
                } else {
                    v0 += bias[c]; v1 += bias[c + 1];
                    if (EPI == 5) { v0 = fmaxf(v0, 0.f); v1 = fmaxf(v1, 0.f); }
                    float2 st; st.x = v0; st.y = v1;
                    *(float2*)(C + (size_t)r * 256 + c) = st;
                }
            }
        }
    }
}

// ---------------- launch ----------------
#define SMEM_GEMM (2 * STAGE_BYTES)

extern "C" void kernel_launch(void* const* d_in, const int* in_sizes, int n_in,
                              void* d_out, int out_size) {
    const float* x    = (const float*)d_in[0];
    const int*   e1   = (const int*)d_in[1];
    const int*   e2   = (const int*)d_in[2];
    const int*   i1   = (const int*)d_in[3];
    const int*   i2   = (const int*)d_in[4];
    const float* w11  = (const float*)d_in[5];
    const float* b11  = (const float*)d_in[6];
    const float* w12  = (const float*)d_in[7];
    const float* b12  = (const float*)d_in[8];
    const float* w21  = (const float*)d_in[9];
    const float* b21  = (const float*)d_in[10];
    const float* w22  = (const float*)d_in[11];
    const float* b22  = (const float*)d_in[12];
    const float* m1w1 = (const float*)d_in[13];
    const float* m1b1 = (const float*)d_in[14];
    const float* m1w2 = (const float*)d_in[15];
    const float* m1b2 = (const float*)d_in[16];
    const float* m2w1 = (const float*)d_in[17];
    const float* m2b1 = (const float*)d_in[18];
    const float* m2w2 = (const float*)d_in[19];
    const float* m2b2 = (const float*)d_in[20];
    const float* mw1  = (const float*)d_in[21];
    const float* mb1  = (const float*)d_in[22];
    const float* mw2  = (const float*)d_in[23];
    const float* mb2  = (const float*)d_in[24];
    float* out = (float*)d_out;

    int Nn = in_sizes[0] / FIN;
    int E1 = in_sizes[1] / 2;
    int E2 = in_sizes[2] / 2;
    int S  = out_size / CC;

    float* base = nullptr;
    cudaGetSymbolAddress((void**)&base, g_buf);
    float* h    = base + OFF_H;
    float* hf   = base + OFF_HF;
    float* hid2 = base + OFF_HID2;
    float* dis1 = base + OFF_DIS1;
    float* dis2 = base + OFF_DIS2;
    int* cc     = (int*)(base + OFF_CC);
    int* sc     = (int*)(base + OFF_SC);
    int* bsn    = (int*)(base + OFF_BSN);
    int* bss    = (int*)(base + OFF_BSS);
    int* coff   = (int*)(base + OFF_COFF);
    int* ccur   = (int*)(base + OFF_CCUR);
    int* soff   = (int*)(base + OFF_SOFF);
    int* scur   = (int*)(base + OFF_SCUR);
    int* csr    = (int*)(base + OFF_CSR);
    int* slist  = (int*)(base + OFF_SLIST);
    bf16* XH = (bf16*)(base + OFF_XH);
    bf16* XL = (bf16*)(base + OFF_XL);
    bf16* YH = (bf16*)(base + OFF_YH);
    bf16* YL = (bf16*)(base + OFF_YL);
    bf16* WH = (bf16*)(base + OFF_WH);
    bf16* WL = (bf16*)(base + OFF_WL);

    cudaFuncSetAttribute(gemm_bf16<0>, cudaFuncAttributeMaxDynamicSharedMemorySize, SMEM_GEMM);
    cudaFuncSetAttribute(gemm_bf16<2>, cudaFuncAttributeMaxDynamicSharedMemorySize, SMEM_GEMM);
    cudaFuncSetAttribute(gemm_bf16<3>, cudaFuncAttributeMaxDynamicSharedMemorySize, SMEM_GEMM);
    cudaFuncSetAttribute(gemm_bf16<4>, cudaFuncAttributeMaxDynamicSharedMemorySize, SMEM_GEMM);
    cudaFuncSetAttribute(gemm_bf16<5>, cudaFuncAttributeMaxDynamicSharedMemorySize, SMEM_GEMM);

    const int T = 256;
    unsigned gy  = (unsigned)((Nn + 127) / 128);
    unsigned gys = (unsigned)((S + 127) / 128);
    dim3 g512(4, gy), g256(2, gy), gh(2, gys);
    unsigned gGat = (unsigned)((Nn + 3) / 4);
    unsigned gPool = (unsigned)((2 * S + 3) / 4);
    int nbN = (2 * Nn + SCAN_B - 1) / SCAN_B;
    int nbS = (2 * S + SCAN_B - 1) / SCAN_B;
    int nz = (int)(OFF_COFF - OFF_CC);

    // ---- prologue: zero + node/segment CSR build ----
    zero_k<<<(nz + T - 1) / T, T>>>(base + OFF_CC, nz);
    countall_k<<<(E1 + E2 + Nn + T - 1) / T, T>>>(e1, E1, e2, E2, i1, i2, Nn, S, cc, sc);
    blocksum_k<<<nbN, SCAN_B>>>(cc, bsn, 2 * Nn);
    blocksum_k<<<nbS, SCAN_B>>>(sc, bss, 2 * S);
    scanbsum_k<<<1, 32>>>(bsn, nbN, coff + 2 * Nn);
    scanbsum_k<<<1, 32>>>(bss, nbS, soff + 2 * S);
    scanblock_k<<<nbN, SCAN_B>>>(cc, bsn, coff, ccur, 2 * Nn);
    scanblock_k<<<nbS, SCAN_B>>>(sc, bss, soff, scur, 2 * S);
    disint_k<<<(Nn + T - 1) / T, T>>>(cc, dis1, dis2, Nn);
    placeboth_k<<<(E1 + E2 + T - 1) / T, T>>>(e1, E1, e2, E2, Nn, ccur, csr);
    placeseg_k<<<(Nn + T - 1) / T, T>>>(i1, i2, Nn, S, scur, slist);

    // ---- splits: input x + all weights (one launch each) ----
    long t4 = (long)Nn * FIN / 4;
    splitA_k<false><<<(unsigned)((t4 + T - 1) / T), T>>>(x, FIN, XH, XL, 512, 0, t4);
    splitAllW_k<<<(WTOT + T - 1) / T, T>>>(w11, w12, w21, w22, m1w1, m1w2, m2w1, m2w2, mw1, WH, WL);

    // ---- layer 1: dual conv GEMM + gathers ----
    gemm_bf16<0><<<g512, 256, SMEM_GEMM>>>(XH, XL, 512, WH + WC1, WL + WC1, FIN,
        h, nullptr, nullptr, nullptr, 0, 0, Nn, FIN);
    gather_k<<<gGat, T>>>(csr, coff,      dis1, h,       b11, XH, XL, 0,   Nn);
    gather_k<<<gGat, T>>>(csr, coff + Nn, dis2, h + 256, b12, XH, XL, 256, Nn);
    // ---- mlp_1 ----
    gemm_bf16<2><<<g256, 256, SMEM_GEMM>>>(XH, XL, 512, WH + WM1A, WL + WM1A, 512,
        nullptr, m1b1, YH, YL, 256, 0, Nn, 512);
    gemm_bf16<3><<<g256, 256, SMEM_GEMM>>>(YH, YL, 256, WH + WM1B, WL + WM1B, 256,
        nullptr, m1b2, XH, XL, 512, 0, Nn, 256);

    // ---- layer 2: dual conv GEMM + gathers ----
    gemm_bf16<0><<<g512, 256, SMEM_GEMM>>>(XH, XL, 512, WH + WC2, WL + WC2, DD,
        h, nullptr, nullptr, nullptr, 0, 0, Nn, DD);
    gather_k<<<gGat, T>>>(csr, coff,      dis1, h,       b21, XH, XL, 0,   Nn);
    gather_k<<<gGat, T>>>(csr, coff + Nn, dis2, h + 256, b22, XH, XL, 256, Nn);
    // ---- mlp_2 ----
    gemm_bf16<2><<<g256, 256, SMEM_GEMM>>>(XH, XL, 512, WH + WM2A, WL + WM2A, 512,
        nullptr, m2b1, YH, YL, 256, 0, Nn, 512);
    gemm_bf16<4><<<g256, 256, SMEM_GEMM>>>(YH, YL, 256, WH + WM2B, WL + WM2B, 256,
        hf, m2b2, nullptr, nullptr, 0, 0, Nn, 256);

    // ---- pooling (atomic-free, fused mean + split into head A) ----
    poolgather_k<<<gPool, T>>>(slist, soff, hf, XH, XL, S);

    // ---- head ----
    gemm_bf16<5><<<gh, 256, SMEM_GEMM>>>(XH, XL, 512, WH + WHD, WL + WHD, 512,
        hid2, mb1, nullptr, nullptr, 0, 0, S, 512);
    final_k<<<S, DD>>>(hid2, mw2, mb2, out);
}

// round 11
// speedup vs baseline: 2.6656x; 1.0290x over previous
#include <cuda_runtime.h>
#include <cuda_bf16.h>
#include <math.h>
#include <stdint.h>
#include <cstdint>

// ---------------- Problem constants ----------------
#define DD 256
#define FIN 128
#define CC 7

typedef __nv_bfloat16 bf16;

// ---------------- Scratch layout (float offsets) ----------------
#define OFF_H     0L             // fp32 [M,512]
#define OFF_HF    51200000L      // fp32 [M,256]
#define OFF_XH    76800000L      // bf16 [M,512] hi
#define OFF_XL    102400000L
#define OFF_YH    128000000L     // bf16 [M,256] hi
#define OFF_YL    140800000L
#define OFF_WH    153600000L     // bf16 weight arena hi (720896 bf16)
#define OFF_WL    154000000L
#define OFF_HID2  154400000L
#define OFF_DIS1  155680000L
#define OFF_DIS2  155780000L
// ---- zero block start ----
#define OFF_CC    155880000L     // int[2N]
#define OFF_SC    156080000L     // int[2S]
#define OFF_BSN   156090000L     // int[256]
#define OFF_BSS   156090256L     // int[16]
// ---- zero block end ----
#define OFF_COFF  156090272L     // int[2N+1]
#define OFF_CCUR  156290276L
#define OFF_SOFF  156490276L     // int[2S+1]
#define OFF_SCUR  156500280L
#define OFF_CSR   156510280L     // int[E1+E2]
#define OFF_SLIST 158110280L     // int[2N]
#define SCRATCH_TOTAL 158310280L

// weight arena offsets (bf16 elements)
#define WC1  0
#define WC2  65536
#define WM1A 196608
#define WM1B 327680
#define WM2A 393216
#define WM2B 524288
#define WHD  589824
#define WTOT 720896

__device__ float g_buf[SCRATCH_TOTAL];

// ---------------- helpers ----------------
__device__ __forceinline__ void splitbf(float v, bf16& h, bf16& l) {
    h = __float2bfloat16(v);
    l = __float2bfloat16(v - __bfloat162float(h));
}

__device__ __forceinline__ void ldm_x4(uint32_t r[4], const void* p) {
    uint32_t addr = (uint32_t)__cvta_generic_to_shared(p);
    asm volatile("ldmatrix.sync.aligned.m8n8.x4.shared.b16 {%0,%1,%2,%3}, [%4];"
                 : "=r"(r[0]), "=r"(r[1]), "=r"(r[2]), "=r"(r[3]) : "r"(addr));
}

__device__ __forceinline__ void mma16816(float c[4], const uint32_t a[4],
                                         uint32_t b0, uint32_t b1) {
    asm volatile(
        "mma.sync.aligned.m16n8k16.row.col.f32.bf16.bf16.f32 "
        "{%0,%1,%2,%3}, {%4,%5,%6,%7}, {%8,%9}, {%0,%1,%2,%3};"
        : "+f"(c[0]), "+f"(c[1]), "+f"(c[2]), "+f"(c[3])
        : "r"(a[0]), "r"(a[1]), "r"(a[2]), "r"(a[3]), "r"(b0), "r"(b1));
}

__device__ __forceinline__ void cp16(uint32_t s, const void* g, int sz) {
    asm volatile("cp.async.cg.shared.global [%0], [%1], 16, %2;"
                 :: "r"(s), "l"(g), "r"(sz));
}

// ---------------- prologue kernels ----------------
#define SCAN_B 1024

__global__ void zero_k(float* __restrict__ p, int n) {
    int i = blockIdx.x * blockDim.x + threadIdx.x;
    if (i < n) p[i] = 0.0f;
}

__global__ void countall_k(const int* __restrict__ e1, int E1,
                           const int* __restrict__ e2, int E2,
                           const int* __restrict__ i1, const int* __restrict__ i2,
                           int Nn, int S,
                           int* __restrict__ cc, int* __restrict__ sc) {
    int i = blockIdx.x * blockDim.x + threadIdx.x;
    if (i < E1) atomicAdd(&cc[e1[E1 + i]], 1);
    else if (i < E1 + E2) atomicAdd(&cc[Nn + e2[E2 + (i - E1)]], 1);
    else {
        int j = i - E1 - E2;
        if (j < Nn) {
            atomicAdd(&sc[i1[j]], 1);
            atomicAdd(&sc[S + i2[j]], 1);
        }
    }
}

__global__ void blocksum_k(const int* __restrict__ cnt, int* __restrict__ bsum, int n) {
    int i = blockIdx.x * SCAN_B + threadIdx.x;
    int v = (i < n) ? cnt[i] : 0;
    #pragma unroll
    for (int o = 16; o > 0; o >>= 1) v += __shfl_xor_sync(0xFFFFFFFFu, v, o);
    if ((threadIdx.x & 31) == 0) atomicAdd(&bsum[blockIdx.x], v);
}

__global__ void scanbsum_k(int* __restrict__ bsum, int nb, int* __restrict__ off_n) {
    if (threadIdx.x == 0) {
        int acc = 0;
        for (int i = 0; i < nb; i++) { int v = bsum[i]; bsum[i] = acc; acc += v; }
        *off_n = acc;
    }
}

__global__ void scanblock_k(const int* __restrict__ cnt, const int* __restrict__ bsum,
                            int* __restrict__ off, int* __restrict__ cur, int n) {
    __shared__ int sw[32];
    int tid = threadIdx.x, lane = tid & 31, wid = tid >> 5;
    int i = blockIdx.x * SCAN_B + tid;
    int v = (i < n) ? cnt[i] : 0;
    int inc = v;
    #pragma unroll
    for (int o = 1; o < 32; o <<= 1) {
        int t = __shfl_up_sync(0xFFFFFFFFu, inc, o);
        if (lane >= o) inc += t;
    }
    if (lane == 31) sw[wid] = inc;
    __syncthreads();
    if (wid == 0) {
        int t = sw[lane];
        int ti = t;
        #pragma unroll
        for (int o = 1; o < 32; o <<= 1) {
            int u = __shfl_up_sync(0xFFFFFFFFu, ti, o);
            if (lane >= o) ti += u;
        }
        sw[lane] = ti - t;
    }
    __syncthreads();
    int excl = inc - v + sw[wid] + bsum[blockIdx.x];
    if (i < n) { off[i] = excl; cur[i] = excl; }
}

__global__ void disint_k(const int* __restrict__ cc,
                         float* __restrict__ d1, float* __restrict__ d2, int Nn) {
    int i = blockIdx.x * blockDim.x + threadIdx.x;
    if (i < Nn) {
        d1[i] = rsqrtf((float)cc[i] + 1.0f);
        d2[i] = rsqrtf((float)cc[Nn + i] + 1.0f);
    }
}

__global__ void placeboth_k(const int* __restrict__ e1, int E1,
                            const int* __restrict__ e2, int E2, int Nn,
                            int* __restrict__ cur, int* __restrict__ csr) {
    int i = blockIdx.x * blockDim.x + threadIdx.x;
    if (i < E1) {
        int pos = atomicAdd(&cur[e1[E1 + i]], 1);
        csr[pos] = e1[i];
    } else if (i < E1 + E2) {
        int j = i - E1;
        int pos = atomicAdd(&cur[Nn + e2[E2 + j]], 1);
        csr[pos] = e2[j];
    }
}

__global__ void placeseg_k(const int* __restrict__ i1, const int* __restrict__ i2,
                           int Nn, int S,
                           int* __restrict__ scur, int* __restrict__ slist) {
    int i = blockIdx.x * blockDim.x + threadIdx.x;
    if (i < Nn) {
        int p1 = atomicAdd(&scur[i1[i]], 1);
        slist[p1] = i;
        int p2 = atomicAdd(&scur[S + i2[i]], 1);
        slist[p2] = i;
    }
}

// ---------------- gather conv (column-blocked for L2 residency) ----------------
// Processes 128 feature columns starting at cblk. 32 threads per node.
// X[node, ocoff+cblk+c] = split(relu(bias + d^2 h_i + sum coef h_j))[c]
__global__ void gather_k(const int* __restrict__ csr, const int* __restrict__ off,
                         const float* __restrict__ dis,
                         const float* __restrict__ h,      // pre-offset, stride 512
                         const float* __restrict__ bias,
                         bf16* __restrict__ oH, bf16* __restrict__ oL,
                         int ocoff, int cblk, int Nn) {
    int node = blockIdx.x * 8 + (threadIdx.x >> 5);
    if (node >= Nn) return;
    int c = cblk + ((threadIdx.x & 31) << 2);
    float di = dis[node];
    float d2 = di * di;
    float4 hv = *(const float4*)(h + (size_t)node * 512 + c);
    float4 bv = *(const float4*)(bias + c);
    float4 acc;
    acc.x = bv.x + d2 * hv.x; acc.y = bv.y + d2 * hv.y;
    acc.z = bv.z + d2 * hv.z; acc.w = bv.w + d2 * hv.w;
    int s = off[node], e = off[node + 1];
    for (int k = s; k < e; k++) {
        int j = csr[k];
        float coef = di * dis[j];
        float4 hj = *(const float4*)(h + (size_t)j * 512 + c);
        acc.x += coef * hj.x; acc.y += coef * hj.y;
        acc.z += coef * hj.z; acc.w += coef * hj.w;
    }
    acc.x = fmaxf(acc.x, 0.f); acc.y = fmaxf(acc.y, 0.f);
    acc.z = fmaxf(acc.z, 0.f); acc.w = fmaxf(acc.w, 0.f);
    bf16 h0,l0,h1,l1,h2,l2,h3,l3;
    splitbf(acc.x,h0,l0); splitbf(acc.y,h1,l1);
    splitbf(acc.z,h2,l2); splitbf(acc.w,h3,l3);
    size_t o = (size_t)node * 512 + ocoff + c;
    __nv_bfloat162 t;
    t.x=h0; t.y=h1; *(__nv_bfloat162*)(oH + o) = t;
    t.x=h2; t.y=h3; *(__nv_bfloat162*)(oH + o + 2) = t;
    t.x=l0; t.y=l1; *(__nv_bfloat162*)(oL + o) = t;
    t.x=l2; t.y=l3; *(__nv_bfloat162*)(oL + o + 2) = t;
}

// ---------------- pool gather ----------------
__global__ void poolgather_k(const int* __restrict__ slist, const int* __restrict__ soff,
                             const float* __restrict__ hf,
                             bf16* __restrict__ oH, bf16* __restrict__ oL, int S) {
    int g = blockIdx.x * 4 + (threadIdx.x >> 6);
    if (g >= 2 * S) return;
    int part = (g >= S);
    int seg = g - part * S;
    int c = (threadIdx.x & 63) << 2;
    int s = soff[g], e = soff[g + 1];
    float4 acc = make_float4(0.f, 0.f, 0.f, 0.f);
    for (int k = s; k < e; k++) {
        int node = slist[k];
        float4 hv = *(const float4*)(hf + (size_t)node * 256 + c);
        acc.x += hv.x; acc.y += hv.y; acc.z += hv.z; acc.w += hv.w;
    }
    float inv = 1.0f / fmaxf((float)(e - s), 1.0f);
    acc.x *= inv; acc.y *= inv; acc.z *= inv; acc.w *= inv;
    bf16 h0,l0,h1,l1,h2,l2,h3,l3;
    splitbf(acc.x,h0,l0); splitbf(acc.y,h1,l1);
    splitbf(acc.z,h2,l2); splitbf(acc.w,h3,l3);
    size_t o = (size_t)seg * 512 + part * 256 + c;
    __nv_bfloat162 t;
    t.x=h0; t.y=h1; *(__nv_bfloat162*)(oH + o) = t;
    t.x=h2; t.y=h3; *(__nv_bfloat162*)(oH + o + 2) = t;
    t.x=l0; t.y=l1; *(__nv_bfloat162*)(oL + o) = t;
    t.x=l2; t.y=l3; *(__nv_bfloat162*)(oL + o + 2) = t;
}

// ---------------- splits ----------------
template<bool RELU>
__global__ void splitA_k(const float* __restrict__ src, int Ks,
                         bf16* __restrict__ dh, bf16* __restrict__ dl,
                         int dstride, int coff, long total4) {
    long gid = blockIdx.x * (long)blockDim.x + threadIdx.x;
    if (gid >= total4) return;
    long e = gid * 4;
    long r = e / Ks;
    int  c = (int)(e - r * Ks);
    float4 v = *(const float4*)(src + e);
    if (RELU) {
        v.x = fmaxf(v.x, 0.f); v.y = fmaxf(v.y, 0.f);
        v.z = fmaxf(v.z, 0.f); v.w = fmaxf(v.w, 0.f);
    }
    bf16 h0,l0,h1,l1,h2,l2,h3,l3;
    splitbf(v.x,h0,l0); splitbf(v.y,h1,l1); splitbf(v.z,h2,l2); splitbf(v.w,h3,l3);
    __nv_bfloat162* ph = (__nv_bfloat162*)(dh + r * (long)dstride + coff + c);
    __nv_bfloat162* pl = (__nv_bfloat162*)(dl + r * (long)dstride + coff + c);
    __nv_bfloat162 t;
    t.x=h0; t.y=h1; ph[0]=t;  t.x=h2; t.y=h3; ph[1]=t;
    t.x=l0; t.y=l1; pl[0]=t;  t.x=l2; t.y=l3; pl[1]=t;
}

__global__ void splitAllW_k(const float* __restrict__ w11, const float* __restrict__ w12,
                            const float* __restrict__ w21, const float* __restrict__ w22,
                            const float* __restrict__ m1w1, const float* __restrict__ m1w2,
                            const float* __restrict__ m2w1, const float* __restrict__ m2w2,
                            const float* __restrict__ mw1,
                            bf16* __restrict__ dh, bf16* __restrict__ dl) {
    int gid = blockIdx.x * blockDim.x + threadIdx.x;
    if (gid >= WTOT) return;
    float v; int dst;
    if (gid < 65536) {
        int l = gid, which = l >= 32768, g = l - which * 32768;
        int k = g >> 8, n = g & 255;
        v = which ? w12[g] : w11[g];
        dst = WC1 + (n + which * 256) * 128 + k;
    } else if (gid < 196608) {
        int l = gid - 65536, which = l >= 65536, g = l - which * 65536;
        int k = g >> 8, n = g & 255;
        v = which ? w22[g] : w21[g];
        dst = WC2 + (n + which * 256) * 256 + k;
    } else if (gid < 327680) {
        int g = gid - 196608;
        int k = g >> 8, n = g & 255;
        v = m1w1[g];
        dst = WM1A + n * 512 + k;
    } else if (gid < 393216) {
        int g = gid - 327680;
        int k = g >> 8, n = g & 255;
        v = m1w2[g];
        dst = WM1B + n * 256 + k;
    } else if (gid < 524288) {
        int g = gid - 393216;
        int k = g >> 8, n = g & 255;
        v = m2w1[g];
        dst = WM2A + n * 512 + k;
    } else if (gid < 589824) {
        int g = gid - 524288;
        int k = g >> 8, n = g & 255;
        v = m2w2[g];
        dst = WM2B + n * 256 + k;
    } else {
        int g = gid - 589824;
        int k = g >> 8, n = g & 255;
        v = mw1[g];
        dst = WHD + n * 512 + k;
    }
    bf16 h, l;
    splitbf(v, h, l);
    dh[dst] = h;
    dl[dst] = l;
}

// ---------------- head ----------------
__global__ void final_k(const float* __restrict__ hid, const float* __restrict__ w2,
                        const float* __restrict__ b2, float* __restrict__ out) {
    __shared__ float sh[DD];
    __shared__ float lg[CC];
    int s = blockIdx.x;
    int tid = threadIdx.x;
    sh[tid] = hid[(size_t)s * DD + tid];
    __syncthreads();
    int w = tid >> 5, lane = tid & 31;
    if (w < CC) {
        float sum = 0.0f;
        for (int k = lane; k < DD; k += 32) sum += sh[k] * w2[k * CC + w];
        #pragma unroll
        for (int o = 16; o > 0; o >>= 1) sum += __shfl_xor_sync(0xFFFFFFFFu, sum, o);
        if (lane == 0) lg[w] = sum + b2[w];
    }
    __syncthreads();
    if (tid == 0) {
        float mx = -1e30f;
        #pragma unroll
        for (int c = 0; c < CC; c++) mx = fmaxf(mx, lg[c]);
        float se = 0.0f;
        #pragma unroll
        for (int c = 0; c < CC; c++) se += expf(lg[c] - mx);
        float lse = mx + logf(se);
        #pragma unroll
        for (int c = 0; c < CC; c++) out[(size_t)s * CC + c] = lg[c] - lse;
    }
}

// ---------------- bf16 double-buffered GEMM ----------------
#define LDK2 40
#define STAGE_BYTES 40960

__device__ __forceinline__ void gemm_prefetch(
    char* smbase, int stage, int row, int half,
    const bf16* AH, const bf16* AL, int lda,
    const bf16* BH, const bf16* BL, int ldb,
    int bm, int bn, int M, int k0)
{
    int gra = bm + row;
    int szA = (gra < M) ? 16 : 0;
    if (gra >= M) gra = 0;
    const char* pAH = (const char*)(AH + (size_t)gra * lda + k0) + half * 32;
    const char* pAL = (const char*)(AL + (size_t)gra * lda + k0) + half * 32;
    int grb = bn + row;
    const char* pBH = (const char*)(BH + (size_t)grb * ldb + k0) + half * 32;
    const char* pBL = (const char*)(BL + (size_t)grb * ldb + k0) + half * 32;
    uint32_t so = (uint32_t)__cvta_generic_to_shared(smbase + stage * STAGE_BYTES)
                  + row * (LDK2 * 2) + half * 32;
    cp16(so,              pAH,      szA);  cp16(so + 16,          pAH + 16, szA);
    cp16(so + 10240,      pAL,      szA);  cp16(so + 10240 + 16,  pAL + 16, szA);
    cp16(so + 20480,      pBH,      16);   cp16(so + 20480 + 16,  pBH + 16, 16);
    cp16(so + 30720,      pBL,      16);   cp16(so + 30720 + 16,  pBL + 16, 16);
}

template<int EPI>
__global__ void __launch_bounds__(256)
gemm_bf16(const bf16* __restrict__ AH, const bf16* __restrict__ AL, int lda,
          const bf16* __restrict__ BH, const bf16* __restrict__ BL, int ldb,
          float* __restrict__ C,
          const float* __restrict__ bias,
          bf16* __restrict__ oH, bf16* __restrict__ oL, int ostride, int ocoff,
          int M, int K)
{
    extern __shared__ char sm_[];
    int tid = threadIdx.x, wid = tid >> 5, lane = tid & 31;
    int bm = blockIdx.y * 128, bn = blockIdx.x * 128;
    int wm = (wid & 3) * 32, wn = (wid >> 2) * 64;
    int idx = lane >> 3, lr = lane & 7;
    int row = tid >> 1, half = tid & 1;

    float acc[2][8][4];
    #pragma unroll
    for (int i = 0; i < 2; i++)
        #pragma unroll
        for (int j = 0; j < 8; j++)
            #pragma unroll
            for (int q = 0; q < 4; q++) acc[i][j][q] = 0.0f;

    int KT = K >> 5;
    gemm_prefetch(sm_, 0, row, half, AH, AL, lda, BH, BL, ldb, bm, bn, M, 0);
    asm volatile("cp.async.commit_group;");

    for (int kt = 0; kt < KT; kt++) {
        int s = kt & 1;
        if (kt + 1 < KT) {
            gemm_prefetch(sm_, s ^ 1, row, half, AH, AL, lda, BH, BL, ldb,
                          bm, bn, M, (kt + 1) << 5);
            asm volatile("cp.async.commit_group;");
            asm volatile("cp.async.wait_group 1;");
        } else {
            asm volatile("cp.async.wait_group 0;");
        }
        __syncthreads();

        const bf16* sAh = (const bf16*)(sm_ + s * STAGE_BYTES);
        const bf16* sAl = (const bf16*)(sm_ + s * STAGE_BYTES + 10240);
        const bf16* sBh = (const bf16*)(sm_ + s * STAGE_BYTES + 20480);
        const bf16* sBl = (const bf16*)(sm_ + s * STAGE_BYTES + 30720);

        #pragma unroll
        for (int ks = 0; ks < 2; ks++) {
            int kb = ks * 16;
            uint32_t ah[2][4], al[2][4];
            #pragma unroll
            for (int mf = 0; mf < 2; mf++) {
                int rr = wm + mf * 16 + (idx & 1) * 8 + lr;
                int cc = kb + (idx >> 1) * 8;
                ldm_x4(ah[mf], &sAh[rr * LDK2 + cc]);
                ldm_x4(al[mf], &sAl[rr * LDK2 + cc]);
            }
            uint32_t bh[4][4], bl[4][4];
            #pragma unroll
            for (int bg = 0; bg < 4; bg++) {
                int rr = wn + bg * 16 + (idx >> 1) * 8 + lr;
                int cc = kb + (idx & 1) * 8;
                ldm_x4(bh[bg], &sBh[rr * LDK2 + cc]);
                ldm_x4(bl[bg], &sBl[rr * LDK2 + cc]);
            }
            #pragma unroll
            for (int mf = 0; mf < 2; mf++)
                #pragma unroll
                for (int ng = 0; ng < 8; ng++) {
                    int bg = ng >> 1, pr = (ng & 1) * 2;
                    mma16816(acc[mf][ng], ah[mf], bh[bg][pr], bh[bg][pr + 1]);
                    mma16816(acc[mf][ng], ah[mf], bl[bg][pr], bl[bg][pr + 1]);
                    mma16816(acc[mf][ng], al[mf], bh[bg][pr], bh[bg][pr + 1]);
                }
        }
        __syncthreads();
    }

    // ---- epilogue ----
    int r0 = bm + wm + (lane >> 2);
    int lc0 = wn + (lane & 3) * 2;
    #pragma unroll
    for (int mf = 0; mf < 2; mf++) {
        #pragma unroll
        for (int hf2 = 0; hf2 < 2; hf2++) {
            int r = r0 + mf * 16 + hf2 * 8;
            if (r >= M) continue;
            #pragma unroll
            for (int ng = 0; ng < 8; ng++) {
                int lc = lc0 + ng * 8;
                int c = bn + lc;
                float v0 = acc[mf][ng][hf2 * 2 + 0];
                float v1 = acc[mf][ng][hf2 * 2 + 1];
                if (EPI == 0) {
                    float2 st; st.x = v0; st.y = v1;
                    *(float2*)(C + (size_t)r * 512 + c) = st;
                } else if (EPI == 2 || EPI == 3) {
                    v0 += bias[c]; v1 += bias[c + 1];
                    if (EPI == 2) { v0 = fmaxf(v0, 0.f); v1 = fmaxf(v1, 0.f); }
                    bf16 h0, l0, h1, l1;
                    splitbf(v0, h0, l0); splitbf(v1, h1, l1);
                    __nv_bfloat162 th; th.x = h0; th.y = h1;
                    __nv_bfloat162 tl; tl.x = l0; tl.y = l1;
                    size_t o = (size_t)r * ostride + ocoff + c;
                    *(__nv_bfloat162*)(oH + o) = th;
                    *(__nv_bfloat162*)(oL + o) = tl;
                } else {
                    v0 += bias[c]; v1 += bias[c + 1];
                    if (EPI == 5) { v0 = fmaxf(v0, 0.f); v1 = fmaxf(v1, 0.f); }
                    float2 st; st.x = v0; st.y = v1;
                    *(float2*)(C + (size_t)r * 256 + c) = st;
                }
            }
        }
    }
}

// ---------------- launch ----------------
#define SMEM_GEMM (2 * STAGE_BYTES)

extern "C" void kernel_launch(void* const* d_in, const int* in_sizes, int n_in,
                              void* d_out, int out_size) {
    const float* x    = (const float*)d_in[0];
    const int*   e1   = (const int*)d_in[1];
    const int*   e2   = (const int*)d_in[2];
    const int*   i1   = (const int*)d_in[3];
    const int*   i2   = (const int*)d_in[4];
    const float* w11  = (const float*)d_in[5];
    const float* b11  = (const float*)d_in[6];
    const float* w12  = (const float*)d_in[7];
    const float* b12  = (const float*)d_in[8];
    const float* w21  = (const float*)d_in[9];
    const float* b21  = (const float*)d_in[10];
    const float* w22  = (const float*)d_in[11];
    const float* b22  = (const float*)d_in[12];
    const float* m1w1 = (const float*)d_in[13];
    const float* m1b1 = (const float*)d_in[14];
    const float* m1w2 = (const float*)d_in[15];
    const float* m1b2 = (const float*)d_in[16];
    const float* m2w1 = (const float*)d_in[17];
    const float* m2b1 = (const float*)d_in[18];
    const float* m2w2 = (const float*)d_in[19];
    const float* m2b2 = (const float*)d_in[20];
    const float* mw1  = (const float*)d_in[21];
    const float* mb1  = (const float*)d_in[22];
    const float* mw2  = (const float*)d_in[23];
    const float* mb2  = (const float*)d_in[24];
    float* out = (float*)d_out;

    int Nn = in_sizes[0] / FIN;
    int E1 = in_sizes[1] / 2;
    int E2 = in_sizes[2] / 2;
    int S  = out_size / CC;

    float* base = nullptr;
    cudaGetSymbolAddress((void**)&base, g_buf);
    float* h    = base + OFF_H;
    float* hf   = base + OFF_HF;
    float* hid2 = base + OFF_HID2;
    float* dis1 = base + OFF_DIS1;
    float* dis2 = base + OFF_DIS2;
    int* cc     = (int*)(base + OFF_CC);
    int* sc     = (int*)(base + OFF_SC);
    int* bsn    = (int*)(base + OFF_BSN);
    int* bss    = (int*)(base + OFF_BSS);
    int* coff   = (int*)(base + OFF_COFF);
    int* ccur   = (int*)(base + OFF_CCUR);
    int* soff   = (int*)(base + OFF_SOFF);
    int* scur   = (int*)(base + OFF_SCUR);
    int* csr    = (int*)(base + OFF_CSR);
    int* slist  = (int*)(base + OFF_SLIST);
    bf16* XH = (bf16*)(base + OFF_XH);
    bf16* XL = (bf16*)(base + OFF_XL);
    bf16* YH = (bf16*)(base + OFF_YH);
    bf16* YL = (bf16*)(base + OFF_YL);
    bf16* WH = (bf16*)(base + OFF_WH);
    bf16* WL = (bf16*)(base + OFF_WL);

    cudaFuncSetAttribute(gemm_bf16<0>, cudaFuncAttributeMaxDynamicSharedMemorySize, SMEM_GEMM);
    cudaFuncSetAttribute(gemm_bf16<2>, cudaFuncAttributeMaxDynamicSharedMemorySize, SMEM_GEMM);
    cudaFuncSetAttribute(gemm_bf16<3>, cudaFuncAttributeMaxDynamicSharedMemorySize, SMEM_GEMM);
    cudaFuncSetAttribute(gemm_bf16<4>, cudaFuncAttributeMaxDynamicSharedMemorySize, SMEM_GEMM);
    cudaFuncSetAttribute(gemm_bf16<5>, cudaFuncAttributeMaxDynamicSharedMemorySize, SMEM_GEMM);

    const int T = 256;
    unsigned gy  = (unsigned)((Nn + 127) / 128);
    unsigned gys = (unsigned)((S + 127) / 128);
    dim3 g512(4, gy), g256(2, gy), gh(2, gys);
    unsigned gGat = (unsigned)((Nn + 7) / 8);
    unsigned gPool = (unsigned)((2 * S + 3) / 4);
    int nbN = (2 * Nn + SCAN_B - 1) / SCAN_B;
    int nbS = (2 * S + SCAN_B - 1) / SCAN_B;
    int nz = (int)(OFF_COFF - OFF_CC);

    // ---- prologue: zero + node/segment CSR build ----
    zero_k<<<(nz + T - 1) / T, T>>>(base + OFF_CC, nz);
    countall_k<<<(E1 + E2 + Nn + T - 1) / T, T>>>(e1, E1, e2, E2, i1, i2, Nn, S, cc, sc);
    blocksum_k<<<nbN, SCAN_B>>>(cc, bsn, 2 * Nn);
    blocksum_k<<<nbS, SCAN_B>>>(sc, bss, 2 * S);
    scanbsum_k<<<1, 32>>>(bsn, nbN, coff + 2 * Nn);
    scanbsum_k<<<1, 32>>>(bss, nbS, soff + 2 * S);
    scanblock_k<<<nbN, SCAN_B>>>(cc, bsn, coff, ccur, 2 * Nn);
    scanblock_k<<<nbS, SCAN_B>>>(sc, bss, soff, scur, 2 * S);
    disint_k<<<(Nn + T - 1) / T, T>>>(cc, dis1, dis2, Nn);
    placeboth_k<<<(E1 + E2 + T - 1) / T, T>>>(e1, E1, e2, E2, Nn, ccur, csr);
    placeseg_k<<<(Nn + T - 1) / T, T>>>(i1, i2, Nn, S, scur, slist);

    // ---- splits: input x + all weights ----
    long t4 = (long)Nn * FIN / 4;
    splitA_k<false><<<(unsigned)((t4 + T - 1) / T), T>>>(x, FIN, XH, XL, 512, 0, t4);
    splitAllW_k<<<(WTOT + T - 1) / T, T>>>(w11, w12, w21, w22, m1w1, m1w2, m2w1, m2w2, mw1, WH, WL);

    // ---- layer 1: dual conv GEMM + column-blocked gathers ----
    gemm_bf16<0><<<g512, 256, SMEM_GEMM>>>(XH, XL, 512, WH + WC1, WL + WC1, FIN,
        h, nullptr, nullptr, nullptr, 0, 0, Nn, FIN);
    gather_k<<<gGat, T>>>(csr, coff,      dis1, h,       b11, XH, XL, 0,   0,   Nn);
    gather_k<<<gGat, T>>>(csr, coff,      dis1, h,       b11, XH, XL, 0,   128, Nn);
    gather_k<<<gGat, T>>>(csr, coff + Nn, dis2, h + 256, b12, XH, XL, 256, 0,   Nn);
    gather_k<<<gGat, T>>>(csr, coff + Nn, dis2, h + 256, b12, XH, XL, 256, 128, Nn);
    // ---- mlp_1 ----
    gemm_bf16<2><<<g256, 256, SMEM_GEMM>>>(XH, XL, 512, WH + WM1A, WL + WM1A, 512,
        nullptr, m1b1, YH, YL, 256, 0, Nn, 512);
    gemm_bf16<3><<<g256, 256, SMEM_GEMM>>>(YH, YL, 256, WH + WM1B, WL + WM1B, 256,
        nullptr, m1b2, XH, XL, 512, 0, Nn, 256);

    // ---- layer 2: dual conv GEMM + column-blocked gathers ----
    gemm_bf16<0><<<g512, 256, SMEM_GEMM>>>(XH, XL, 512, WH + WC2, WL + WC2, DD,
        h, nullptr, nullptr, nullptr, 0, 0, Nn, DD);
    gather_k<<<gGat, T>>>(csr, coff,      dis1, h,       b21, XH, XL, 0,   0,   Nn);
    gather_k<<<gGat, T>>>(csr, coff,      dis1, h,       b21, XH, XL, 0,   128, Nn);
    gather_k<<<gGat, T>>>(csr, coff + Nn, dis2, h + 256, b22, XH, XL, 256, 0,   Nn);
    gather_k<<<gGat, T>>>(csr, coff + Nn, dis2, h + 256, b22, XH, XL, 256, 128, Nn);
    // ---- mlp_2 ----
    gemm_bf16<2><<<g256, 256, SMEM_GEMM>>>(XH, XL, 512, WH + WM2A, WL + WM2A, 512,
        nullptr, m2b1, YH, YL, 256, 0, Nn, 512);
    gemm_bf16<4><<<g256, 256, SMEM_GEMM>>>(YH, YL, 256, WH + WM2B, WL + WM2B, 256,
        hf, m2b2, nullptr, nullptr, 0, 0, Nn, 256);

    // ---- pooling ----
    poolgather_k<<<gPool, T>>>(slist, soff, hf, XH, XL, S);

    // ---- head ----
    gemm_bf16<5><<<gh, 256, SMEM_GEMM>>>(XH, XL, 512, WH + WHD, WL + WHD, 512,
        hid2, mb1, nullptr, nullptr, 0, 0, S, 512);
    final_k<<<S, DD>>>(hid2, mw2, mb2, out);
}